// round 1
// baseline (speedup 1.0000x reference)
#include <cuda_runtime.h>
#include <math.h>

// Problem constants
#define BWIN 8192
#define NTOK 49
#define CDIM 128
#define HEADS 4
#define HD 32
#define NWIN 4096

// Shared-memory layout strides (in floats)
#define XSS 132           // x / O buffer row stride (64 rows, rows 49..63 zero)
#define QS  388           // qkv row stride (384 + 4 pad)
#define ATS 52            // attn row stride (49 + 3 pad)
#define ATN 56            // attn rows per head (49 + 7 pad, so n-overreads stay in-region)
#define WSTS 132          // staged weight-tile row stride

// float offsets inside dynamic smem
#define OFF_XS    0
#define OFF_QKV   (64*XSS)                       // 8448
#define OFF_SCR   (OFF_QKV + NTOK*QS)            // 27460  (WST 64x132 | ATTN 4x56x52)
#define OFF_MASK  (OFF_SCR + HEADS*ATN*ATS)      // 39108
#define OFF_BIAS  (OFF_MASK + NTOK*NTOK)         // 41509
#define OFF_REL   (OFF_BIAS + 169*4)             // 42185
#define SMEM_FLOATS (OFF_REL + NTOK*NTOK)        // 44586
#define SMEM_BYTES  (SMEM_FLOATS * 4)            // 178344 B

typedef unsigned long long ull;

__device__ __forceinline__ ull dup2(float v){
    ull r; asm("mov.b64 %0, {%1, %1};" : "=l"(r) : "f"(v)); return r;
}
__device__ __forceinline__ void fma2(ull &c, ull a, ull b){
    asm("fma.rn.f32x2 %0, %1, %2, %0;" : "+l"(c) : "l"(a), "l"(b));
}
__device__ __forceinline__ void unp2(ull v, float &lo, float &hi){
    asm("mov.b64 {%0, %1}, %2;" : "=f"(lo), "=f"(hi) : "l"(v));
}

extern __shared__ float smem[];

__global__ void __launch_bounds__(256, 1)
lpwin_attn_kernel(const float* __restrict__ x,
                  const float* __restrict__ mask,
                  const float* __restrict__ qkv_w,
                  const float* __restrict__ proj_w,
                  const float* __restrict__ proj_b,
                  const float* __restrict__ bias_table,
                  const float* __restrict__ alpha,
                  const int*   __restrict__ rel_idx,
                  float* __restrict__ out)
{
    float* XS    = smem + OFF_XS;
    float* QKV   = smem + OFF_QKV;
    float* SCR   = smem + OFF_SCR;
    float* MASKS = smem + OFF_MASK;
    float* BIASS = smem + OFF_BIAS;
    int*   RELS  = (int*)(smem + OFF_REL);

    const int tid = threadIdx.x;
    const int b   = blockIdx.x;
    const int w   = b & (NWIN - 1);

    // ---------------- P1: load x window, mask, rel_idx, bias_table ----------------
    {
        const float4* xg = (const float4*)(x + (size_t)b * NTOK * CDIM);
        for (int i = tid; i < NTOK * 32; i += 256) {
            int n = i >> 5, k4 = i & 31;
            float4 v = xg[i];
            *(float4*)&XS[n * XSS + k4 * 4] = v;
        }
        // zero pad rows 49..63 (full padded width: 33 float4 per row)
        for (int i = tid; i < 15 * 33; i += 256) {
            int n = 49 + i / 33, k4 = i % 33;
            *(float4*)&XS[n * XSS + k4 * 4] = make_float4(0.f, 0.f, 0.f, 0.f);
        }
        const float* mg = mask + (size_t)w * NTOK * NTOK;
        for (int i = tid; i < NTOK * NTOK; i += 256) MASKS[i] = mg[i];
        for (int i = tid; i < NTOK * NTOK; i += 256) RELS[i]  = rel_idx[i];
        for (int i = tid; i < 169 * 4;   i += 256) BIASS[i]  = bias_table[i];
    }
    __syncthreads();

    // ---------------- P2: QKV GEMM  QKV[n][o] = sum_k XS[n][k]*qkv_w[o][k] ----------------
    {
        const int to = tid & 15, tn = tid >> 4;     // compute mapping
        const int so = tid & 127, skg = tid >> 7;   // staging mapping
        for (int oc = 0; oc < 3; ++oc) {
            ull acc[4][4];
            #pragma unroll
            for (int j = 0; j < 4; ++j)
                #pragma unroll
                for (int p = 0; p < 4; ++p) acc[j][p] = 0ull;

            for (int kt = 0; kt < 2; ++kt) {
                __syncthreads();
                // stage transposed tile: WST[k_local][o_local] for o in [oc*128,+128), k in [kt*64,+64)
                {
                    const float* wg = qkv_w + (size_t)(oc * 128 + so) * CDIM + kt * 64 + skg * 32;
                    #pragma unroll 8
                    for (int j2 = 0; j2 < 32; ++j2)
                        SCR[(skg * 32 + j2) * WSTS + so] = wg[j2];
                }
                __syncthreads();
                #pragma unroll 4
                for (int k = 0; k < 64; ++k) {
                    ull w2[4];
                    #pragma unroll
                    for (int p = 0; p < 4; ++p)
                        w2[p] = *(const ull*)&SCR[k * WSTS + 2 * to + 32 * p];
                    #pragma unroll
                    for (int j = 0; j < 4; ++j) {
                        ull x2 = dup2(XS[(tn + 16 * j) * XSS + kt * 64 + k]);
                        #pragma unroll
                        for (int p = 0; p < 4; ++p) fma2(acc[j][p], x2, w2[p]);
                    }
                }
            }
            #pragma unroll
            for (int j = 0; j < 4; ++j) {
                int n = tn + 16 * j;
                if (n < NTOK) {
                    #pragma unroll
                    for (int p = 0; p < 4; ++p)
                        *(ull*)&QKV[n * QS + oc * 128 + 2 * to + 32 * p] = acc[j][p];
                }
            }
        }
    }
    __syncthreads();

    // ---------------- P3: L2-normalize q and k; fold alpha into q ----------------
    for (int t = tid; t < 2 * HEADS * NTOK; t += 256) {
        int isq = (t < HEADS * NTOK);
        int r = isq ? t : t - HEADS * NTOK;
        int h = r / NTOK, n = r % NTOK;
        float* base = &QKV[n * QS + (isq ? 0 : 128) + h * HD];
        float ss = 0.f;
        #pragma unroll
        for (int d = 0; d < HD; ++d) { float v = base[d]; ss += v * v; }
        float inv = 1.f / (sqrtf(ss) + 1e-6f);
        if (isq) inv *= __ldg(&alpha[h]);
        #pragma unroll
        for (int d = 0; d < HD; ++d) base[d] *= inv;
    }
    __syncthreads();

    // ---------------- P4: attn[h][n][m] = q_hat . k_hat + rpb + mask ----------------
    if (tid < HEADS * NTOK) {
        int h = tid / NTOK, n = tid % NTOK;
        const ull* qp = (const ull*)&QKV[n * QS + h * HD];
        ull q2[16];
        #pragma unroll
        for (int i = 0; i < 16; ++i) q2[i] = qp[i];
        float*       arow = &SCR[(h * ATN + n) * ATS];
        const float* mrow = &MASKS[n * NTOK];
        const int*   rrow = &RELS[n * NTOK];
        for (int m = 0; m < NTOK; ++m) {
            const ull* kp = (const ull*)&QKV[m * QS + 128 + h * HD];
            ull a = 0ull, c = 0ull;
            #pragma unroll
            for (int i = 0; i < 16; i += 2) { fma2(a, q2[i], kp[i]); fma2(c, q2[i + 1], kp[i + 1]); }
            float l0, h0, l1, h1;
            unp2(a, l0, h0); unp2(c, l1, h1);
            float s = (l0 + h0) + (l1 + h1);
            s += BIASS[rrow[m] * 4 + h] + mrow[m];
            arow[m] = s;
        }
    }
    __syncthreads();

    // ---------------- softmax over m (warp per row) ----------------
    {
        int lane = tid & 31, warp = tid >> 5;
        for (int r = warp; r < HEADS * NTOK; r += 8) {
            float* arow = &SCR[((r / NTOK) * ATN + (r % NTOK)) * ATS];
            float v0 = arow[lane];
            float v1 = (lane + 32 < NTOK) ? arow[lane + 32] : -1e30f;
            float mx = fmaxf(v0, v1);
            #pragma unroll
            for (int o = 16; o; o >>= 1) mx = fmaxf(mx, __shfl_xor_sync(0xffffffffu, mx, o));
            float e0 = __expf(v0 - mx);
            float e1 = (lane + 32 < NTOK) ? __expf(v1 - mx) : 0.f;
            float sm = e0 + e1;
            #pragma unroll
            for (int o = 16; o; o >>= 1) sm += __shfl_xor_sync(0xffffffffu, sm, o);
            float inv = 1.f / sm;
            arow[lane] = e0 * inv;
            if (lane + 32 < NTOK) arow[lane + 32] = e1 * inv;
        }
    }
    __syncthreads();

    // ---------------- P5: O[n][c] = sum_m attn[h][n][m] * V[m][c]  (h = c/32) ----------------
    {
        int cg = tid & 31, ng = tid >> 5;
        int h0 = cg >> 4;       // head of column pair 2*cg
        int h1 = h0 + 2;        // head of column pair 64 + 2*cg
        ull acc[7][2];
        #pragma unroll
        for (int i = 0; i < 7; ++i) { acc[i][0] = 0ull; acc[i][1] = 0ull; }
        for (int m = 0; m < NTOK; ++m) {
            ull v20 = *(const ull*)&QKV[m * QS + 256 + 2 * cg];
            ull v21 = *(const ull*)&QKV[m * QS + 256 + 64 + 2 * cg];
            #pragma unroll
            for (int i = 0; i < 7; ++i) {
                int n = ng + 8 * i;   // may exceed 48; padded ATTN rows keep reads in-region
                ull a0 = dup2(SCR[(h0 * ATN + n) * ATS + m]);
                ull a1 = dup2(SCR[(h1 * ATN + n) * ATS + m]);
                fma2(acc[i][0], a0, v20);
                fma2(acc[i][1], a1, v21);
            }
        }
        #pragma unroll
        for (int i = 0; i < 7; ++i) {
            int n = ng + 8 * i;
            if (n < NTOK) {
                *(ull*)&XS[n * XSS + 2 * cg]      = acc[i][0];
                *(ull*)&XS[n * XSS + 64 + 2 * cg] = acc[i][1];
            }
        }
    }
    __syncthreads();

    // ---------------- P6: proj GEMM  out[n][o] = sum_c O[n][c]*proj_w[o][c] + b[o] ----------------
    {
        const int to = tid & 15, tn = tid >> 4;
        const int so = tid & 127, skg = tid >> 7;
        ull acc[4][4];
        #pragma unroll
        for (int j = 0; j < 4; ++j)
            #pragma unroll
            for (int p = 0; p < 4; ++p) acc[j][p] = 0ull;

        for (int kt = 0; kt < 2; ++kt) {
            __syncthreads();
            {
                const float* wg = proj_w + (size_t)so * CDIM + kt * 64 + skg * 32;
                #pragma unroll 8
                for (int j2 = 0; j2 < 32; ++j2)
                    SCR[(skg * 32 + j2) * WSTS + so] = wg[j2];
            }
            __syncthreads();
            #pragma unroll 4
            for (int k = 0; k < 64; ++k) {
                ull w2[4];
                #pragma unroll
                for (int p = 0; p < 4; ++p)
                    w2[p] = *(const ull*)&SCR[k * WSTS + 2 * to + 32 * p];
                #pragma unroll
                for (int j = 0; j < 4; ++j) {
                    ull x2 = dup2(XS[(tn + 16 * j) * XSS + kt * 64 + k]);
                    #pragma unroll
                    for (int p = 0; p < 4; ++p) fma2(acc[j][p], x2, w2[p]);
                }
            }
        }
        float* og = out + (size_t)b * NTOK * CDIM;
        #pragma unroll
        for (int j = 0; j < 4; ++j) {
            int n = tn + 16 * j;
            if (n < NTOK) {
                #pragma unroll
                for (int p = 0; p < 4; ++p) {
                    int o = 2 * to + 32 * p;
                    float lo, hi;
                    unp2(acc[j][p], lo, hi);
                    float2 r = make_float2(lo + __ldg(&proj_b[o]), hi + __ldg(&proj_b[o + 1]));
                    *(float2*)&og[n * CDIM + o] = r;
                }
            }
        }
    }
}

extern "C" void kernel_launch(void* const* d_in, const int* in_sizes, int n_in,
                              void* d_out, int out_size)
{
    (void)in_sizes; (void)n_in; (void)out_size;
    const float* x          = (const float*)d_in[0];
    const float* mask       = (const float*)d_in[1];
    const float* qkv_w      = (const float*)d_in[2];
    const float* proj_w     = (const float*)d_in[3];
    const float* proj_b     = (const float*)d_in[4];
    const float* bias_table = (const float*)d_in[5];
    const float* alpha      = (const float*)d_in[6];
    const int*   rel_idx    = (const int*)d_in[7];
    float* out = (float*)d_out;

    cudaFuncSetAttribute(lpwin_attn_kernel,
                         cudaFuncAttributeMaxDynamicSharedMemorySize, SMEM_BYTES);
    lpwin_attn_kernel<<<BWIN, 256, SMEM_BYTES>>>(
        x, mask, qkv_w, proj_w, proj_b, bias_table, alpha, rel_idx, out);
}

// round 2
// speedup vs baseline: 1.4313x; 1.4313x over previous
#include <cuda_runtime.h>
#include <math.h>

// Problem constants
#define BWIN 8192
#define NTOK 49
#define CDIM 128
#define HEADS 4
#define HD 32
#define NWIN 4096

// Shared-memory layout strides (in floats)
#define XSS 132           // x / O buffer row stride (64 rows, rows 49..63 zero)
#define QS  388           // qkv row stride (384 + 4 pad)
#define ATS 52            // attn row stride (49 + 3 pad)
#define ATN 56            // attn rows per head (49 + 7 pad)
#define WTS 392           // staged transposed weight tile row stride (k-major)

// float offsets inside dynamic smem
#define OFF_XS    0
#define OFF_QKV   (64*XSS)                       // 8448
#define OFF_SCR   (OFF_QKV + NTOK*QS)            // 27460  (WT 32x392=12544 | ATTN 4x56x52=11648)
#define OFF_MASK  (OFF_SCR + 32*WTS)             // 40004
#define OFF_BIAS  (OFF_MASK + NTOK*NTOK)         // 42405
#define OFF_REL   (OFF_BIAS + 169*4)             // 43081
#define SMEM_FLOATS (OFF_REL + NTOK*NTOK)        // 45482
#define SMEM_BYTES  (SMEM_FLOATS * 4)            // 181928 B

typedef unsigned long long ull;

__device__ __forceinline__ ull dup2(float v){
    ull r; asm("mov.b64 %0, {%1, %1};" : "=l"(r) : "f"(v)); return r;
}
__device__ __forceinline__ void fma2(ull &c, ull a, ull b){
    asm("fma.rn.f32x2 %0, %1, %2, %0;" : "+l"(c) : "l"(a), "l"(b));
}
__device__ __forceinline__ void unp2(ull v, float &lo, float &hi){
    asm("mov.b64 {%0, %1}, %2;" : "=f"(lo), "=f"(hi) : "l"(v));
}

extern __shared__ float smem[];

__global__ void __launch_bounds__(256, 1)
lpwin_attn_kernel(const float* __restrict__ x,
                  const float* __restrict__ mask,
                  const float* __restrict__ qkv_w,
                  const float* __restrict__ proj_w,
                  const float* __restrict__ proj_b,
                  const float* __restrict__ bias_table,
                  const float* __restrict__ alpha,
                  const int*   __restrict__ rel_idx,
                  float* __restrict__ out)
{
    float* XS    = smem + OFF_XS;
    float* QKV   = smem + OFF_QKV;
    float* SCR   = smem + OFF_SCR;
    float* MASKS = smem + OFF_MASK;
    float* BIASS = smem + OFF_BIAS;
    int*   RELS  = (int*)(smem + OFF_REL);

    const int tid = threadIdx.x;
    const int b   = blockIdx.x;
    const int w   = b & (NWIN - 1);

    // ---------------- P1: load x window, mask, rel_idx, bias_table ----------------
    {
        const float4* xg = (const float4*)(x + (size_t)b * NTOK * CDIM);
        for (int i = tid; i < NTOK * 32; i += 256) {
            int n = i >> 5, k4 = i & 31;
            float4 v = xg[i];
            *(float4*)&XS[n * XSS + k4 * 4] = v;
        }
        for (int i = tid; i < 15 * 33; i += 256) {
            int n = 49 + i / 33, k4 = i % 33;
            *(float4*)&XS[n * XSS + k4 * 4] = make_float4(0.f, 0.f, 0.f, 0.f);
        }
        const float* mg = mask + (size_t)w * NTOK * NTOK;
        for (int i = tid; i < NTOK * NTOK; i += 256) MASKS[i] = mg[i];
        for (int i = tid; i < NTOK * NTOK; i += 256) RELS[i]  = rel_idx[i];
        for (int i = tid; i < 169 * 4;   i += 256) BIASS[i]  = bias_table[i];
    }

    // ---------------- P2: QKV GEMM  QKV[n][o] = sum_k XS[n][k]*qkv_w[o][k] ----------------
    // Thread tile: Rn=8 rows (ng = warp id), Ro=12 columns o in {2og+64i, 2og+1+64i}, og = lane.
    {
        const int og = tid & 31, ng = tid >> 5;
        const int nb = ng * 8;
        const int ob = 2 * og;
        ull acc[8][6];
        #pragma unroll
        for (int j = 0; j < 8; ++j)
            #pragma unroll
            for (int i = 0; i < 6; ++i) acc[j][i] = 0ull;

        const int oo = tid & 127, kh = tid >> 7;   // staging map
        for (int kt = 0; kt < 4; ++kt) {
            __syncthreads();
            // stage transposed tile WT[k_local][o], k_local in [0,32), o in [0,384)
            #pragma unroll
            for (int seg = 0; seg < 3; ++seg) {
                int o = seg * 128 + oo;
                const float4* wg = (const float4*)(qkv_w + (size_t)o * CDIM + kt * 32 + kh * 16);
                #pragma unroll
                for (int q4 = 0; q4 < 4; ++q4) {
                    float4 v = wg[q4];
                    int kk = kh * 16 + q4 * 4;
                    SCR[(kk + 0) * WTS + o] = v.x;
                    SCR[(kk + 1) * WTS + o] = v.y;
                    SCR[(kk + 2) * WTS + o] = v.z;
                    SCR[(kk + 3) * WTS + o] = v.w;
                }
            }
            __syncthreads();
            #pragma unroll 2
            for (int kp = 0; kp < 16; ++kp) {
                const int k0 = kt * 32 + kp * 2;
                ull w0[6], w1[6];
                #pragma unroll
                for (int i = 0; i < 6; ++i) {
                    w0[i] = *(const ull*)&SCR[(kp * 2 + 0) * WTS + ob + 64 * i];
                    w1[i] = *(const ull*)&SCR[(kp * 2 + 1) * WTS + ob + 64 * i];
                }
                #pragma unroll
                for (int j = 0; j < 8; ++j) {
                    ull xp = *(const ull*)&XS[(nb + j) * XSS + k0];
                    float xl, xh; unp2(xp, xl, xh);
                    ull x0 = dup2(xl), x1 = dup2(xh);
                    #pragma unroll
                    for (int i = 0; i < 6; ++i) {
                        fma2(acc[j][i], x0, w0[i]);
                        fma2(acc[j][i], x1, w1[i]);
                    }
                }
            }
        }
        __syncthreads();
        #pragma unroll
        for (int j = 0; j < 8; ++j) {
            int n = nb + j;
            if (n < NTOK) {
                #pragma unroll
                for (int i = 0; i < 6; ++i)
                    *(ull*)&QKV[n * QS + ob + 64 * i] = acc[j][i];
            }
        }
    }
    __syncthreads();

    // ---------------- P3: L2-normalize q and k; fold alpha into q ----------------
    for (int t = tid; t < 2 * HEADS * NTOK; t += 256) {
        int isq = (t < HEADS * NTOK);
        int r = isq ? t : t - HEADS * NTOK;
        int h = r / NTOK, n = r % NTOK;
        float* base = &QKV[n * QS + (isq ? 0 : 128) + h * HD];
        float ss = 0.f;
        #pragma unroll
        for (int d = 0; d < HD; ++d) { float v = base[d]; ss += v * v; }
        float inv = 1.f / (sqrtf(ss) + 1e-6f);
        if (isq) inv *= __ldg(&alpha[h]);
        #pragma unroll
        for (int d = 0; d < HD; ++d) base[d] *= inv;
    }
    __syncthreads();

    // ---------------- P4: attn[h][n][m] = q_hat . k_hat + rpb + mask (2 q-rows per thread) ----------------
    if (tid < 100) {
        const int h = tid / 25, np = tid % 25;
        const int n0 = 2 * np;
        const bool has1 = (n0 + 1) < NTOK;
        const int n1 = has1 ? n0 + 1 : n0;
        const ull* qp0 = (const ull*)&QKV[n0 * QS + h * HD];
        const ull* qp1 = (const ull*)&QKV[n1 * QS + h * HD];
        ull q0[16], q1[16];
        #pragma unroll
        for (int i = 0; i < 16; ++i) { q0[i] = qp0[i]; q1[i] = qp1[i]; }
        float*       arow0 = &SCR[(h * ATN + n0) * ATS];
        float*       arow1 = &SCR[(h * ATN + n1) * ATS];
        const float* mrow0 = &MASKS[n0 * NTOK];
        const float* mrow1 = &MASKS[n1 * NTOK];
        const int*   rrow0 = &RELS[n0 * NTOK];
        const int*   rrow1 = &RELS[n1 * NTOK];
        for (int m = 0; m < NTOK; ++m) {
            const ull* kp = (const ull*)&QKV[m * QS + 128 + h * HD];
            ull a0 = 0ull, c0 = 0ull, a1 = 0ull, c1 = 0ull;
            #pragma unroll
            for (int i = 0; i < 16; i += 2) {
                ull kv0 = kp[i], kv1 = kp[i + 1];
                fma2(a0, q0[i], kv0); fma2(c0, q0[i + 1], kv1);
                fma2(a1, q1[i], kv0); fma2(c1, q1[i + 1], kv1);
            }
            float l0, h0v, l1, h1v;
            unp2(a0, l0, h0v); unp2(c0, l1, h1v);
            float s0 = (l0 + h0v) + (l1 + h1v);
            unp2(a1, l0, h0v); unp2(c1, l1, h1v);
            float s1 = (l0 + h0v) + (l1 + h1v);
            arow0[m] = s0 + BIASS[rrow0[m] * 4 + h] + mrow0[m];
            if (has1) arow1[m] = s1 + BIASS[rrow1[m] * 4 + h] + mrow1[m];
        }
    }
    __syncthreads();

    // ---------------- softmax over m (warp per row) ----------------
    {
        int lane = tid & 31, warp = tid >> 5;
        for (int r = warp; r < HEADS * NTOK; r += 8) {
            float* arow = &SCR[((r / NTOK) * ATN + (r % NTOK)) * ATS];
            float v0 = arow[lane];
            float v1 = (lane + 32 < NTOK) ? arow[lane + 32] : -1e30f;
            float mx = fmaxf(v0, v1);
            #pragma unroll
            for (int o = 16; o; o >>= 1) mx = fmaxf(mx, __shfl_xor_sync(0xffffffffu, mx, o));
            float e0 = __expf(v0 - mx);
            float e1 = (lane + 32 < NTOK) ? __expf(v1 - mx) : 0.f;
            float sm = e0 + e1;
            #pragma unroll
            for (int o = 16; o; o >>= 1) sm += __shfl_xor_sync(0xffffffffu, sm, o);
            float inv = 1.f / sm;
            arow[lane] = e0 * inv;
            if (lane + 32 < NTOK) arow[lane + 32] = e1 * inv;
        }
    }
    __syncthreads();

    // ---------------- P5: O[n][c] = sum_m attn[h][n][m] * V[m][c]  (m-paired) ----------------
    {
        const int cg = tid & 31, ng5 = tid >> 5;
        const int h0 = cg >> 4;
        const int h1 = h0 + 2;
        ull acc[7][2];
        #pragma unroll
        for (int i = 0; i < 7; ++i) { acc[i][0] = 0ull; acc[i][1] = 0ull; }
        for (int mp = 0; mp < 24; ++mp) {
            const int m = 2 * mp;
            ull va0 = *(const ull*)&QKV[(m + 0) * QS + 256 + 2 * cg];
            ull vb0 = *(const ull*)&QKV[(m + 0) * QS + 256 + 64 + 2 * cg];
            ull va1 = *(const ull*)&QKV[(m + 1) * QS + 256 + 2 * cg];
            ull vb1 = *(const ull*)&QKV[(m + 1) * QS + 256 + 64 + 2 * cg];
            #pragma unroll
            for (int i = 0; i < 7; ++i) {
                int n = ng5 + 8 * i;   // padded rows keep reads in-region
                ull ap0 = *(const ull*)&SCR[(h0 * ATN + n) * ATS + m];
                ull ap1 = *(const ull*)&SCR[(h1 * ATN + n) * ATS + m];
                float a00, a01, a10, a11;
                unp2(ap0, a00, a01); unp2(ap1, a10, a11);
                fma2(acc[i][0], dup2(a00), va0);
                fma2(acc[i][0], dup2(a01), va1);
                fma2(acc[i][1], dup2(a10), vb0);
                fma2(acc[i][1], dup2(a11), vb1);
            }
        }
        {   // tail m = 48
            const int m = 48;
            ull va0 = *(const ull*)&QKV[m * QS + 256 + 2 * cg];
            ull vb0 = *(const ull*)&QKV[m * QS + 256 + 64 + 2 * cg];
            #pragma unroll
            for (int i = 0; i < 7; ++i) {
                int n = ng5 + 8 * i;
                float a0 = SCR[(h0 * ATN + n) * ATS + m];
                float a1 = SCR[(h1 * ATN + n) * ATS + m];
                fma2(acc[i][0], dup2(a0), va0);
                fma2(acc[i][1], dup2(a1), vb0);
            }
        }
        __syncthreads();
        #pragma unroll
        for (int i = 0; i < 7; ++i) {
            int n = ng5 + 8 * i;
            if (n < NTOK) {
                *(ull*)&XS[n * XSS + 2 * cg]      = acc[i][0];
                *(ull*)&XS[n * XSS + 64 + 2 * cg] = acc[i][1];
            }
        }
    }
    __syncthreads();

    // ---------------- P6: proj GEMM  out[n][o] = sum_c O[n][c]*proj_w[o][c] + b[o] ----------------
    // Thread tile: Rn=8, Ro=4: o in {2og+64i}, i<2
    {
        const int og = tid & 31, ng = tid >> 5;
        const int nb = ng * 8;
        const int ob = 2 * og;
        ull acc[8][2];
        #pragma unroll
        for (int j = 0; j < 8; ++j) { acc[j][0] = 0ull; acc[j][1] = 0ull; }

        const int oo = tid & 127, kh = tid >> 7;
        for (int kt = 0; kt < 4; ++kt) {
            __syncthreads();
            {
                const float4* wg = (const float4*)(proj_w + (size_t)oo * CDIM + kt * 32 + kh * 16);
                #pragma unroll
                for (int q4 = 0; q4 < 4; ++q4) {
                    float4 v = wg[q4];
                    int kk = kh * 16 + q4 * 4;
                    SCR[(kk + 0) * WTS + oo] = v.x;
                    SCR[(kk + 1) * WTS + oo] = v.y;
                    SCR[(kk + 2) * WTS + oo] = v.z;
                    SCR[(kk + 3) * WTS + oo] = v.w;
                }
            }
            __syncthreads();
            #pragma unroll 4
            for (int kp = 0; kp < 16; ++kp) {
                const int k0 = kt * 32 + kp * 2;
                ull w0[2], w1[2];
                #pragma unroll
                for (int i = 0; i < 2; ++i) {
                    w0[i] = *(const ull*)&SCR[(kp * 2 + 0) * WTS + ob + 64 * i];
                    w1[i] = *(const ull*)&SCR[(kp * 2 + 1) * WTS + ob + 64 * i];
                }
                #pragma unroll
                for (int j = 0; j < 8; ++j) {
                    ull xp = *(const ull*)&XS[(nb + j) * XSS + k0];
                    float xl, xh; unp2(xp, xl, xh);
                    ull x0 = dup2(xl), x1 = dup2(xh);
                    #pragma unroll
                    for (int i = 0; i < 2; ++i) {
                        fma2(acc[j][i], x0, w0[i]);
                        fma2(acc[j][i], x1, w1[i]);
                    }
                }
            }
        }
        float* og_ptr = out + (size_t)b * NTOK * CDIM;
        #pragma unroll
        for (int j = 0; j < 8; ++j) {
            int n = nb + j;
            if (n < NTOK) {
                #pragma unroll
                for (int i = 0; i < 2; ++i) {
                    int o = ob + 64 * i;
                    float lo, hi;
                    unp2(acc[j][i], lo, hi);
                    float2 r = make_float2(lo + __ldg(&proj_b[o]), hi + __ldg(&proj_b[o + 1]));
                    *(float2*)&og_ptr[n * CDIM + o] = r;
                }
            }
        }
    }
}

extern "C" void kernel_launch(void* const* d_in, const int* in_sizes, int n_in,
                              void* d_out, int out_size)
{
    (void)in_sizes; (void)n_in; (void)out_size;
    const float* x          = (const float*)d_in[0];
    const float* mask       = (const float*)d_in[1];
    const float* qkv_w      = (const float*)d_in[2];
    const float* proj_w     = (const float*)d_in[3];
    const float* proj_b     = (const float*)d_in[4];
    const float* bias_table = (const float*)d_in[5];
    const float* alpha      = (const float*)d_in[6];
    const int*   rel_idx    = (const int*)d_in[7];
    float* out = (float*)d_out;

    cudaFuncSetAttribute(lpwin_attn_kernel,
                         cudaFuncAttributeMaxDynamicSharedMemorySize, SMEM_BYTES);
    lpwin_attn_kernel<<<BWIN, 256, SMEM_BYTES>>>(
        x, mask, qkv_w, proj_w, proj_b, bias_table, alpha, rel_idx, out);
}

// round 4
// speedup vs baseline: 1.7063x; 1.1921x over previous
#include <cuda_runtime.h>
#include <math.h>

// Problem constants
#define BWIN 8192
#define NTOK 49
#define CDIM 128
#define HEADS 4
#define HD 32
#define NWIN 4096
#define THREADS 512

// Shared-memory layout strides (in floats)
#define XSS 132           // x / O buffer row stride (64 rows, rows 49..63 zero)
#define QS  388           // qkv row stride (384 + 4 pad)
#define ATS 52            // attn row stride (49 + 3 pad)
#define ATN 56            // attn rows per head (49 + 7 pad)
#define WTS 392           // staged transposed weight tile row stride (k-major)

// float offsets inside dynamic smem
#define OFF_XS    0
#define OFF_QKV   (64*XSS)                       // 8448
#define OFF_SCR   (OFF_QKV + NTOK*QS)            // 27460  (WT 32x392=12544 | ATTN 4x56x52=11648)
#define OFF_MASK  (OFF_SCR + 32*WTS)             // 40004
#define OFF_BIAS  (OFF_MASK + NTOK*NTOK)         // 42405
#define OFF_REL   (OFF_BIAS + 169*4)             // 43081
#define SMEM_FLOATS (OFF_REL + NTOK*NTOK)        // 45482
#define SMEM_BYTES  (SMEM_FLOATS * 4)            // 181928 B

typedef unsigned long long ull;

__device__ __forceinline__ ull dup2(float v){
    ull r; asm("mov.b64 %0, {%1, %1};" : "=l"(r) : "f"(v)); return r;
}
__device__ __forceinline__ void fma2(ull &c, ull a, ull b){
    asm("fma.rn.f32x2 %0, %1, %2, %0;" : "+l"(c) : "l"(a), "l"(b));
}
__device__ __forceinline__ void unp2(ull v, float &lo, float &hi){
    asm("mov.b64 {%0, %1}, %2;" : "=f"(lo), "=f"(hi) : "l"(v));
}

extern __shared__ float smem[];

__global__ void __launch_bounds__(THREADS, 1)
lpwin_attn_kernel(const float* __restrict__ x,
                  const float* __restrict__ mask,
                  const float* __restrict__ qkv_w,
                  const float* __restrict__ proj_w,
                  const float* __restrict__ proj_b,
                  const float* __restrict__ bias_table,
                  const float* __restrict__ alpha,
                  const int*   __restrict__ rel_idx,
                  float* __restrict__ out)
{
    float* XS    = smem + OFF_XS;
    float* QKV   = smem + OFF_QKV;
    float* SCR   = smem + OFF_SCR;
    float* MASKS = smem + OFF_MASK;
    float* BIASS = smem + OFF_BIAS;
    int*   RELS  = (int*)(smem + OFF_REL);

    const int tid = threadIdx.x;
    const int b   = blockIdx.x;
    const int w   = b & (NWIN - 1);

    // ---------------- P1: load x window, mask, rel_idx, bias_table ----------------
    {
        const float4* xg = (const float4*)(x + (size_t)b * NTOK * CDIM);
        for (int i = tid; i < NTOK * 32; i += THREADS) {
            int n = i >> 5, k4 = i & 31;
            float4 v = xg[i];
            *(float4*)&XS[n * XSS + k4 * 4] = v;
        }
        for (int i = tid; i < 15 * 33; i += THREADS) {
            int n = 49 + i / 33, k4 = i % 33;
            *(float4*)&XS[n * XSS + k4 * 4] = make_float4(0.f, 0.f, 0.f, 0.f);
        }
        const float* mg = mask + (size_t)w * NTOK * NTOK;
        for (int i = tid; i < NTOK * NTOK; i += THREADS) MASKS[i] = mg[i];
        for (int i = tid; i < NTOK * NTOK; i += THREADS) RELS[i]  = rel_idx[i];
        for (int i = tid; i < 169 * 4;   i += THREADS) BIASS[i]  = bias_table[i];
    }

    // ---------------- P2: QKV GEMM  QKV[n][o] = sum_k XS[n][k]*qkv_w[o][k] ----------------
    // 16 warps: warp = n-group (4 rows), lane = o-pair; Ro=12 cols o in {2og+64i}.
    {
        const int og = tid & 31, ng = tid >> 5;
        const int nb = ng * 4;
        const int ob = 2 * og;
        ull acc[4][6];
        #pragma unroll
        for (int j = 0; j < 4; ++j)
            #pragma unroll
            for (int i = 0; i < 6; ++i) acc[j][i] = 0ull;

        const int oo = tid & 127, kh = tid >> 7;   // staging map (kh 0..3)
        for (int kt = 0; kt < 4; ++kt) {
            __syncthreads();
            // stage transposed tile WT[k_local][o], k_local in [0,32), o in [0,384)
            #pragma unroll
            for (int seg = 0; seg < 3; ++seg) {
                int o = seg * 128 + oo;
                const float4* wg = (const float4*)(qkv_w + (size_t)o * CDIM + kt * 32 + kh * 8);
                #pragma unroll
                for (int q4 = 0; q4 < 2; ++q4) {
                    float4 v = wg[q4];
                    int kk = kh * 8 + q4 * 4;
                    SCR[(kk + 0) * WTS + o] = v.x;
                    SCR[(kk + 1) * WTS + o] = v.y;
                    SCR[(kk + 2) * WTS + o] = v.z;
                    SCR[(kk + 3) * WTS + o] = v.w;
                }
            }
            __syncthreads();
            #pragma unroll 2
            for (int kp = 0; kp < 16; ++kp) {
                const int k0 = kt * 32 + kp * 2;
                ull w0[6], w1[6];
                #pragma unroll
                for (int i = 0; i < 6; ++i) {
                    w0[i] = *(const ull*)&SCR[(kp * 2 + 0) * WTS + ob + 64 * i];
                    w1[i] = *(const ull*)&SCR[(kp * 2 + 1) * WTS + ob + 64 * i];
                }
                #pragma unroll
                for (int j = 0; j < 4; ++j) {
                    ull xp = *(const ull*)&XS[(nb + j) * XSS + k0];
                    float xl, xh; unp2(xp, xl, xh);
                    ull x0 = dup2(xl), x1 = dup2(xh);
                    #pragma unroll
                    for (int i = 0; i < 6; ++i) {
                        fma2(acc[j][i], x0, w0[i]);
                        fma2(acc[j][i], x1, w1[i]);
                    }
                }
            }
        }
        __syncthreads();
        #pragma unroll
        for (int j = 0; j < 4; ++j) {
            int n = nb + j;
            if (n < NTOK) {
                #pragma unroll
                for (int i = 0; i < 6; ++i)
                    *(ull*)&QKV[n * QS + ob + 64 * i] = acc[j][i];
            }
        }
    }
    __syncthreads();

    // ---------------- P3: L2-normalize q and k; fold alpha into q ----------------
    if (tid < 2 * HEADS * NTOK) {
        int isq = (tid < HEADS * NTOK);
        int r = isq ? tid : tid - HEADS * NTOK;
        int h = r / NTOK, n = r % NTOK;
        float* base = &QKV[n * QS + (isq ? 0 : 128) + h * HD];
        float ss = 0.f;
        #pragma unroll
        for (int d = 0; d < HD; ++d) { float v = base[d]; ss += v * v; }
        float inv = 1.f / (sqrtf(ss) + 1e-6f);
        if (isq) inv *= __ldg(&alpha[h]);
        #pragma unroll
        for (int d = 0; d < HD; ++d) base[d] *= inv;
    }
    __syncthreads();

    // ---------------- P4: attn[h][n][m] = q_hat . k_hat + rpb + mask (1 row per thread) ----------------
    if (tid < HEADS * NTOK) {
        const int h = tid / NTOK, n = tid % NTOK;
        const ull* qp = (const ull*)&QKV[n * QS + h * HD];
        ull q2[16];
        #pragma unroll
        for (int i = 0; i < 16; ++i) q2[i] = qp[i];
        float*       arow = &SCR[(h * ATN + n) * ATS];
        const float* mrow = &MASKS[n * NTOK];
        const int*   rrow = &RELS[n * NTOK];
        for (int m = 0; m < NTOK; ++m) {
            const ull* kp = (const ull*)&QKV[m * QS + 128 + h * HD];
            ull a = 0ull, c = 0ull;
            #pragma unroll
            for (int i = 0; i < 16; i += 2) { fma2(a, q2[i], kp[i]); fma2(c, q2[i + 1], kp[i + 1]); }
            float l0, h0v, l1, h1v;
            unp2(a, l0, h0v); unp2(c, l1, h1v);
            float s = (l0 + h0v) + (l1 + h1v);
            arow[m] = s + BIASS[rrow[m] * 4 + h] + mrow[m];
        }
    }
    __syncthreads();

    // ---------------- softmax over m (warp per row) ----------------
    {
        int lane = tid & 31, warp = tid >> 5;
        for (int r = warp; r < HEADS * NTOK; r += 16) {
            float* arow = &SCR[((r / NTOK) * ATN + (r % NTOK)) * ATS];
            float v0 = arow[lane];
            float v1 = (lane + 32 < NTOK) ? arow[lane + 32] : -1e30f;
            float mx = fmaxf(v0, v1);
            #pragma unroll
            for (int o = 16; o; o >>= 1) mx = fmaxf(mx, __shfl_xor_sync(0xffffffffu, mx, o));
            float e0 = __expf(v0 - mx);
            float e1 = (lane + 32 < NTOK) ? __expf(v1 - mx) : 0.f;
            float sm = e0 + e1;
            #pragma unroll
            for (int o = 16; o; o >>= 1) sm += __shfl_xor_sync(0xffffffffu, sm, o);
            float inv = 1.f / sm;
            arow[lane] = e0 * inv;
            if (lane + 32 < NTOK) arow[lane + 32] = e1 * inv;
        }
    }
    __syncthreads();

    // ---------------- P5: O[n][c] = sum_m attn[h][n][m] * V[m][c]  (m-paired, 4 rows/thread) ----------------
    {
        const int cg = tid & 31, ng5 = tid >> 5;   // ng5 0..15
        const int h0 = cg >> 4;
        const int h1 = h0 + 2;
        ull acc[4][2];
        #pragma unroll
        for (int i = 0; i < 4; ++i) { acc[i][0] = 0ull; acc[i][1] = 0ull; }
        for (int mp = 0; mp < 24; ++mp) {
            const int m = 2 * mp;
            ull va0 = *(const ull*)&QKV[(m + 0) * QS + 256 + 2 * cg];
            ull vb0 = *(const ull*)&QKV[(m + 0) * QS + 256 + 64 + 2 * cg];
            ull va1 = *(const ull*)&QKV[(m + 1) * QS + 256 + 2 * cg];
            ull vb1 = *(const ull*)&QKV[(m + 1) * QS + 256 + 64 + 2 * cg];
            #pragma unroll
            for (int i = 0; i < 4; ++i) {
                int n = ng5 + 16 * i;   // up to 63; overreads stay inside SCR allocation, results unused
                ull ap0 = *(const ull*)&SCR[(h0 * ATN + n) * ATS + m];
                ull ap1 = *(const ull*)&SCR[(h1 * ATN + n) * ATS + m];
                float a00, a01, a10, a11;
                unp2(ap0, a00, a01); unp2(ap1, a10, a11);
                fma2(acc[i][0], dup2(a00), va0);
                fma2(acc[i][0], dup2(a01), va1);
                fma2(acc[i][1], dup2(a10), vb0);
                fma2(acc[i][1], dup2(a11), vb1);
            }
        }
        {   // tail m = 48
            const int m = 48;
            ull va0 = *(const ull*)&QKV[m * QS + 256 + 2 * cg];
            ull vb0 = *(const ull*)&QKV[m * QS + 256 + 64 + 2 * cg];
            #pragma unroll
            for (int i = 0; i < 4; ++i) {
                int n = ng5 + 16 * i;
                float a0 = SCR[(h0 * ATN + n) * ATS + m];
                float a1 = SCR[(h1 * ATN + n) * ATS + m];
                fma2(acc[i][0], dup2(a0), va0);
                fma2(acc[i][1], dup2(a1), vb0);
            }
        }
        __syncthreads();
        #pragma unroll
        for (int i = 0; i < 4; ++i) {
            int n = ng5 + 16 * i;
            if (n < NTOK) {
                *(ull*)&XS[n * XSS + 2 * cg]      = acc[i][0];
                *(ull*)&XS[n * XSS + 64 + 2 * cg] = acc[i][1];
            }
        }
    }
    __syncthreads();

    // ---------------- P6: proj GEMM  out[n][o] = sum_c O[n][c]*proj_w[o][c] + b[o] ----------------
    // 16 warps: Rn=4, Ro=4: o in {2og+64i}, i<2
    {
        const int og = tid & 31, ng = tid >> 5;
        const int nb = ng * 4;
        const int ob = 2 * og;
        ull acc[4][2];
        #pragma unroll
        for (int j = 0; j < 4; ++j) { acc[j][0] = 0ull; acc[j][1] = 0ull; }

        const int oo = tid & 127, kh = tid >> 7;
        for (int kt = 0; kt < 4; ++kt) {
            __syncthreads();
            {
                const float4* wg = (const float4*)(proj_w + (size_t)oo * CDIM + kt * 32 + kh * 8);
                #pragma unroll
                for (int q4 = 0; q4 < 2; ++q4) {
                    float4 v = wg[q4];
                    int kk = kh * 8 + q4 * 4;
                    SCR[(kk + 0) * WTS + oo] = v.x;
                    SCR[(kk + 1) * WTS + oo] = v.y;
                    SCR[(kk + 2) * WTS + oo] = v.z;
                    SCR[(kk + 3) * WTS + oo] = v.w;
                }
            }
            __syncthreads();
            #pragma unroll 4
            for (int kp = 0; kp < 16; ++kp) {
                const int k0 = kt * 32 + kp * 2;
                ull w0[2], w1[2];
                #pragma unroll
                for (int i = 0; i < 2; ++i) {
                    w0[i] = *(const ull*)&SCR[(kp * 2 + 0) * WTS + ob + 64 * i];
                    w1[i] = *(const ull*)&SCR[(kp * 2 + 1) * WTS + ob + 64 * i];
                }
                #pragma unroll
                for (int j = 0; j < 4; ++j) {
                    ull xp = *(const ull*)&XS[(nb + j) * XSS + k0];
                    float xl, xh; unp2(xp, xl, xh);
                    ull x0 = dup2(xl), x1 = dup2(xh);
                    #pragma unroll
                    for (int i = 0; i < 2; ++i) {
                        fma2(acc[j][i], x0, w0[i]);
                        fma2(acc[j][i], x1, w1[i]);
                    }
                }
            }
        }
        float* og_ptr = out + (size_t)b * NTOK * CDIM;
        #pragma unroll
        for (int j = 0; j < 4; ++j) {
            int n = nb + j;
            if (n < NTOK) {
                #pragma unroll
                for (int i = 0; i < 2; ++i) {
                    int o = ob + 64 * i;
                    float lo, hi;
                    unp2(acc[j][i], lo, hi);
                    float2 r = make_float2(lo + __ldg(&proj_b[o]), hi + __ldg(&proj_b[o + 1]));
                    *(float2*)&og_ptr[n * CDIM + o] = r;
                }
            }
        }
    }
}

extern "C" void kernel_launch(void* const* d_in, const int* in_sizes, int n_in,
                              void* d_out, int out_size)
{
    (void)in_sizes; (void)n_in; (void)out_size;
    const float* x          = (const float*)d_in[0];
    const float* mask       = (const float*)d_in[1];
    const float* qkv_w      = (const float*)d_in[2];
    const float* proj_w     = (const float*)d_in[3];
    const float* proj_b     = (const float*)d_in[4];
    const float* bias_table = (const float*)d_in[5];
    const float* alpha      = (const float*)d_in[6];
    const int*   rel_idx    = (const int*)d_in[7];
    float* out = (float*)d_out;

    cudaFuncSetAttribute(lpwin_attn_kernel,
                         cudaFuncAttributeMaxDynamicSharedMemorySize, SMEM_BYTES);
    lpwin_attn_kernel<<<BWIN, THREADS, SMEM_BYTES>>>(
        x, mask, qkv_w, proj_w, proj_b, bias_table, alpha, rel_idx, out);
}

// round 5
// speedup vs baseline: 1.7228x; 1.0097x over previous
#include <cuda_runtime.h>
#include <math.h>

// Problem constants
#define BWIN 8192
#define NTOK 49
#define CDIM 128
#define HEADS 4
#define HD 32
#define NWIN 4096
#define THREADS 512

// Shared-memory layout strides (in floats)
#define XSS 132           // x / O buffer row stride (64 rows, rows 49..55 zero)
#define QS  388           // qkv row stride (384 + 4 pad)
#define ATS 52            // attn row stride (49 + 3 pad)
#define ATN 56            // attn rows per head (49 + 7 pad)
#define WTS 392           // staged transposed weight tile row stride (k-major)

// float offsets inside dynamic smem
#define OFF_XS    0
#define OFF_QKV   (64*XSS)                       // 8448
#define OFF_SCR   (OFF_QKV + NTOK*QS)            // 27460  (WT 32x392=12544 | ATTN 4x56x52=11648)
#define OFF_MASK  (OFF_SCR + 32*WTS)             // 40004
#define OFF_BIAS  (OFF_MASK + NTOK*NTOK)         // 42405
#define OFF_REL   (OFF_BIAS + 169*4)             // 43081
#define SMEM_FLOATS (OFF_REL + NTOK*NTOK)        // 45482
#define SMEM_BYTES  (SMEM_FLOATS * 4)            // 181928 B

typedef unsigned long long ull;

__device__ __forceinline__ ull dup2(float v){
    ull r; asm("mov.b64 %0, {%1, %1};" : "=l"(r) : "f"(v)); return r;
}
__device__ __forceinline__ ull pack2(float lo, float hi){
    ull r; asm("mov.b64 %0, {%1, %2};" : "=l"(r) : "f"(lo), "f"(hi)); return r;
}
__device__ __forceinline__ void fma2(ull &c, ull a, ull b){
    asm("fma.rn.f32x2 %0, %1, %2, %0;" : "+l"(c) : "l"(a), "l"(b));
}
__device__ __forceinline__ void unp2(ull v, float &lo, float &hi){
    asm("mov.b64 {%0, %1}, %2;" : "=f"(lo), "=f"(hi) : "l"(v));
}

extern __shared__ float smem[];

__global__ void __launch_bounds__(THREADS, 1)
lpwin_attn_kernel(const float* __restrict__ x,
                  const float* __restrict__ mask,
                  const float* __restrict__ qkv_w,
                  const float* __restrict__ proj_w,
                  const float* __restrict__ proj_b,
                  const float* __restrict__ bias_table,
                  const float* __restrict__ alpha,
                  const int*   __restrict__ rel_idx,
                  float* __restrict__ out)
{
    float* XS    = smem + OFF_XS;
    float* QKV   = smem + OFF_QKV;
    float* SCR   = smem + OFF_SCR;
    float* MASKS = smem + OFF_MASK;
    float* BIASS = smem + OFF_BIAS;
    int*   RELS  = (int*)(smem + OFF_REL);

    const int tid = threadIdx.x;
    const int b   = blockIdx.x;
    const int w   = b & (NWIN - 1);

    // ---------------- P1: load x window, mask, rel_idx, bias_table ----------------
    {
        const float4* xg = (const float4*)(x + (size_t)b * NTOK * CDIM);
        for (int i = tid; i < NTOK * 32; i += THREADS) {
            int n = i >> 5, k4 = i & 31;
            float4 v = xg[i];
            *(float4*)&XS[n * XSS + k4 * 4] = v;
        }
        // zero rows 49..55 (read by GEMM row-padding)
        if (tid < 7 * 32) {
            int n = 49 + (tid >> 5), k4 = tid & 31;
            *(float4*)&XS[n * XSS + k4 * 4] = make_float4(0.f, 0.f, 0.f, 0.f);
        }
        const float* mg = mask + (size_t)w * NTOK * NTOK;
        for (int i = tid; i < NTOK * NTOK; i += THREADS) MASKS[i] = mg[i];
        for (int i = tid; i < NTOK * NTOK; i += THREADS) RELS[i]  = rel_idx[i];
        for (int i = tid; i < 169 * 4;   i += THREADS) BIASS[i]  = bias_table[i];
    }

    const int og = tid & 31;             // lane
    const int wg = tid >> 5;             // warp 0..15
    const int oo = tid & 127, kh = tid >> 7;   // staging map

    // ---------------- P2: QKV GEMM  QKV[n][o] = sum_k XS[n][k]*qkv_w[o][k] ----------------
    // warp grid: 8 n-groups x 2 o-halves. lane covers o-pairs {oh*192 + 2og + 64i}, i<3.
    {
        const int oh = wg & 1, ng = wg >> 1;
        const int nb = ng * 7;
        const int ob = oh * 192 + 2 * og;
        ull acc[7][3];
        #pragma unroll
        for (int j = 0; j < 7; ++j)
            #pragma unroll
            for (int i = 0; i < 3; ++i) acc[j][i] = 0ull;

        // register prefetch of weight tile kt=0
        float4 pf[6];
        #pragma unroll
        for (int seg = 0; seg < 3; ++seg) {
            const float4* wgp = (const float4*)(qkv_w + (size_t)(seg * 128 + oo) * CDIM + kh * 8);
            pf[seg * 2 + 0] = wgp[0];
            pf[seg * 2 + 1] = wgp[1];
        }

        for (int kt = 0; kt < 4; ++kt) {
            __syncthreads();
            // store staged tile WT[k_local][o]
            #pragma unroll
            for (int seg = 0; seg < 3; ++seg) {
                int o = seg * 128 + oo;
                #pragma unroll
                for (int q4 = 0; q4 < 2; ++q4) {
                    float4 v = pf[seg * 2 + q4];
                    int kk = kh * 8 + q4 * 4;
                    SCR[(kk + 0) * WTS + o] = v.x;
                    SCR[(kk + 1) * WTS + o] = v.y;
                    SCR[(kk + 2) * WTS + o] = v.z;
                    SCR[(kk + 3) * WTS + o] = v.w;
                }
            }
            if (kt < 3) {
                #pragma unroll
                for (int seg = 0; seg < 3; ++seg) {
                    const float4* wgp = (const float4*)(qkv_w + (size_t)(seg * 128 + oo) * CDIM + (kt + 1) * 32 + kh * 8);
                    pf[seg * 2 + 0] = wgp[0];
                    pf[seg * 2 + 1] = wgp[1];
                }
            }
            __syncthreads();
            #pragma unroll 2
            for (int kq = 0; kq < 8; ++kq) {
                ull wv[4][3];
                #pragma unroll
                for (int kk = 0; kk < 4; ++kk)
                    #pragma unroll
                    for (int i = 0; i < 3; ++i)
                        wv[kk][i] = *(const ull*)&SCR[(kq * 4 + kk) * WTS + ob + 64 * i];
                #pragma unroll
                for (int j = 0; j < 7; ++j) {
                    float4 xq = *(const float4*)&XS[(nb + j) * XSS + kt * 32 + kq * 4];
                    ull x0 = dup2(xq.x), x1 = dup2(xq.y), x2 = dup2(xq.z), x3 = dup2(xq.w);
                    #pragma unroll
                    for (int i = 0; i < 3; ++i) {
                        fma2(acc[j][i], x0, wv[0][i]);
                        fma2(acc[j][i], x1, wv[1][i]);
                        fma2(acc[j][i], x2, wv[2][i]);
                        fma2(acc[j][i], x3, wv[3][i]);
                    }
                }
            }
        }
        __syncthreads();
        #pragma unroll
        for (int j = 0; j < 7; ++j) {
            int n = nb + j;
            if (n < NTOK) {
                #pragma unroll
                for (int i = 0; i < 3; ++i)
                    *(ull*)&QKV[n * QS + ob + 64 * i] = acc[j][i];
            }
        }
    }
    __syncthreads();

    // ---------------- P3: L2-normalize q and k; fold alpha into q ----------------
    if (tid < 2 * HEADS * NTOK) {
        int isq = (tid < HEADS * NTOK);
        int r = isq ? tid : tid - HEADS * NTOK;
        int h = r / NTOK, n = r % NTOK;
        float* base = &QKV[n * QS + (isq ? 0 : 128) + h * HD];
        float ss = 0.f;
        #pragma unroll
        for (int d = 0; d < HD; ++d) { float v = base[d]; ss += v * v; }
        float inv = 1.f / (sqrtf(ss) + 1e-6f);
        if (isq) inv *= __ldg(&alpha[h]);
        #pragma unroll
        for (int d = 0; d < HD; ++d) base[d] *= inv;
    }
    __syncthreads();

    // ---------------- P4: attn[h][n][m] = q_hat . k_hat + rpb + mask (1 row per thread) ----------------
    if (tid < HEADS * NTOK) {
        const int h = tid / NTOK, n = tid % NTOK;
        ull q2[16];
        #pragma unroll
        for (int t = 0; t < 8; ++t) {
            float4 qv = *(const float4*)&QKV[n * QS + h * HD + t * 4];
            q2[2 * t]     = pack2(qv.x, qv.y);
            q2[2 * t + 1] = pack2(qv.z, qv.w);
        }
        float*       arow = &SCR[(h * ATN + n) * ATS];
        const float* mrow = &MASKS[n * NTOK];
        const int*   rrow = &RELS[n * NTOK];
        for (int m = 0; m < NTOK; ++m) {
            ull a = 0ull, c = 0ull;
            #pragma unroll
            for (int t = 0; t < 8; ++t) {
                float4 kv = *(const float4*)&QKV[m * QS + 128 + h * HD + t * 4];
                fma2(a, q2[2 * t],     pack2(kv.x, kv.y));
                fma2(c, q2[2 * t + 1], pack2(kv.z, kv.w));
            }
            float l0, h0v, l1, h1v;
            unp2(a, l0, h0v); unp2(c, l1, h1v);
            float s = (l0 + h0v) + (l1 + h1v);
            arow[m] = s + BIASS[rrow[m] * 4 + h] + mrow[m];
        }
    }
    __syncthreads();

    // ---------------- softmax over m (warp per row) ----------------
    {
        int lane = og, warp = wg;
        for (int r = warp; r < HEADS * NTOK; r += 16) {
            float* arow = &SCR[((r / NTOK) * ATN + (r % NTOK)) * ATS];
            float v0 = arow[lane];
            float v1 = (lane + 32 < NTOK) ? arow[lane + 32] : -1e30f;
            float mx = fmaxf(v0, v1);
            #pragma unroll
            for (int o = 16; o; o >>= 1) mx = fmaxf(mx, __shfl_xor_sync(0xffffffffu, mx, o));
            float e0 = __expf(v0 - mx);
            float e1 = (lane + 32 < NTOK) ? __expf(v1 - mx) : 0.f;
            float sm = e0 + e1;
            #pragma unroll
            for (int o = 16; o; o >>= 1) sm += __shfl_xor_sync(0xffffffffu, sm, o);
            float inv = 1.f / sm;
            arow[lane] = e0 * inv;
            if (lane + 32 < NTOK) arow[lane + 32] = e1 * inv;
        }
    }
    __syncthreads();

    // ---------------- P5: O[n][c] = sum_m attn[h][n][m] * V[m][c] ----------------
    // lane = col-quad (4 consecutive cols), warp = n-group; LDS.128 V loads.
    {
        const int cq = og;              // cols 4cq..4cq+3
        const int h  = cq >> 3;         // head of this quad
        const int ng5 = wg;             // rows ng5 + 16*i
        ull acc[4][2];
        #pragma unroll
        for (int i = 0; i < 4; ++i) { acc[i][0] = 0ull; acc[i][1] = 0ull; }
        for (int m = 0; m < NTOK; ++m) {
            float4 v4 = *(const float4*)&QKV[m * QS + 256 + 4 * cq];
            ull v01 = pack2(v4.x, v4.y), v23 = pack2(v4.z, v4.w);
            #pragma unroll
            for (int i = 0; i < 4; ++i) {
                int n = ng5 + 16 * i;   // up to 63; overreads stay inside SCR allocation
                ull ad = dup2(SCR[(h * ATN + n) * ATS + m]);
                fma2(acc[i][0], ad, v01);
                fma2(acc[i][1], ad, v23);
            }
        }
        #pragma unroll
        for (int i = 0; i < 4; ++i) {
            int n = ng5 + 16 * i;
            if (n < NTOK) {
                *(ull*)&XS[n * XSS + 4 * cq]     = acc[i][0];
                *(ull*)&XS[n * XSS + 4 * cq + 2] = acc[i][1];
            }
        }
    }

    // ---------------- P6: proj GEMM  out[n][o] = sum_c O[n][c]*proj_w[o][c] + b[o] ----------------
    // warp grid: 8 n-groups x 2 o-halves; lane covers o-pair {oh*64 + 2og}.
    {
        const int oh = wg & 1, ng = wg >> 1;
        const int nb = ng * 7;
        const int ob = oh * 64 + 2 * og;
        ull acc[7];
        #pragma unroll
        for (int j = 0; j < 7; ++j) acc[j] = 0ull;

        float4 pf2[2];
        {
            const float4* wgp = (const float4*)(proj_w + (size_t)oo * CDIM + kh * 8);
            pf2[0] = wgp[0]; pf2[1] = wgp[1];
        }

        for (int kt = 0; kt < 4; ++kt) {
            __syncthreads();   // protects SCR (attn reads in P5 / prior tile) and XS (P5 stores)
            #pragma unroll
            for (int q4 = 0; q4 < 2; ++q4) {
                float4 v = pf2[q4];
                int kk = kh * 8 + q4 * 4;
                SCR[(kk + 0) * WTS + oo] = v.x;
                SCR[(kk + 1) * WTS + oo] = v.y;
                SCR[(kk + 2) * WTS + oo] = v.z;
                SCR[(kk + 3) * WTS + oo] = v.w;
            }
            if (kt < 3) {
                const float4* wgp = (const float4*)(proj_w + (size_t)oo * CDIM + (kt + 1) * 32 + kh * 8);
                pf2[0] = wgp[0]; pf2[1] = wgp[1];
            }
            __syncthreads();
            #pragma unroll 4
            for (int kq = 0; kq < 8; ++kq) {
                ull wv[4];
                #pragma unroll
                for (int kk = 0; kk < 4; ++kk)
                    wv[kk] = *(const ull*)&SCR[(kq * 4 + kk) * WTS + ob];
                #pragma unroll
                for (int j = 0; j < 7; ++j) {
                    float4 xq = *(const float4*)&XS[(nb + j) * XSS + kt * 32 + kq * 4];
                    fma2(acc[j], dup2(xq.x), wv[0]);
                    fma2(acc[j], dup2(xq.y), wv[1]);
                    fma2(acc[j], dup2(xq.z), wv[2]);
                    fma2(acc[j], dup2(xq.w), wv[3]);
                }
            }
        }
        float* og_ptr = out + (size_t)b * NTOK * CDIM;
        float b0 = __ldg(&proj_b[ob]), b1 = __ldg(&proj_b[ob + 1]);
        #pragma unroll
        for (int j = 0; j < 7; ++j) {
            int n = nb + j;
            if (n < NTOK) {
                float lo, hi;
                unp2(acc[j], lo, hi);
                *(float2*)&og_ptr[n * CDIM + ob] = make_float2(lo + b0, hi + b1);
            }
        }
    }
}

extern "C" void kernel_launch(void* const* d_in, const int* in_sizes, int n_in,
                              void* d_out, int out_size)
{
    (void)in_sizes; (void)n_in; (void)out_size;
    const float* x          = (const float*)d_in[0];
    const float* mask       = (const float*)d_in[1];
    const float* qkv_w      = (const float*)d_in[2];
    const float* proj_w     = (const float*)d_in[3];
    const float* proj_b     = (const float*)d_in[4];
    const float* bias_table = (const float*)d_in[5];
    const float* alpha      = (const float*)d_in[6];
    const int*   rel_idx    = (const int*)d_in[7];
    float* out = (float*)d_out;

    cudaFuncSetAttribute(lpwin_attn_kernel,
                         cudaFuncAttributeMaxDynamicSharedMemorySize, SMEM_BYTES);
    lpwin_attn_kernel<<<BWIN, THREADS, SMEM_BYTES>>>(
        x, mask, qkv_w, proj_w, proj_b, bias_table, alpha, rel_idx, out);
}

// round 7
// speedup vs baseline: 2.5651x; 1.4889x over previous
#include <cuda_runtime.h>
#include <cuda_bf16.h>
#include <math.h>

// Problem constants
#define BWIN 8192
#define NTOK 49
#define CDIM 128
#define HEADS 4
#define HD 32
#define NWIN 4096
#define THREADS 512

// strides (floats)
#define QS  388           // qkv row stride
#define ATS 52            // attn row stride
#define ATN 56            // attn rows per head

// smem float offsets
#define OFF_QKV  0                    // 49*388 = 19012
#define OFF_ATW  19072                // 24576 floats: W-stage (bf16 hi|lo) / attn / P6 W
#define OFF_X2   43648                // 8192 floats: X bf16 hi|lo, later O bf16 hi|lo
#define OFF_MASK 51840                // 2401
#define OFF_BIAS (OFF_MASK + 2401)    // 676
#define OFF_REL  (OFF_BIAS + 676)     // 2401
#define SMEM_FLOATS (OFF_REL + 2401)  // 57318
#define SMEM_BYTES  (SMEM_FLOATS * 4) // 229272 B

typedef unsigned long long ull;
typedef unsigned int uint;
typedef unsigned short ushort;

__device__ __nv_bfloat16 g_wq_hi[384 * 128];
__device__ __nv_bfloat16 g_wq_lo[384 * 128];
__device__ __nv_bfloat16 g_wp_hi[128 * 128];
__device__ __nv_bfloat16 g_wp_lo[128 * 128];

__device__ __forceinline__ ull dup2(float v){
    ull r; asm("mov.b64 %0, {%1, %1};" : "=l"(r) : "f"(v)); return r;
}
__device__ __forceinline__ ull pack2(float lo, float hi){
    ull r; asm("mov.b64 %0, {%1, %2};" : "=l"(r) : "f"(lo), "f"(hi)); return r;
}
__device__ __forceinline__ void fma2(ull &c, ull a, ull b){
    asm("fma.rn.f32x2 %0, %1, %2, %0;" : "+l"(c) : "l"(a), "l"(b));
}
__device__ __forceinline__ void unp2(ull v, float &lo, float &hi){
    asm("mov.b64 {%0, %1}, %2;" : "=f"(lo), "=f"(hi) : "l"(v));
}
__device__ __forceinline__ uint smem_u32(const void* p){
    uint a; asm("{ .reg .u64 t; cvta.to.shared.u64 t, %1; cvt.u32.u64 %0, t; }" : "=r"(a) : "l"(p));
    return a;
}
__device__ __forceinline__ void ldsm4(uint* r, uint addr){
    asm volatile("ldmatrix.sync.aligned.m8n8.x4.shared.b16 {%0,%1,%2,%3}, [%4];"
        : "=r"(r[0]), "=r"(r[1]), "=r"(r[2]), "=r"(r[3]) : "r"(addr));
}
__device__ __forceinline__ void ldsm2(uint &r0, uint &r1, uint addr){
    asm volatile("ldmatrix.sync.aligned.m8n8.x2.shared.b16 {%0,%1}, [%2];"
        : "=r"(r0), "=r"(r1) : "r"(addr));
}
__device__ __forceinline__ void mma16816(float* d, const uint* a, uint b0, uint b1){
    asm volatile("mma.sync.aligned.m16n8k16.row.col.f32.bf16.bf16.f32 "
        "{%0,%1,%2,%3}, {%4,%5,%6,%7}, {%8,%9}, {%0,%1,%2,%3};"
        : "+f"(d[0]), "+f"(d[1]), "+f"(d[2]), "+f"(d[3])
        : "r"(a[0]), "r"(a[1]), "r"(a[2]), "r"(a[3]), "r"(b0), "r"(b1));
}
__device__ __forceinline__ ushort bfbits(float v){
    __nv_bfloat16 h = __float2bfloat16(v);
    return *(ushort*)&h;
}

extern __shared__ float smem[];

__global__ void conv_w_kernel(const float* __restrict__ qkv_w,
                              const float* __restrict__ proj_w){
    int i = blockIdx.x * blockDim.x + threadIdx.x;
    if (i < 384 * 128) {
        float v = qkv_w[i];
        __nv_bfloat16 h = __float2bfloat16(v);
        g_wq_hi[i] = h;
        g_wq_lo[i] = __float2bfloat16(v - __bfloat162float(h));
    } else if (i < 384 * 128 + 128 * 128) {
        int j = i - 384 * 128;
        float v = proj_w[j];
        __nv_bfloat16 h = __float2bfloat16(v);
        g_wp_hi[j] = h;
        g_wp_lo[j] = __float2bfloat16(v - __bfloat162float(h));
    }
}

__global__ void __launch_bounds__(THREADS, 1)
lpwin_attn_kernel(const float* __restrict__ x,
                  const float* __restrict__ mask,
                  const float* __restrict__ qkv_w,
                  const float* __restrict__ proj_w,
                  const float* __restrict__ proj_b,
                  const float* __restrict__ bias_table,
                  const float* __restrict__ alpha,
                  const int*   __restrict__ rel_idx,
                  float* __restrict__ out)
{
    float* QKV   = smem + OFF_QKV;
    float* ATW   = smem + OFF_ATW;
    float* MASKS = smem + OFF_MASK;
    float* BIASS = smem + OFF_BIAS;
    int*   RELS  = (int*)(smem + OFF_REL);

    const int tid = threadIdx.x;
    const int b   = blockIdx.x;
    const int w   = b & (NWIN - 1);
    const int og  = tid & 31;
    const int wg  = tid >> 5;

    const uint smem_base = smem_u32(smem);
    const uint xhA = smem_base + OFF_X2 * 4;        // X/O bf16 hi (64 rows x 256B)
    const uint xlA = xhA + 16384;                   // bf16 lo
    const uint whA = smem_base + OFF_ATW * 4;       // W bf16 hi (192 rows x 256B)
    const uint wlA = whA + 49152;                   // W bf16 lo
    char* XHb = (char*)smem + OFF_X2 * 4;
    char* XLb = XHb + 16384;
    char* WHb = (char*)smem + OFF_ATW * 4;
    char* WLb = WHb + 49152;

    // ---------------- P1: mask, rel_idx, bias ----------------
    {
        const float* mg = mask + (size_t)w * NTOK * NTOK;
        for (int i = tid; i < NTOK * NTOK; i += THREADS) MASKS[i] = mg[i];
        for (int i = tid; i < NTOK * NTOK; i += THREADS) RELS[i]  = rel_idx[i];
        for (int i = tid; i < 169 * 4;   i += THREADS) BIASS[i]  = bias_table[i];
    }

    // ---------------- P2a: x -> bf16 hi/lo swizzled; zero pad rows; stage W pass 0 ----------------
    {
        const float4* xg4 = (const float4*)(x + (size_t)b * NTOK * CDIM);
        for (int i = tid; i < 49 * 16; i += THREADS) {
            int n = i >> 4, c8 = i & 15;
            float4 a = xg4[n * 32 + c8 * 2];
            float4 c = xg4[n * 32 + c8 * 2 + 1];
            float vs[8] = {a.x, a.y, a.z, a.w, c.x, c.y, c.z, c.w};
            ushort hs[8], ls[8];
            #pragma unroll
            for (int j = 0; j < 8; ++j) {
                __nv_bfloat16 h = __float2bfloat16(vs[j]);
                hs[j] = *(ushort*)&h;
                ls[j] = bfbits(vs[j] - __bfloat162float(h));
            }
            uint off = (uint)n * 256 + (((uint)(c8 ^ (n & 7))) << 4);
            *(uint4*)(XHb + off) = *(uint4*)hs;
            *(uint4*)(XLb + off) = *(uint4*)ls;
        }
        uint4 z = make_uint4(0, 0, 0, 0);
        for (int i = tid; i < 15 * 16; i += THREADS) {
            int n = 49 + (i >> 4), c8 = i & 15;
            uint off = (uint)n * 256 + (((uint)(c8 ^ (n & 7))) << 4);
            *(uint4*)(XHb + off) = z;
            *(uint4*)(XLb + off) = z;
        }
        // stage W rows 0..191 (pass 0)
        for (int i = tid; i < 3072; i += THREADS) {
            int row = i >> 4, c8 = i & 15;
            uint4 hv = ((const uint4*)g_wq_hi)[i];
            uint4 lv = ((const uint4*)g_wq_lo)[i];
            uint off = (uint)row * 256 + (((uint)(c8 ^ (row & 7))) << 4);
            *(uint4*)(WHb + off) = hv;
            *(uint4*)(WLb + off) = lv;
        }
    }
    __syncthreads();

    // ---------------- P2b: QKV GEMM via bf16 3-split mma.sync ----------------
    {
        const int mw = wg & 3, nwg = wg >> 2;
        const int arow = mw * 16 + (og & 15);
        const int ac8  = og >> 4;
        const int brl  = og & 7;
        const int bc8  = (og >> 3) & 1;
        const int g = og >> 2, c = (og & 3) * 2;
        const int n0 = mw * 16 + g;

        for (int pass = 0; pass < 2; ++pass) {
            float acc[6][4];
            #pragma unroll
            for (int t = 0; t < 6; ++t)
                #pragma unroll
                for (int j = 0; j < 4; ++j) acc[t][j] = 0.f;

            #pragma unroll
            for (int ks = 0; ks < 8; ++ks) {
                uint aoff = (uint)arow * 256 + (((uint)((2 * ks + ac8) ^ (arow & 7))) << 4);
                uint ah[4], al[4];
                ldsm4(ah, xhA + aoff);
                ldsm4(al, xlA + aoff);
                #pragma unroll
                for (int t = 0; t < 6; ++t) {
                    int nr = nwg * 48 + t * 8 + brl;
                    uint boff = (uint)nr * 256 + (((uint)((2 * ks + bc8) ^ (nr & 7))) << 4);
                    uint bh0, bh1, bl0, bl1;
                    ldsm2(bh0, bh1, whA + boff);
                    ldsm2(bl0, bl1, wlA + boff);
                    mma16816(acc[t], ah, bh0, bh1);
                    mma16816(acc[t], ah, bl0, bl1);
                    mma16816(acc[t], al, bh0, bh1);
                }
            }
            #pragma unroll
            for (int t = 0; t < 6; ++t) {
                int o = pass * 192 + nwg * 48 + t * 8 + c;
                if (n0 < NTOK)     *(float2*)&QKV[n0 * QS + o]       = make_float2(acc[t][0], acc[t][1]);
                if (n0 + 8 < NTOK) *(float2*)&QKV[(n0 + 8) * QS + o] = make_float2(acc[t][2], acc[t][3]);
            }
            if (pass == 0) {
                __syncthreads();
                for (int i = tid; i < 3072; i += THREADS) {
                    int row = i >> 4, c8 = i & 15;
                    uint4 hv = ((const uint4*)g_wq_hi)[3072 + i];
                    uint4 lv = ((const uint4*)g_wq_lo)[3072 + i];
                    uint off = (uint)row * 256 + (((uint)(c8 ^ (row & 7))) << 4);
                    *(uint4*)(WHb + off) = hv;
                    *(uint4*)(WLb + off) = lv;
                }
                __syncthreads();
            }
        }
    }
    __syncthreads();

    // ---------------- P3: L2-normalize q and k; fold alpha into q ----------------
    if (tid < 2 * HEADS * NTOK) {
        int isq = (tid < HEADS * NTOK);
        int r = isq ? tid : tid - HEADS * NTOK;
        int h = r / NTOK, n = r % NTOK;
        float* base = &QKV[n * QS + (isq ? 0 : 128) + h * HD];
        float ss = 0.f;
        #pragma unroll
        for (int d = 0; d < HD; ++d) { float v = base[d]; ss += v * v; }
        float inv = 1.f / (sqrtf(ss) + 1e-6f);
        if (isq) inv *= __ldg(&alpha[h]);
        #pragma unroll
        for (int d = 0; d < HD; ++d) base[d] *= inv;
    }
    __syncthreads();

    // ---------------- P4: attn[h][n][m] = q.k + rpb + mask ----------------
    if (tid < HEADS * NTOK) {
        const int h = tid / NTOK, n = tid % NTOK;
        ull q2[16];
        #pragma unroll
        for (int t = 0; t < 8; ++t) {
            float4 qv = *(const float4*)&QKV[n * QS + h * HD + t * 4];
            q2[2 * t]     = pack2(qv.x, qv.y);
            q2[2 * t + 1] = pack2(qv.z, qv.w);
        }
        float*       arow = &ATW[(h * ATN + n) * ATS];
        const float* mrow = &MASKS[n * NTOK];
        const int*   rrow = &RELS[n * NTOK];
        for (int m = 0; m < NTOK; ++m) {
            ull a = 0ull, cc = 0ull;
            #pragma unroll
            for (int t = 0; t < 8; ++t) {
                float4 kv = *(const float4*)&QKV[m * QS + 128 + h * HD + t * 4];
                fma2(a,  q2[2 * t],     pack2(kv.x, kv.y));
                fma2(cc, q2[2 * t + 1], pack2(kv.z, kv.w));
            }
            float l0, h0v, l1, h1v;
            unp2(a, l0, h0v); unp2(cc, l1, h1v);
            float s = (l0 + h0v) + (l1 + h1v);
            arow[m] = s + BIASS[rrow[m] * 4 + h] + mrow[m];
        }
    }
    __syncthreads();

    // ---------------- softmax over m (warp per row) ----------------
    {
        for (int r = wg; r < HEADS * NTOK; r += 16) {
            float* arow = &ATW[((r / NTOK) * ATN + (r % NTOK)) * ATS];
            float v0 = arow[og];
            float v1 = (og + 32 < NTOK) ? arow[og + 32] : -1e30f;
            float mx = fmaxf(v0, v1);
            #pragma unroll
            for (int o = 16; o; o >>= 1) mx = fmaxf(mx, __shfl_xor_sync(0xffffffffu, mx, o));
            float e0 = __expf(v0 - mx);
            float e1 = (og + 32 < NTOK) ? __expf(v1 - mx) : 0.f;
            float sm = e0 + e1;
            #pragma unroll
            for (int o = 16; o; o >>= 1) sm += __shfl_xor_sync(0xffffffffu, sm, o);
            float inv = 1.f / sm;
            arow[og] = e0 * inv;
            if (og + 32 < NTOK) arow[og + 32] = e1 * inv;
        }
    }
    __syncthreads();

    // ---------------- P5: O[n][c] = sum_m attn[h][n][m] * V[m][c]; write O as bf16 hi/lo ----------------
    {
        const int cq = og;              // cols 4cq..4cq+3
        const int h  = cq >> 3;
        const int ng5 = wg;
        ull acc[4][2];
        #pragma unroll
        for (int i = 0; i < 4; ++i) { acc[i][0] = 0ull; acc[i][1] = 0ull; }
        for (int m = 0; m < NTOK; ++m) {
            float4 v4 = *(const float4*)&QKV[m * QS + 256 + 4 * cq];
            ull v01 = pack2(v4.x, v4.y), v23 = pack2(v4.z, v4.w);
            #pragma unroll
            for (int i = 0; i < 4; ++i) {
                int n = ng5 + 16 * i;   // up to 63; overreads stay inside ATW region
                ull ad = dup2(ATW[(h * ATN + n) * ATS + m]);
                fma2(acc[i][0], ad, v01);
                fma2(acc[i][1], ad, v23);
            }
        }
        const int c8s = cq >> 1, half = cq & 1;
        #pragma unroll
        for (int i = 0; i < 4; ++i) {
            int n = ng5 + 16 * i;
            if (n < NTOK) {
                float cv[4];
                unp2(acc[i][0], cv[0], cv[1]);
                unp2(acc[i][1], cv[2], cv[3]);
                ushort hs[4], ls[4];
                #pragma unroll
                for (int j = 0; j < 4; ++j) {
                    __nv_bfloat16 hb = __float2bfloat16(cv[j]);
                    hs[j] = *(ushort*)&hb;
                    ls[j] = bfbits(cv[j] - __bfloat162float(hb));
                }
                uint off = (uint)n * 256 + (((uint)(c8s ^ (n & 7))) << 4) + half * 8;
                *(ull*)(XHb + off) = *(ull*)hs;
                *(ull*)(XLb + off) = *(ull*)ls;
            }
        }
    }
    __syncthreads();

    // ---------------- P6a: stage proj W bf16 hi/lo ----------------
    for (int i = tid; i < 2048; i += THREADS) {
        int row = i >> 4, c8 = i & 15;
        uint4 hv = ((const uint4*)g_wp_hi)[i];
        uint4 lv = ((const uint4*)g_wp_lo)[i];
        uint off = (uint)row * 256 + (((uint)(c8 ^ (row & 7))) << 4);
        *(uint4*)(WHb + off) = hv;
        *(uint4*)(WLb + off) = lv;
    }
    __syncthreads();

    // ---------------- P6b: proj GEMM via bf16 3-split mma.sync ----------------
    {
        const int mw = wg & 3, nwg = wg >> 2;
        const int arow = mw * 16 + (og & 15);
        const int ac8  = og >> 4;
        const int brl  = og & 7;
        const int bc8  = (og >> 3) & 1;
        float acc[4][4];
        #pragma unroll
        for (int t = 0; t < 4; ++t)
            #pragma unroll
            for (int j = 0; j < 4; ++j) acc[t][j] = 0.f;

        #pragma unroll
        for (int ks = 0; ks < 8; ++ks) {
            uint aoff = (uint)arow * 256 + (((uint)((2 * ks + ac8) ^ (arow & 7))) << 4);
            uint ah[4], al[4];
            ldsm4(ah, xhA + aoff);
            ldsm4(al, xlA + aoff);
            #pragma unroll
            for (int t = 0; t < 4; ++t) {
                int nr = nwg * 32 + t * 8 + brl;
                uint boff = (uint)nr * 256 + (((uint)((2 * ks + bc8) ^ (nr & 7))) << 4);
                uint bh0, bh1, bl0, bl1;
                ldsm2(bh0, bh1, whA + boff);
                ldsm2(bl0, bl1, wlA + boff);
                mma16816(acc[t], ah, bh0, bh1);
                mma16816(acc[t], ah, bl0, bl1);
                mma16816(acc[t], al, bh0, bh1);
            }
        }
        float* og_ptr = out + (size_t)b * NTOK * CDIM;
        const int g = og >> 2, c = (og & 3) * 2;
        const int n0 = mw * 16 + g;
        #pragma unroll
        for (int t = 0; t < 4; ++t) {
            int o = nwg * 32 + t * 8 + c;
            float b0 = __ldg(&proj_b[o]), b1 = __ldg(&proj_b[o + 1]);
            if (n0 < NTOK)
                *(float2*)&og_ptr[n0 * CDIM + o] = make_float2(acc[t][0] + b0, acc[t][1] + b1);
            if (n0 + 8 < NTOK)
                *(float2*)&og_ptr[(n0 + 8) * CDIM + o] = make_float2(acc[t][2] + b0, acc[t][3] + b1);
        }
    }
}

extern "C" void kernel_launch(void* const* d_in, const int* in_sizes, int n_in,
                              void* d_out, int out_size)
{
    (void)in_sizes; (void)n_in; (void)out_size;
    const float* x          = (const float*)d_in[0];
    const float* mask       = (const float*)d_in[1];
    const float* qkv_w      = (const float*)d_in[2];
    const float* proj_w     = (const float*)d_in[3];
    const float* proj_b     = (const float*)d_in[4];
    const float* bias_table = (const float*)d_in[5];
    const float* alpha      = (const float*)d_in[6];
    const int*   rel_idx    = (const int*)d_in[7];
    float* out = (float*)d_out;

    conv_w_kernel<<<(384 * 128 + 128 * 128 + 255) / 256, 256>>>(qkv_w, proj_w);

    cudaFuncSetAttribute(lpwin_attn_kernel,
                         cudaFuncAttributeMaxDynamicSharedMemorySize, SMEM_BYTES);
    lpwin_attn_kernel<<<BWIN, THREADS, SMEM_BYTES>>>(
        x, mask, qkv_w, proj_w, proj_b, bias_table, alpha, rel_idx, out);
}

// round 8
// speedup vs baseline: 2.9054x; 1.1327x over previous
#include <cuda_runtime.h>
#include <cuda_bf16.h>
#include <math.h>

// Problem constants
#define BWIN 8192
#define NTOK 49
#define CDIM 128
#define HEADS 4
#define HD 32
#define NWIN 4096
#define THREADS 512

// strides (floats)
#define QS  388           // qkv f32 row stride
#define ATS 57            // attn row stride (conflict-free for tf32 frag loads)
#define ATN 56            // attn rows per head

// smem float offsets
#define OFF_QKV  0                    // 56*388 = 21728 (rows 49..55 zeroed)
#define OFF_ATW  21728                // 16384: W-stage bf16 hi|lo (128 rows) / attn f32 (4*56*57=12768)
#define OFF_X2   38112                // 8192: X bf16 hi|lo -> O bf16 hi|lo
#define OFF_MASK 46304                // 2401
#define OFF_BIAS 48705                // 676
#define OFF_REL  49381                // 2401
#define SMEM_FLOATS 51782
#define SMEM_BYTES  (SMEM_FLOATS * 4) // 207128 B

typedef unsigned long long ull;
typedef unsigned int uint;
typedef unsigned short ushort;

__device__ __nv_bfloat16 g_wq_hi[384 * 128];
__device__ __nv_bfloat16 g_wq_lo[384 * 128];
__device__ __nv_bfloat16 g_wp_hi[128 * 128];
__device__ __nv_bfloat16 g_wp_lo[128 * 128];

__device__ __forceinline__ uint smem_u32(const void* p){
    uint a; asm("{ .reg .u64 t; cvta.to.shared.u64 t, %1; cvt.u32.u64 %0, t; }" : "=r"(a) : "l"(p));
    return a;
}
__device__ __forceinline__ void ldsm4(uint* r, uint addr){
    asm volatile("ldmatrix.sync.aligned.m8n8.x4.shared.b16 {%0,%1,%2,%3}, [%4];"
        : "=r"(r[0]), "=r"(r[1]), "=r"(r[2]), "=r"(r[3]) : "r"(addr));
}
__device__ __forceinline__ void ldsm2(uint &r0, uint &r1, uint addr){
    asm volatile("ldmatrix.sync.aligned.m8n8.x2.shared.b16 {%0,%1}, [%2];"
        : "=r"(r0), "=r"(r1) : "r"(addr));
}
__device__ __forceinline__ void mma16816(float* d, const uint* a, uint b0, uint b1){
    asm volatile("mma.sync.aligned.m16n8k16.row.col.f32.bf16.bf16.f32 "
        "{%0,%1,%2,%3}, {%4,%5,%6,%7}, {%8,%9}, {%0,%1,%2,%3};"
        : "+f"(d[0]), "+f"(d[1]), "+f"(d[2]), "+f"(d[3])
        : "r"(a[0]), "r"(a[1]), "r"(a[2]), "r"(a[3]), "r"(b0), "r"(b1));
}
__device__ __forceinline__ void mma1688(float* d, const uint* a, uint b0, uint b1){
    asm volatile("mma.sync.aligned.m16n8k8.row.col.f32.tf32.tf32.f32 "
        "{%0,%1,%2,%3}, {%4,%5,%6,%7}, {%8,%9}, {%0,%1,%2,%3};"
        : "+f"(d[0]), "+f"(d[1]), "+f"(d[2]), "+f"(d[3])
        : "r"(a[0]), "r"(a[1]), "r"(a[2]), "r"(a[3]), "r"(b0), "r"(b1));
}
__device__ __forceinline__ uint tf32c(float v){
    uint r; asm("cvt.rna.tf32.f32 %0, %1;" : "=r"(r) : "f"(v)); return r;
}
__device__ __forceinline__ ushort bfbits(float v){
    __nv_bfloat16 h = __float2bfloat16(v);
    return *(ushort*)&h;
}

extern __shared__ float smem[];

__global__ void conv_w_kernel(const float* __restrict__ qkv_w,
                              const float* __restrict__ proj_w){
    int i = blockIdx.x * blockDim.x + threadIdx.x;
    if (i < 384 * 128) {
        float v = qkv_w[i];
        __nv_bfloat16 h = __float2bfloat16(v);
        g_wq_hi[i] = h;
        g_wq_lo[i] = __float2bfloat16(v - __bfloat162float(h));
    } else if (i < 384 * 128 + 128 * 128) {
        int j = i - 384 * 128;
        float v = proj_w[j];
        __nv_bfloat16 h = __float2bfloat16(v);
        g_wp_hi[j] = h;
        g_wp_lo[j] = __float2bfloat16(v - __bfloat162float(h));
    }
}

__global__ void __launch_bounds__(THREADS, 1)
lpwin_attn_kernel(const float* __restrict__ x,
                  const float* __restrict__ mask,
                  const float* __restrict__ qkv_w,
                  const float* __restrict__ proj_w,
                  const float* __restrict__ proj_b,
                  const float* __restrict__ bias_table,
                  const float* __restrict__ alpha,
                  const int*   __restrict__ rel_idx,
                  float* __restrict__ out)
{
    float* QKV   = smem + OFF_QKV;
    float* ATW   = smem + OFF_ATW;
    float* MASKS = smem + OFF_MASK;
    float* BIASS = smem + OFF_BIAS;
    int*   RELS  = (int*)(smem + OFF_REL);

    const int tid = threadIdx.x;
    const int b   = blockIdx.x;
    const int w   = b & (NWIN - 1);
    const int og  = tid & 31;
    const int wg  = tid >> 5;

    const uint smem_base = smem_u32(smem);
    const uint xhA = smem_base + OFF_X2 * 4;        // X/O bf16 hi (64 rows x 256B)
    const uint xlA = xhA + 16384;                   // bf16 lo
    const uint whA = smem_base + OFF_ATW * 4;       // W bf16 hi (128 rows x 256B)
    const uint wlA = whA + 32768;                   // W bf16 lo
    char* XHb = (char*)smem + OFF_X2 * 4;
    char* XLb = XHb + 16384;
    char* WHb = (char*)smem + OFF_ATW * 4;
    char* WLb = WHb + 32768;

    // ---------------- P1: mask, rel_idx, bias; zero QKV pad rows ----------------
    {
        const float* mg = mask + (size_t)w * NTOK * NTOK;
        for (int i = tid; i < NTOK * NTOK; i += THREADS) MASKS[i] = mg[i];
        for (int i = tid; i < NTOK * NTOK; i += THREADS) RELS[i]  = rel_idx[i];
        for (int i = tid; i < 169 * 4;   i += THREADS) BIASS[i]  = bias_table[i];
        for (int i = tid; i < 7 * QS;    i += THREADS) QKV[49 * QS + i] = 0.f;
    }

    // ---------------- P2a: x -> bf16 hi/lo swizzled; zero pad rows; stage W rows 0..127 ----------------
    {
        const float4* xg4 = (const float4*)(x + (size_t)b * NTOK * CDIM);
        for (int i = tid; i < 49 * 16; i += THREADS) {
            int n = i >> 4, c8 = i & 15;
            float4 a = xg4[n * 32 + c8 * 2];
            float4 c = xg4[n * 32 + c8 * 2 + 1];
            float vs[8] = {a.x, a.y, a.z, a.w, c.x, c.y, c.z, c.w};
            ushort hs[8], ls[8];
            #pragma unroll
            for (int j = 0; j < 8; ++j) {
                __nv_bfloat16 h = __float2bfloat16(vs[j]);
                hs[j] = *(ushort*)&h;
                ls[j] = bfbits(vs[j] - __bfloat162float(h));
            }
            uint off = (uint)n * 256 + (((uint)(c8 ^ (n & 7))) << 4);
            *(uint4*)(XHb + off) = *(uint4*)hs;
            *(uint4*)(XLb + off) = *(uint4*)ls;
        }
        uint4 z = make_uint4(0, 0, 0, 0);
        for (int i = tid; i < 15 * 16; i += THREADS) {
            int n = 49 + (i >> 4), c8 = i & 15;
            uint off = (uint)n * 256 + (((uint)(c8 ^ (n & 7))) << 4);
            *(uint4*)(XHb + off) = z;
            *(uint4*)(XLb + off) = z;
        }
        for (int i = tid; i < 2048; i += THREADS) {
            int row = i >> 4, c8 = i & 15;
            uint4 hv = ((const uint4*)g_wq_hi)[i];
            uint4 lv = ((const uint4*)g_wq_lo)[i];
            uint off = (uint)row * 256 + (((uint)(c8 ^ (row & 7))) << 4);
            *(uint4*)(WHb + off) = hv;
            *(uint4*)(WLb + off) = lv;
        }
    }
    __syncthreads();

    // ---------------- P2b: QKV GEMM via bf16 3-split mma.sync, 3 passes of 128 W rows ----------------
    {
        const int mw = wg & 3, nwg = wg >> 2;
        const int arow = mw * 16 + (og & 15);
        const int ac8  = og >> 4;
        const int brl  = og & 7;
        const int bc8  = (og >> 3) & 1;
        const int g = og >> 2, c = (og & 3) * 2;
        const int n0 = mw * 16 + g;

        for (int pass = 0; pass < 3; ++pass) {
            float acc[4][4];
            #pragma unroll
            for (int t = 0; t < 4; ++t)
                #pragma unroll
                for (int j = 0; j < 4; ++j) acc[t][j] = 0.f;

            #pragma unroll
            for (int ks = 0; ks < 8; ++ks) {
                uint aoff = (uint)arow * 256 + (((uint)((2 * ks + ac8) ^ (arow & 7))) << 4);
                uint ah[4], al[4];
                ldsm4(ah, xhA + aoff);
                ldsm4(al, xlA + aoff);
                #pragma unroll
                for (int t = 0; t < 4; ++t) {
                    int nr = nwg * 32 + t * 8 + brl;
                    uint boff = (uint)nr * 256 + (((uint)((2 * ks + bc8) ^ (nr & 7))) << 4);
                    uint bh0, bh1, bl0, bl1;
                    ldsm2(bh0, bh1, whA + boff);
                    ldsm2(bl0, bl1, wlA + boff);
                    mma16816(acc[t], ah, bh0, bh1);
                    mma16816(acc[t], ah, bl0, bl1);
                    mma16816(acc[t], al, bh0, bh1);
                }
            }
            #pragma unroll
            for (int t = 0; t < 4; ++t) {
                int o = pass * 128 + nwg * 32 + t * 8 + c;
                if (n0 < NTOK)     *(float2*)&QKV[n0 * QS + o]       = make_float2(acc[t][0], acc[t][1]);
                if (n0 + 8 < NTOK) *(float2*)&QKV[(n0 + 8) * QS + o] = make_float2(acc[t][2], acc[t][3]);
            }
            if (pass < 2) {
                __syncthreads();
                for (int i = tid; i < 2048; i += THREADS) {
                    int row = i >> 4, c8 = i & 15;
                    uint4 hv = ((const uint4*)g_wq_hi)[(pass + 1) * 2048 + i];
                    uint4 lv = ((const uint4*)g_wq_lo)[(pass + 1) * 2048 + i];
                    uint off = (uint)row * 256 + (((uint)(c8 ^ (row & 7))) << 4);
                    *(uint4*)(WHb + off) = hv;
                    *(uint4*)(WLb + off) = lv;
                }
                __syncthreads();
            }
        }
    }
    __syncthreads();

    // ---------------- P3: L2-normalize q and k; fold alpha into q ----------------
    if (tid < 2 * HEADS * NTOK) {
        int isq = (tid < HEADS * NTOK);
        int r = isq ? tid : tid - HEADS * NTOK;
        int h = r / NTOK, n = r % NTOK;
        float* base = &QKV[n * QS + (isq ? 0 : 128) + h * HD];
        float ss = 0.f;
        #pragma unroll
        for (int d = 0; d < HD; ++d) { float v = base[d]; ss += v * v; }
        float inv = 1.f / (sqrtf(ss) + 1e-6f);
        if (isq) inv *= __ldg(&alpha[h]);
        #pragma unroll
        for (int d = 0; d < HD; ++d) base[d] *= inv;
    }
    __syncthreads();

    // ---------------- P4: attn logits via tf32 3-split mma (warp = head x m16-tile) ----------------
    {
        const int h = wg >> 2, mt = wg & 3;
        const int g = og >> 2, tig = og & 3;
        float acc[7][4];
        #pragma unroll
        for (int t = 0; t < 7; ++t)
            #pragma unroll
            for (int j = 0; j < 4; ++j) acc[t][j] = 0.f;

        #pragma unroll
        for (int ks = 0; ks < 4; ++ks) {
            const int d0 = h * 32 + ks * 8 + tig;
            float a0f = QKV[(mt * 16 + g) * QS + d0];
            float a1f = QKV[(mt * 16 + g + 8) * QS + d0];
            float a2f = QKV[(mt * 16 + g) * QS + d0 + 4];
            float a3f = QKV[(mt * 16 + g + 8) * QS + d0 + 4];
            uint ah[4] = {tf32c(a0f), tf32c(a1f), tf32c(a2f), tf32c(a3f)};
            uint al[4] = {tf32c(a0f - __uint_as_float(ah[0])),
                          tf32c(a1f - __uint_as_float(ah[1])),
                          tf32c(a2f - __uint_as_float(ah[2])),
                          tf32c(a3f - __uint_as_float(ah[3]))};
            #pragma unroll
            for (int nt = 0; nt < 7; ++nt) {
                int tok = nt * 8 + g;                 // K token (rows 49..55 zeroed)
                float b0f = QKV[tok * QS + 128 + d0];
                float b1f = QKV[tok * QS + 128 + d0 + 4];
                uint bh0 = tf32c(b0f), bh1 = tf32c(b1f);
                uint bl0 = tf32c(b0f - __uint_as_float(bh0));
                uint bl1 = tf32c(b1f - __uint_as_float(bh1));
                mma1688(acc[nt], ah, bh0, bh1);
                mma1688(acc[nt], ah, bl0, bl1);
                mma1688(acc[nt], al, bh0, bh1);
            }
        }
        const int n0 = mt * 16 + g;
        #pragma unroll
        for (int nt = 0; nt < 7; ++nt) {
            int m0 = nt * 8 + 2 * tig;
            if (n0 < NTOK) {
                if (m0 < NTOK)
                    ATW[(h * ATN + n0) * ATS + m0] = acc[nt][0] + BIASS[RELS[n0 * NTOK + m0] * 4 + h] + MASKS[n0 * NTOK + m0];
                if (m0 + 1 < NTOK)
                    ATW[(h * ATN + n0) * ATS + m0 + 1] = acc[nt][1] + BIASS[RELS[n0 * NTOK + m0 + 1] * 4 + h] + MASKS[n0 * NTOK + m0 + 1];
            }
            if (n0 + 8 < NTOK) {
                if (m0 < NTOK)
                    ATW[(h * ATN + n0 + 8) * ATS + m0] = acc[nt][2] + BIASS[RELS[(n0 + 8) * NTOK + m0] * 4 + h] + MASKS[(n0 + 8) * NTOK + m0];
                if (m0 + 1 < NTOK)
                    ATW[(h * ATN + n0 + 8) * ATS + m0 + 1] = acc[nt][3] + BIASS[RELS[(n0 + 8) * NTOK + m0 + 1] * 4 + h] + MASKS[(n0 + 8) * NTOK + m0 + 1];
            }
        }
    }
    __syncthreads();

    // ---------------- softmax over m (warp per row); zero pad cols 49..55 ----------------
    {
        for (int r = wg; r < HEADS * NTOK; r += 16) {
            float* arow = &ATW[((r / NTOK) * ATN + (r % NTOK)) * ATS];
            float v0 = arow[og];
            float v1 = (og + 32 < NTOK) ? arow[og + 32] : -1e30f;
            float mx = fmaxf(v0, v1);
            #pragma unroll
            for (int o = 16; o; o >>= 1) mx = fmaxf(mx, __shfl_xor_sync(0xffffffffu, mx, o));
            float e0 = __expf(v0 - mx);
            float e1 = (og + 32 < NTOK) ? __expf(v1 - mx) : 0.f;
            float sm = e0 + e1;
            #pragma unroll
            for (int o = 16; o; o >>= 1) sm += __shfl_xor_sync(0xffffffffu, sm, o);
            float inv = 1.f / sm;
            arow[og] = e0 * inv;
            if (og + 32 < NTOK) arow[og + 32] = e1 * inv;
            else if (og + 32 < 56) arow[og + 32] = 0.f;
        }
    }
    __syncthreads();

    // ---------------- P5: O = attn @ V via tf32 3-split mma; write O bf16 hi/lo ----------------
    {
        const int h = wg >> 2, mt = wg & 3;
        const int g = og >> 2, tig = og & 3;
        float acc[4][4];
        #pragma unroll
        for (int t = 0; t < 4; ++t)
            #pragma unroll
            for (int j = 0; j < 4; ++j) acc[t][j] = 0.f;

        #pragma unroll
        for (int ks = 0; ks < 7; ++ks) {
            const int k0 = ks * 8 + tig;          // token index (pad cols zeroed)
            float a0f = ATW[(h * ATN + mt * 16 + g) * ATS + k0];
            float a1f = ATW[(h * ATN + mt * 16 + g + 8) * ATS + k0];
            float a2f = ATW[(h * ATN + mt * 16 + g) * ATS + k0 + 4];
            float a3f = ATW[(h * ATN + mt * 16 + g + 8) * ATS + k0 + 4];
            uint ah[4] = {tf32c(a0f), tf32c(a1f), tf32c(a2f), tf32c(a3f)};
            uint al[4] = {tf32c(a0f - __uint_as_float(ah[0])),
                          tf32c(a1f - __uint_as_float(ah[1])),
                          tf32c(a2f - __uint_as_float(ah[2])),
                          tf32c(a3f - __uint_as_float(ah[3]))};
            #pragma unroll
            for (int nt = 0; nt < 4; ++nt) {
                int vc = 256 + h * 32 + nt * 8 + g;
                float b0f = QKV[k0 * QS + vc];          // V rows 49..55 zeroed
                float b1f = QKV[(k0 + 4) * QS + vc];
                uint bh0 = tf32c(b0f), bh1 = tf32c(b1f);
                uint bl0 = tf32c(b0f - __uint_as_float(bh0));
                uint bl1 = tf32c(b1f - __uint_as_float(bh1));
                mma1688(acc[nt], ah, bh0, bh1);
                mma1688(acc[nt], ah, bl0, bl1);
                mma1688(acc[nt], al, bh0, bh1);
            }
        }
        const int n0 = mt * 16 + g;
        #pragma unroll
        for (int nt = 0; nt < 4; ++nt) {
            int col = h * 32 + nt * 8 + 2 * tig;
            #pragma unroll
            for (int half = 0; half < 2; ++half) {
                int n = n0 + 8 * half;
                if (n < NTOK) {
                    float v0 = acc[nt][2 * half], v1 = acc[nt][2 * half + 1];
                    __nv_bfloat16 hb0 = __float2bfloat16(v0), hb1 = __float2bfloat16(v1);
                    ushort hs0 = *(ushort*)&hb0, hs1 = *(ushort*)&hb1;
                    ushort ls0 = bfbits(v0 - __bfloat162float(hb0));
                    ushort ls1 = bfbits(v1 - __bfloat162float(hb1));
                    uint off = (uint)n * 256 + (((uint)((col >> 3) ^ (n & 7))) << 4) + ((uint)(col & 7)) * 2;
                    *(uint*)(XHb + off) = ((uint)hs1 << 16) | hs0;
                    *(uint*)(XLb + off) = ((uint)ls1 << 16) | ls0;
                }
            }
        }
    }
    __syncthreads();

    // ---------------- P6a: stage proj W bf16 hi/lo ----------------
    for (int i = tid; i < 2048; i += THREADS) {
        int row = i >> 4, c8 = i & 15;
        uint4 hv = ((const uint4*)g_wp_hi)[i];
        uint4 lv = ((const uint4*)g_wp_lo)[i];
        uint off = (uint)row * 256 + (((uint)(c8 ^ (row & 7))) << 4);
        *(uint4*)(WHb + off) = hv;
        *(uint4*)(WLb + off) = lv;
    }
    __syncthreads();

    // ---------------- P6b: proj GEMM via bf16 3-split mma.sync ----------------
    {
        const int mw = wg & 3, nwg = wg >> 2;
        const int arow = mw * 16 + (og & 15);
        const int ac8  = og >> 4;
        const int brl  = og & 7;
        const int bc8  = (og >> 3) & 1;
        float acc[4][4];
        #pragma unroll
        for (int t = 0; t < 4; ++t)
            #pragma unroll
            for (int j = 0; j < 4; ++j) acc[t][j] = 0.f;

        #pragma unroll
        for (int ks = 0; ks < 8; ++ks) {
            uint aoff = (uint)arow * 256 + (((uint)((2 * ks + ac8) ^ (arow & 7))) << 4);
            uint ah[4], al[4];
            ldsm4(ah, xhA + aoff);
            ldsm4(al, xlA + aoff);
            #pragma unroll
            for (int t = 0; t < 4; ++t) {
                int nr = nwg * 32 + t * 8 + brl;
                uint boff = (uint)nr * 256 + (((uint)((2 * ks + bc8) ^ (nr & 7))) << 4);
                uint bh0, bh1, bl0, bl1;
                ldsm2(bh0, bh1, whA + boff);
                ldsm2(bl0, bl1, wlA + boff);
                mma16816(acc[t], ah, bh0, bh1);
                mma16816(acc[t], ah, bl0, bl1);
                mma16816(acc[t], al, bh0, bh1);
            }
        }
        float* og_ptr = out + (size_t)b * NTOK * CDIM;
        const int g = og >> 2, c = (og & 3) * 2;
        const int n0 = mw * 16 + g;
        #pragma unroll
        for (int t = 0; t < 4; ++t) {
            int o = nwg * 32 + t * 8 + c;
            float b0 = __ldg(&proj_b[o]), b1 = __ldg(&proj_b[o + 1]);
            if (n0 < NTOK)
                *(float2*)&og_ptr[n0 * CDIM + o] = make_float2(acc[t][0] + b0, acc[t][1] + b1);
            if (n0 + 8 < NTOK)
                *(float2*)&og_ptr[(n0 + 8) * CDIM + o] = make_float2(acc[t][2] + b0, acc[t][3] + b1);
        }
    }
}

extern "C" void kernel_launch(void* const* d_in, const int* in_sizes, int n_in,
                              void* d_out, int out_size)
{
    (void)in_sizes; (void)n_in; (void)out_size;
    const float* x          = (const float*)d_in[0];
    const float* mask       = (const float*)d_in[1];
    const float* qkv_w      = (const float*)d_in[2];
    const float* proj_w     = (const float*)d_in[3];
    const float* proj_b     = (const float*)d_in[4];
    const float* bias_table = (const float*)d_in[5];
    const float* alpha      = (const float*)d_in[6];
    const int*   rel_idx    = (const int*)d_in[7];
    float* out = (float*)d_out;

    conv_w_kernel<<<(384 * 128 + 128 * 128 + 255) / 256, 256>>>(qkv_w, proj_w);

    cudaFuncSetAttribute(lpwin_attn_kernel,
                         cudaFuncAttributeMaxDynamicSharedMemorySize, SMEM_BYTES);
    lpwin_attn_kernel<<<BWIN, THREADS, SMEM_BYTES>>>(
        x, mask, qkv_w, proj_w, proj_b, bias_table, alpha, rel_idx, out);
}

// round 9
// speedup vs baseline: 3.1535x; 1.0854x over previous
#include <cuda_runtime.h>
#include <cuda_bf16.h>
#include <math.h>

// Problem constants
#define BWIN 8192
#define NTOK 49
#define CDIM 128
#define HEADS 4
#define HD 32
#define NWIN 4096
#define THREADS 512

// strides (floats)
#define QS  388           // qkv f32 row stride
#define ATS 57            // logits row stride
#define ATN 56            // logits rows per head

// smem float offsets (region A = [0, 21728) : QKV f32 -> logits f32 -> O bf16)
#define OFF_QKV  0
#define OFF_ATL  0
#define OFF_OB   13056                // O bf16 hi|lo (8192 floats = 32KB), after logits (12768)
#define OFF_B    21728                // 16384 floats (64KB): Wqkv-stage | Q^K^ bf16 | P bf16 | Wproj-stage
#define OFF_C    38112                // 8192 floats (32KB): X bf16 hi|lo | V^T bf16 hi|lo
#define OFF_MASK 46304                // 2401
#define OFF_BIAS 48705                // 676
#define OFF_REL  49381                // 2401
#define SMEM_FLOATS 51782
#define SMEM_BYTES  (SMEM_FLOATS * 4) // 207128 B

typedef unsigned long long ull;
typedef unsigned int uint;
typedef unsigned short ushort;

__device__ __nv_bfloat16 g_wq_hi[384 * 128];
__device__ __nv_bfloat16 g_wq_lo[384 * 128];
__device__ __nv_bfloat16 g_wp_hi[128 * 128];
__device__ __nv_bfloat16 g_wp_lo[128 * 128];

__device__ __forceinline__ uint smem_u32(const void* p){
    uint a; asm("{ .reg .u64 t; cvta.to.shared.u64 t, %1; cvt.u32.u64 %0, t; }" : "=r"(a) : "l"(p));
    return a;
}
__device__ __forceinline__ void ldsm4(uint* r, uint addr){
    asm volatile("ldmatrix.sync.aligned.m8n8.x4.shared.b16 {%0,%1,%2,%3}, [%4];"
        : "=r"(r[0]), "=r"(r[1]), "=r"(r[2]), "=r"(r[3]) : "r"(addr));
}
__device__ __forceinline__ void ldsm2(uint &r0, uint &r1, uint addr){
    asm volatile("ldmatrix.sync.aligned.m8n8.x2.shared.b16 {%0,%1}, [%2];"
        : "=r"(r0), "=r"(r1) : "r"(addr));
}
__device__ __forceinline__ void mma16816(float* d, const uint* a, uint b0, uint b1){
    asm volatile("mma.sync.aligned.m16n8k16.row.col.f32.bf16.bf16.f32 "
        "{%0,%1,%2,%3}, {%4,%5,%6,%7}, {%8,%9}, {%0,%1,%2,%3};"
        : "+f"(d[0]), "+f"(d[1]), "+f"(d[2]), "+f"(d[3])
        : "r"(a[0]), "r"(a[1]), "r"(a[2]), "r"(a[3]), "r"(b0), "r"(b1));
}
__device__ __forceinline__ ushort bfbits(float v){
    __nv_bfloat16 h = __float2bfloat16(v);
    return *(ushort*)&h;
}

extern __shared__ float smem[];

__global__ void conv_w_kernel(const float* __restrict__ qkv_w,
                              const float* __restrict__ proj_w){
    int i = blockIdx.x * blockDim.x + threadIdx.x;
    if (i < 384 * 128) {
        float v = qkv_w[i];
        __nv_bfloat16 h = __float2bfloat16(v);
        g_wq_hi[i] = h;
        g_wq_lo[i] = __float2bfloat16(v - __bfloat162float(h));
    } else if (i < 384 * 128 + 128 * 128) {
        int j = i - 384 * 128;
        float v = proj_w[j];
        __nv_bfloat16 h = __float2bfloat16(v);
        g_wp_hi[j] = h;
        g_wp_lo[j] = __float2bfloat16(v - __bfloat162float(h));
    }
}

__global__ void __launch_bounds__(THREADS, 1)
lpwin_attn_kernel(const float* __restrict__ x,
                  const float* __restrict__ mask,
                  const float* __restrict__ qkv_w,
                  const float* __restrict__ proj_w,
                  const float* __restrict__ proj_b,
                  const float* __restrict__ bias_table,
                  const float* __restrict__ alpha,
                  const int*   __restrict__ rel_idx,
                  float* __restrict__ out)
{
    float* QKV   = smem + OFF_QKV;
    float* ATL   = smem + OFF_ATL;
    float* MASKS = smem + OFF_MASK;
    float* BIASS = smem + OFF_BIAS;
    int*   RELS  = (int*)(smem + OFF_REL);

    const int tid = threadIdx.x;
    const int b   = blockIdx.x;
    const int w   = b & (NWIN - 1);
    const int og  = tid & 31;
    const int wg  = tid >> 5;

    const uint smem_base = smem_u32(smem);
    const uint bB = smem_base + OFF_B * 4;
    const uint bC = smem_base + OFF_C * 4;
    // region B aliases
    const uint whA = bB,            wlA = bB + 32768;
    const uint qhA = bB,            qlA = bB + 16384;
    const uint khA = bB + 32768,    klA = bB + 49152;
    const uint phA = bB,            plA = bB + 32768;
    // region C aliases
    const uint xhA = bC,            xlA = bC + 16384;
    const uint vhA = bC,            vlA = bC + 16384;
    // region A (O bf16)
    const uint ohA = smem_base + OFF_OB * 4, olA = ohA + 16384;

    char* XHb = (char*)smem + OFF_C * 4;
    char* XLb = XHb + 16384;
    char* VHb = XHb;
    char* VLb = XHb + 16384;
    char* WHb = (char*)smem + OFF_B * 4;
    char* WLb = WHb + 32768;
    char* QHb = WHb;
    char* QLb = WHb + 16384;
    char* KHb = WHb + 32768;
    char* KLb = WHb + 49152;
    char* PHb = WHb;
    char* PLb = WHb + 32768;
    char* OHb = (char*)smem + OFF_OB * 4;
    char* OLb = OHb + 16384;

    // ---------------- P1: mask, rel_idx, bias ----------------
    {
        const float* mg = mask + (size_t)w * NTOK * NTOK;
        for (int i = tid; i < NTOK * NTOK; i += THREADS) MASKS[i] = mg[i];
        for (int i = tid; i < NTOK * NTOK; i += THREADS) RELS[i]  = rel_idx[i];
        for (int i = tid; i < 169 * 4;   i += THREADS) BIASS[i]  = bias_table[i];
    }

    // ---------------- P2a: x -> bf16 hi/lo swizzled; zero pad rows; stage W rows 0..127 ----------------
    {
        const float4* xg4 = (const float4*)(x + (size_t)b * NTOK * CDIM);
        for (int i = tid; i < 49 * 16; i += THREADS) {
            int n = i >> 4, c8 = i & 15;
            float4 a = xg4[n * 32 + c8 * 2];
            float4 c = xg4[n * 32 + c8 * 2 + 1];
            float vs[8] = {a.x, a.y, a.z, a.w, c.x, c.y, c.z, c.w};
            ushort hs[8], ls[8];
            #pragma unroll
            for (int j = 0; j < 8; ++j) {
                __nv_bfloat16 h = __float2bfloat16(vs[j]);
                hs[j] = *(ushort*)&h;
                ls[j] = bfbits(vs[j] - __bfloat162float(h));
            }
            uint off = (uint)n * 256 + (((uint)(c8 ^ (n & 7))) << 4);
            *(uint4*)(XHb + off) = *(uint4*)hs;
            *(uint4*)(XLb + off) = *(uint4*)ls;
        }
        uint4 z = make_uint4(0, 0, 0, 0);
        for (int i = tid; i < 15 * 16; i += THREADS) {
            int n = 49 + (i >> 4), c8 = i & 15;
            uint off = (uint)n * 256 + (((uint)(c8 ^ (n & 7))) << 4);
            *(uint4*)(XHb + off) = z;
            *(uint4*)(XLb + off) = z;
        }
        for (int i = tid; i < 2048; i += THREADS) {
            int row = i >> 4, c8 = i & 15;
            uint4 hv = ((const uint4*)g_wq_hi)[i];
            uint4 lv = ((const uint4*)g_wq_lo)[i];
            uint off = (uint)row * 256 + (((uint)(c8 ^ (row & 7))) << 4);
            *(uint4*)(WHb + off) = hv;
            *(uint4*)(WLb + off) = lv;
        }
    }
    __syncthreads();

    // ---------------- P2b: QKV GEMM via bf16 3-split mma.sync, 3 passes of 128 W rows ----------------
    {
        const int mw = wg & 3, nwg = wg >> 2;
        const int arow = mw * 16 + (og & 15);
        const int ac8  = og >> 4;
        const int brl  = og & 7;
        const int bc8  = (og >> 3) & 1;
        const int g = og >> 2, c = (og & 3) * 2;
        const int n0 = mw * 16 + g;

        for (int pass = 0; pass < 3; ++pass) {
            float acc[4][4];
            #pragma unroll
            for (int t = 0; t < 4; ++t)
                #pragma unroll
                for (int j = 0; j < 4; ++j) acc[t][j] = 0.f;

            #pragma unroll
            for (int ks = 0; ks < 8; ++ks) {
                uint aoff = (uint)arow * 256 + (((uint)((2 * ks + ac8) ^ (arow & 7))) << 4);
                uint ah[4], al[4];
                ldsm4(ah, xhA + aoff);
                ldsm4(al, xlA + aoff);
                #pragma unroll
                for (int t = 0; t < 4; ++t) {
                    int nr = nwg * 32 + t * 8 + brl;
                    uint boff = (uint)nr * 256 + (((uint)((2 * ks + bc8) ^ (nr & 7))) << 4);
                    uint bh0, bh1, bl0, bl1;
                    ldsm2(bh0, bh1, whA + boff);
                    ldsm2(bl0, bl1, wlA + boff);
                    mma16816(acc[t], ah, bh0, bh1);
                    mma16816(acc[t], ah, bl0, bl1);
                    mma16816(acc[t], al, bh0, bh1);
                }
            }
            #pragma unroll
            for (int t = 0; t < 4; ++t) {
                int o = pass * 128 + nwg * 32 + t * 8 + c;
                if (n0 < NTOK)     *(float2*)&QKV[n0 * QS + o]       = make_float2(acc[t][0], acc[t][1]);
                if (n0 + 8 < NTOK) *(float2*)&QKV[(n0 + 8) * QS + o] = make_float2(acc[t][2], acc[t][3]);
            }
            if (pass < 2) {
                __syncthreads();
                for (int i = tid; i < 2048; i += THREADS) {
                    int row = i >> 4, c8 = i & 15;
                    uint4 hv = ((const uint4*)g_wq_hi)[(pass + 1) * 2048 + i];
                    uint4 lv = ((const uint4*)g_wq_lo)[(pass + 1) * 2048 + i];
                    uint off = (uint)row * 256 + (((uint)(c8 ^ (row & 7))) << 4);
                    *(uint4*)(WHb + off) = hv;
                    *(uint4*)(WLb + off) = lv;
                }
                __syncthreads();
            }
        }
    }
    __syncthreads();

    // ---------------- P3: normalize q,k -> Q^/K^ bf16 hi/lo; V -> V^T bf16 hi/lo (m-padded) ----------------
    if (tid < 392) {
        int isq = (tid < 196);
        int r = isq ? tid : tid - 196;
        int h = r / NTOK, n = r % NTOK;
        const float* base = &QKV[n * QS + (isq ? 0 : 128) + h * HD];
        float v[32];
        float ss = 0.f;
        #pragma unroll
        for (int d = 0; d < 32; ++d) { v[d] = base[d]; ss += v[d] * v[d]; }
        float inv = 1.f / (sqrtf(ss) + 1e-6f);
        if (isq) inv *= __ldg(&alpha[h]);
        char* Hb = isq ? QHb : KHb;
        char* Lb = isq ? QLb : KLb;
        #pragma unroll
        for (int g8 = 0; g8 < 4; ++g8) {
            ushort hs[8], ls[8];
            #pragma unroll
            for (int j = 0; j < 8; ++j) {
                float val = v[g8 * 8 + j] * inv;
                __nv_bfloat16 hb = __float2bfloat16(val);
                hs[j] = *(ushort*)&hb;
                ls[j] = bfbits(val - __bfloat162float(hb));
            }
            int c8 = h * 4 + g8;
            uint off = (uint)n * 256 + (((uint)(c8 ^ (n & 7))) << 4);
            *(uint4*)(Hb + off) = *(uint4*)hs;
            *(uint4*)(Lb + off) = *(uint4*)ls;
        }
    }
    // V^T: rows = channel c (128), cols = token m (64, zero-padded >= 49)
    for (int i = tid; i < 1024; i += THREADS) {
        int c = i & 127, mg = i >> 7;   // c contiguous across threads -> conflict-free
        ushort hs[8], ls[8];
        #pragma unroll
        for (int j = 0; j < 8; ++j) {
            int m = mg * 8 + j;
            float val = (m < NTOK) ? QKV[m * QS + 256 + c] : 0.f;
            __nv_bfloat16 hb = __float2bfloat16(val);
            hs[j] = *(ushort*)&hb;
            ls[j] = bfbits(val - __bfloat162float(hb));
        }
        uint off = (uint)c * 128 + (((uint)(mg ^ (c & 7))) << 4);
        *(uint4*)(VHb + off) = *(uint4*)hs;
        *(uint4*)(VLb + off) = *(uint4*)ls;
    }
    __syncthreads();

    // ---------------- P4: logits = q^.k^ via bf16 3-split mma; + rpb + mask -> ATL f32 ----------------
    {
        const int h = wg >> 2, mt = wg & 3;
        const int arow = mt * 16 + (og & 15);
        const int ac8  = og >> 4;
        const int brl  = og & 7;
        const int bc8  = (og >> 3) & 1;
        float acc[7][4];
        #pragma unroll
        for (int t = 0; t < 7; ++t)
            #pragma unroll
            for (int j = 0; j < 4; ++j) acc[t][j] = 0.f;

        #pragma unroll
        for (int ks = 0; ks < 2; ++ks) {
            uint aoff = (uint)arow * 256 + (((uint)((h * 4 + 2 * ks + ac8) ^ (arow & 7))) << 4);
            uint ah[4], al[4];
            ldsm4(ah, qhA + aoff);
            ldsm4(al, qlA + aoff);
            #pragma unroll
            for (int nt = 0; nt < 7; ++nt) {
                int tok = nt * 8 + brl;
                uint boff = (uint)tok * 256 + (((uint)((h * 4 + 2 * ks + bc8) ^ (tok & 7))) << 4);
                uint bh0, bh1, bl0, bl1;
                ldsm2(bh0, bh1, khA + boff);
                ldsm2(bl0, bl1, klA + boff);
                mma16816(acc[nt], ah, bh0, bh1);
                mma16816(acc[nt], ah, bl0, bl1);
                mma16816(acc[nt], al, bh0, bh1);
            }
        }
        const int g = og >> 2, tig = og & 3;
        const int n0 = mt * 16 + g;
        #pragma unroll
        for (int nt = 0; nt < 7; ++nt) {
            int m0 = nt * 8 + 2 * tig;
            if (n0 < NTOK) {
                if (m0 < NTOK)
                    ATL[(h * ATN + n0) * ATS + m0] = acc[nt][0] + BIASS[RELS[n0 * NTOK + m0] * 4 + h] + MASKS[n0 * NTOK + m0];
                if (m0 + 1 < NTOK)
                    ATL[(h * ATN + n0) * ATS + m0 + 1] = acc[nt][1] + BIASS[RELS[n0 * NTOK + m0 + 1] * 4 + h] + MASKS[n0 * NTOK + m0 + 1];
            }
            if (n0 + 8 < NTOK) {
                if (m0 < NTOK)
                    ATL[(h * ATN + n0 + 8) * ATS + m0] = acc[nt][2] + BIASS[RELS[(n0 + 8) * NTOK + m0] * 4 + h] + MASKS[(n0 + 8) * NTOK + m0];
                if (m0 + 1 < NTOK)
                    ATL[(h * ATN + n0 + 8) * ATS + m0 + 1] = acc[nt][3] + BIASS[RELS[(n0 + 8) * NTOK + m0 + 1] * 4 + h] + MASKS[(n0 + 8) * NTOK + m0 + 1];
            }
        }
    }
    __syncthreads();

    // ---------------- softmax; write P as bf16 hi/lo (cols 49..63 zero) ----------------
    {
        for (int r = wg; r < HEADS * NTOK; r += 16) {
            int h = r / NTOK, n = r % NTOK;
            float* arow = &ATL[(h * ATN + n) * ATS];
            float v0 = arow[og];
            float v1 = (og + 32 < NTOK) ? arow[og + 32] : -1e30f;
            float mx = fmaxf(v0, v1);
            #pragma unroll
            for (int o = 16; o; o >>= 1) mx = fmaxf(mx, __shfl_xor_sync(0xffffffffu, mx, o));
            float e0 = __expf(v0 - mx);
            float e1 = (og + 32 < NTOK) ? __expf(v1 - mx) : 0.f;
            float sm = e0 + e1;
            #pragma unroll
            for (int o = 16; o; o >>= 1) sm += __shfl_xor_sync(0xffffffffu, sm, o);
            float inv = 1.f / sm;
            float p0 = e0 * inv, p1 = e1 * inv;
            // col og
            {
                __nv_bfloat16 hb = __float2bfloat16(p0);
                ushort hs = *(ushort*)&hb;
                ushort ls = bfbits(p0 - __bfloat162float(hb));
                uint off = (uint)h * 8192 + (uint)n * 128 + (((uint)((og >> 3) ^ (n & 7))) << 4) + ((uint)(og & 7)) * 2;
                *(ushort*)(PHb + off) = hs;
                *(ushort*)(PLb + off) = ls;
            }
            // col og+32 (zeros beyond NTOK, through 63)
            {
                int cc = og + 32;
                __nv_bfloat16 hb = __float2bfloat16(p1);
                ushort hs = *(ushort*)&hb;
                ushort ls = bfbits(p1 - __bfloat162float(hb));
                uint off = (uint)h * 8192 + (uint)n * 128 + (((uint)((cc >> 3) ^ (n & 7))) << 4) + ((uint)(cc & 7)) * 2;
                *(ushort*)(PHb + off) = hs;
                *(ushort*)(PLb + off) = ls;
            }
        }
    }
    __syncthreads();

    // ---------------- P5: O = P @ V via bf16 3-split mma; write O bf16 hi/lo ----------------
    {
        const int h = wg >> 2, mt = wg & 3;
        const int arow = mt * 16 + (og & 15);
        const int ac8  = og >> 4;
        const int brl  = og & 7;
        const int bc8  = (og >> 3) & 1;
        float acc[4][4];
        #pragma unroll
        for (int t = 0; t < 4; ++t)
            #pragma unroll
            for (int j = 0; j < 4; ++j) acc[t][j] = 0.f;

        #pragma unroll
        for (int ks = 0; ks < 4; ++ks) {
            uint aoff = (uint)h * 8192 + (uint)arow * 128 + (((uint)((2 * ks + ac8) ^ (arow & 7))) << 4);
            uint ah[4], al[4];
            ldsm4(ah, phA + aoff);
            ldsm4(al, plA + aoff);
            #pragma unroll
            for (int nt = 0; nt < 4; ++nt) {
                int nr = h * 32 + nt * 8 + brl;          // V^T row = channel
                uint boff = (uint)nr * 128 + (((uint)((2 * ks + bc8) ^ (nr & 7))) << 4);
                uint bh0, bh1, bl0, bl1;
                ldsm2(bh0, bh1, vhA + boff);
                ldsm2(bl0, bl1, vlA + boff);
                mma16816(acc[nt], ah, bh0, bh1);
                mma16816(acc[nt], ah, bl0, bl1);
                mma16816(acc[nt], al, bh0, bh1);
            }
        }
        const int g = og >> 2, tig = og & 3;
        const int n0 = mt * 16 + g;
        #pragma unroll
        for (int nt = 0; nt < 4; ++nt) {
            int col = h * 32 + nt * 8 + 2 * tig;
            #pragma unroll
            for (int half = 0; half < 2; ++half) {
                int n = n0 + 8 * half;
                if (n < NTOK) {
                    float v0 = acc[nt][2 * half], v1 = acc[nt][2 * half + 1];
                    __nv_bfloat16 hb0 = __float2bfloat16(v0), hb1 = __float2bfloat16(v1);
                    ushort hs0 = *(ushort*)&hb0, hs1 = *(ushort*)&hb1;
                    ushort ls0 = bfbits(v0 - __bfloat162float(hb0));
                    ushort ls1 = bfbits(v1 - __bfloat162float(hb1));
                    uint off = (uint)n * 256 + (((uint)((col >> 3) ^ (n & 7))) << 4) + ((uint)(col & 7)) * 2;
                    *(uint*)(OHb + off) = ((uint)hs1 << 16) | hs0;
                    *(uint*)(OLb + off) = ((uint)ls1 << 16) | ls0;
                }
            }
        }
    }
    __syncthreads();

    // ---------------- P6a: stage proj W bf16 hi/lo ----------------
    for (int i = tid; i < 2048; i += THREADS) {
        int row = i >> 4, c8 = i & 15;
        uint4 hv = ((const uint4*)g_wp_hi)[i];
        uint4 lv = ((const uint4*)g_wp_lo)[i];
        uint off = (uint)row * 256 + (((uint)(c8 ^ (row & 7))) << 4);
        *(uint4*)(WHb + off) = hv;
        *(uint4*)(WLb + off) = lv;
    }
    __syncthreads();

    // ---------------- P6b: proj GEMM via bf16 3-split mma.sync ----------------
    {
        const int mw = wg & 3, nwg = wg >> 2;
        const int arow = mw * 16 + (og & 15);
        const int ac8  = og >> 4;
        const int brl  = og & 7;
        const int bc8  = (og >> 3) & 1;
        float acc[4][4];
        #pragma unroll
        for (int t = 0; t < 4; ++t)
            #pragma unroll
            for (int j = 0; j < 4; ++j) acc[t][j] = 0.f;

        #pragma unroll
        for (int ks = 0; ks < 8; ++ks) {
            uint aoff = (uint)arow * 256 + (((uint)((2 * ks + ac8) ^ (arow & 7))) << 4);
            uint ah[4], al[4];
            ldsm4(ah, ohA + aoff);
            ldsm4(al, olA + aoff);
            #pragma unroll
            for (int t = 0; t < 4; ++t) {
                int nr = nwg * 32 + t * 8 + brl;
                uint boff = (uint)nr * 256 + (((uint)((2 * ks + bc8) ^ (nr & 7))) << 4);
                uint bh0, bh1, bl0, bl1;
                ldsm2(bh0, bh1, whA + boff);
                ldsm2(bl0, bl1, wlA + boff);
                mma16816(acc[t], ah, bh0, bh1);
                mma16816(acc[t], ah, bl0, bl1);
                mma16816(acc[t], al, bh0, bh1);
            }
        }
        float* og_ptr = out + (size_t)b * NTOK * CDIM;
        const int g = og >> 2, c = (og & 3) * 2;
        const int n0 = mw * 16 + g;
        #pragma unroll
        for (int t = 0; t < 4; ++t) {
            int o = nwg * 32 + t * 8 + c;
            float b0 = __ldg(&proj_b[o]), b1 = __ldg(&proj_b[o + 1]);
            if (n0 < NTOK)
                *(float2*)&og_ptr[n0 * CDIM + o] = make_float2(acc[t][0] + b0, acc[t][1] + b1);
            if (n0 + 8 < NTOK)
                *(float2*)&og_ptr[(n0 + 8) * CDIM + o] = make_float2(acc[t][2] + b0, acc[t][3] + b1);
        }
    }
}

extern "C" void kernel_launch(void* const* d_in, const int* in_sizes, int n_in,
                              void* d_out, int out_size)
{
    (void)in_sizes; (void)n_in; (void)out_size;
    const float* x          = (const float*)d_in[0];
    const float* mask       = (const float*)d_in[1];
    const float* qkv_w      = (const float*)d_in[2];
    const float* proj_w     = (const float*)d_in[3];
    const float* proj_b     = (const float*)d_in[4];
    const float* bias_table = (const float*)d_in[5];
    const float* alpha      = (const float*)d_in[6];
    const int*   rel_idx    = (const int*)d_in[7];
    float* out = (float*)d_out;

    conv_w_kernel<<<(384 * 128 + 128 * 128 + 255) / 256, 256>>>(qkv_w, proj_w);

    cudaFuncSetAttribute(lpwin_attn_kernel,
                         cudaFuncAttributeMaxDynamicSharedMemorySize, SMEM_BYTES);
    lpwin_attn_kernel<<<BWIN, THREADS, SMEM_BYTES>>>(
        x, mask, qkv_w, proj_w, proj_b, bias_table, alpha, rel_idx, out);
}

// round 10
// speedup vs baseline: 3.3980x; 1.0775x over previous
#include <cuda_runtime.h>
#include <cuda_bf16.h>
#include <math.h>

// Problem constants
#define BWIN 8192
#define NTOK 49
#define CDIM 128
#define HEADS 4
#define HD 32
#define NWIN 4096
#define THREADS 512

// strides (floats)
#define QS  388           // qkv f32 row stride
#define ATS 57            // logits row stride
#define ATN 56            // logits rows per head

// smem float offsets (region A = [0, 21728) : QKV f32 -> logits f32 -> O bf16)
#define OFF_QKV  0
#define OFF_ATL  0
#define OFF_OB   13056                // O bf16 hi|lo (8192 floats = 32KB)
#define OFF_B    21728                // 16384 floats (64KB): Wqkv-stage | Q^K^ bf16 | P bf16 | Wproj-stage
#define OFF_C    38112                // 8192 floats (32KB): X bf16 hi|lo | V^T bf16 hi|lo
#define OFF_MASK 46304                // 2401
#define SMEM_FLOATS 48705
#define SMEM_BYTES  (SMEM_FLOATS * 4) // 194820 B

typedef unsigned long long ull;
typedef unsigned int uint;
typedef unsigned short ushort;

__device__ __nv_bfloat16 g_wq_hi[384 * 128];
__device__ __nv_bfloat16 g_wq_lo[384 * 128];
__device__ __nv_bfloat16 g_wp_hi[128 * 128];
__device__ __nv_bfloat16 g_wp_lo[128 * 128];
__device__ float g_rpb[HEADS * 49 * 50];   // [h][n][m], row stride 50 (8B-aligned float2 reads)

__device__ __forceinline__ uint smem_u32(const void* p){
    uint a; asm("{ .reg .u64 t; cvta.to.shared.u64 t, %1; cvt.u32.u64 %0, t; }" : "=r"(a) : "l"(p));
    return a;
}
__device__ __forceinline__ void ldsm4(uint* r, uint addr){
    asm volatile("ldmatrix.sync.aligned.m8n8.x4.shared.b16 {%0,%1,%2,%3}, [%4];"
        : "=r"(r[0]), "=r"(r[1]), "=r"(r[2]), "=r"(r[3]) : "r"(addr));
}
__device__ __forceinline__ void ldsm2(uint &r0, uint &r1, uint addr){
    asm volatile("ldmatrix.sync.aligned.m8n8.x2.shared.b16 {%0,%1}, [%2];"
        : "=r"(r0), "=r"(r1) : "r"(addr));
}
__device__ __forceinline__ void mma16816(float* d, const uint* a, uint b0, uint b1){
    asm volatile("mma.sync.aligned.m16n8k16.row.col.f32.bf16.bf16.f32 "
        "{%0,%1,%2,%3}, {%4,%5,%6,%7}, {%8,%9}, {%0,%1,%2,%3};"
        : "+f"(d[0]), "+f"(d[1]), "+f"(d[2]), "+f"(d[3])
        : "r"(a[0]), "r"(a[1]), "r"(a[2]), "r"(a[3]), "r"(b0), "r"(b1));
}
__device__ __forceinline__ ushort bfbits(float v){
    __nv_bfloat16 h = __float2bfloat16(v);
    return *(ushort*)&h;
}

extern __shared__ float smem[];

__global__ void conv_w_kernel(const float* __restrict__ qkv_w,
                              const float* __restrict__ proj_w,
                              const float* __restrict__ bias_table,
                              const int*   __restrict__ rel_idx){
    int i = blockIdx.x * blockDim.x + threadIdx.x;
    if (i < 384 * 128) {
        float v = qkv_w[i];
        __nv_bfloat16 h = __float2bfloat16(v);
        g_wq_hi[i] = h;
        g_wq_lo[i] = __float2bfloat16(v - __bfloat162float(h));
    } else if (i < 384 * 128 + 128 * 128) {
        int j = i - 384 * 128;
        float v = proj_w[j];
        __nv_bfloat16 h = __float2bfloat16(v);
        g_wp_hi[j] = h;
        g_wp_lo[j] = __float2bfloat16(v - __bfloat162float(h));
    } else if (i < 384 * 128 + 128 * 128 + HEADS * 2401) {
        int j = i - (384 * 128 + 128 * 128);
        int h = j / 2401, e = j % 2401;
        int n = e / 49, m = e % 49;
        g_rpb[h * 2450 + n * 50 + m] = bias_table[rel_idx[e] * 4 + h];
    }
}

__global__ void __launch_bounds__(THREADS, 1)
lpwin_attn_kernel(const float* __restrict__ x,
                  const float* __restrict__ mask,
                  const float* __restrict__ qkv_w,
                  const float* __restrict__ proj_w,
                  const float* __restrict__ proj_b,
                  const float* __restrict__ bias_table,
                  const float* __restrict__ alpha,
                  const int*   __restrict__ rel_idx,
                  float* __restrict__ out)
{
    float* QKV   = smem + OFF_QKV;
    float* ATL   = smem + OFF_ATL;
    float* MASKS = smem + OFF_MASK;

    const int tid = threadIdx.x;
    const int b   = blockIdx.x;
    const int w   = b & (NWIN - 1);
    const int og  = tid & 31;
    const int wg  = tid >> 5;

    const uint smem_base = smem_u32(smem);
    const uint bB = smem_base + OFF_B * 4;
    const uint bC = smem_base + OFF_C * 4;
    const uint whA = bB,            wlA = bB + 32768;
    const uint qhA = bB,            qlA = bB + 16384;
    const uint khA = bB + 32768,    klA = bB + 49152;
    const uint phA = bB,            plA = bB + 32768;
    const uint xhA = bC,            xlA = bC + 16384;
    const uint vhA = bC,            vlA = bC + 16384;
    const uint ohA = smem_base + OFF_OB * 4, olA = ohA + 16384;

    char* XHb = (char*)smem + OFF_C * 4;
    char* XLb = XHb + 16384;
    char* VHb = XHb;
    char* VLb = XHb + 16384;
    char* WHb = (char*)smem + OFF_B * 4;
    char* WLb = WHb + 32768;
    char* QHb = WHb;
    char* QLb = WHb + 16384;
    char* KHb = WHb + 32768;
    char* KLb = WHb + 49152;
    char* PHb = WHb;
    char* PLb = WHb + 32768;
    char* OHb = (char*)smem + OFF_OB * 4;
    char* OLb = OHb + 16384;

    // lane decompositions for MMA fragment addressing
    const int brl  = og & 7;                       // ldsm2 row-in-tile
    const int bc8g = (og >> 3) & 1;                // ldsm2/4 k-half
    const int brl2 = (og & 7) + ((og & 16) >> 1);  // ldsm4 two-tile row (0..15)

    // ---------------- P1: mask ----------------
    {
        const float* mg = mask + (size_t)w * NTOK * NTOK;
        for (int i = tid; i < NTOK * NTOK; i += THREADS) MASKS[i] = mg[i];
    }

    // ---------------- P2a: x -> bf16 hi/lo swizzled; zero pad rows; stage W rows 0..127 ----------------
    {
        const float4* xg4 = (const float4*)(x + (size_t)b * NTOK * CDIM);
        for (int i = tid; i < 49 * 16; i += THREADS) {
            int n = i >> 4, c8 = i & 15;
            float4 a = xg4[n * 32 + c8 * 2];
            float4 c = xg4[n * 32 + c8 * 2 + 1];
            float vs[8] = {a.x, a.y, a.z, a.w, c.x, c.y, c.z, c.w};
            ushort hs[8], ls[8];
            #pragma unroll
            for (int j = 0; j < 8; ++j) {
                __nv_bfloat16 h = __float2bfloat16(vs[j]);
                hs[j] = *(ushort*)&h;
                ls[j] = bfbits(vs[j] - __bfloat162float(h));
            }
            uint off = (uint)n * 256 + (((uint)(c8 ^ (n & 7))) << 4);
            *(uint4*)(XHb + off) = *(uint4*)hs;
            *(uint4*)(XLb + off) = *(uint4*)ls;
        }
        uint4 z = make_uint4(0, 0, 0, 0);
        for (int i = tid; i < 15 * 16; i += THREADS) {
            int n = 49 + (i >> 4), c8 = i & 15;
            uint off = (uint)n * 256 + (((uint)(c8 ^ (n & 7))) << 4);
            *(uint4*)(XHb + off) = z;
            *(uint4*)(XLb + off) = z;
        }
        for (int i = tid; i < 2048; i += THREADS) {
            int row = i >> 4, c8 = i & 15;
            uint4 hv = ((const uint4*)g_wq_hi)[i];
            uint4 lv = ((const uint4*)g_wq_lo)[i];
            uint off = (uint)row * 256 + (((uint)(c8 ^ (row & 7))) << 4);
            *(uint4*)(WHb + off) = hv;
            *(uint4*)(WLb + off) = lv;
        }
    }
    __syncthreads();

    // ---------------- P2b: QKV GEMM via bf16 3-split mma.sync, 3 passes of 128 W rows ----------------
    {
        const int mw = wg & 3, nwg = wg >> 2;
        const int arow = mw * 16 + (og & 15);
        const int ac8  = og >> 4;
        const int g = og >> 2, c = (og & 3) * 2;
        const int n0 = mw * 16 + g;

        for (int pass = 0; pass < 3; ++pass) {
            float acc[4][4];
            #pragma unroll
            for (int t = 0; t < 4; ++t)
                #pragma unroll
                for (int j = 0; j < 4; ++j) acc[t][j] = 0.f;

            #pragma unroll
            for (int ks = 0; ks < 8; ++ks) {
                uint aoff = (uint)arow * 256 + (((uint)((2 * ks + ac8) ^ (arow & 7))) << 4);
                uint ah[4], al[4];
                ldsm4(ah, xhA + aoff);
                ldsm4(al, xlA + aoff);
                #pragma unroll
                for (int tp = 0; tp < 2; ++tp) {
                    int nr = nwg * 32 + tp * 16 + brl2;
                    uint boff = (uint)nr * 256 + (((uint)((2 * ks + bc8g) ^ (nr & 7))) << 4);
                    uint bh[4], bl[4];
                    ldsm4(bh, whA + boff);
                    ldsm4(bl, wlA + boff);
                    mma16816(acc[2 * tp],     ah, bh[0], bh[1]);
                    mma16816(acc[2 * tp],     ah, bl[0], bl[1]);
                    mma16816(acc[2 * tp],     al, bh[0], bh[1]);
                    mma16816(acc[2 * tp + 1], ah, bh[2], bh[3]);
                    mma16816(acc[2 * tp + 1], ah, bl[2], bl[3]);
                    mma16816(acc[2 * tp + 1], al, bh[2], bh[3]);
                }
            }
            #pragma unroll
            for (int t = 0; t < 4; ++t) {
                int o = pass * 128 + nwg * 32 + t * 8 + c;
                if (n0 < NTOK)     *(float2*)&QKV[n0 * QS + o]       = make_float2(acc[t][0], acc[t][1]);
                if (n0 + 8 < NTOK) *(float2*)&QKV[(n0 + 8) * QS + o] = make_float2(acc[t][2], acc[t][3]);
            }
            if (pass < 2) {
                __syncthreads();
                for (int i = tid; i < 2048; i += THREADS) {
                    int row = i >> 4, c8 = i & 15;
                    uint4 hv = ((const uint4*)g_wq_hi)[(pass + 1) * 2048 + i];
                    uint4 lv = ((const uint4*)g_wq_lo)[(pass + 1) * 2048 + i];
                    uint off = (uint)row * 256 + (((uint)(c8 ^ (row & 7))) << 4);
                    *(uint4*)(WHb + off) = hv;
                    *(uint4*)(WLb + off) = lv;
                }
                __syncthreads();
            }
        }
    }
    __syncthreads();

    // ---------------- P3: normalize q,k -> Q^/K^ bf16 hi/lo; V -> V^T bf16 hi/lo (m-padded) ----------------
    if (tid < 392) {
        int isq = (tid < 196);
        int r = isq ? tid : tid - 196;
        int h = r / NTOK, n = r % NTOK;
        const float* base = &QKV[n * QS + (isq ? 0 : 128) + h * HD];
        float v[32];
        float ss = 0.f;
        #pragma unroll
        for (int d = 0; d < 32; ++d) { v[d] = base[d]; ss += v[d] * v[d]; }
        float inv = 1.f / (sqrtf(ss) + 1e-6f);
        if (isq) inv *= __ldg(&alpha[h]);
        char* Hb = isq ? QHb : KHb;
        char* Lb = isq ? QLb : KLb;
        #pragma unroll
        for (int g8 = 0; g8 < 4; ++g8) {
            ushort hs[8], ls[8];
            #pragma unroll
            for (int j = 0; j < 8; ++j) {
                float val = v[g8 * 8 + j] * inv;
                __nv_bfloat16 hb = __float2bfloat16(val);
                hs[j] = *(ushort*)&hb;
                ls[j] = bfbits(val - __bfloat162float(hb));
            }
            int c8 = h * 4 + g8;
            uint off = (uint)n * 256 + (((uint)(c8 ^ (n & 7))) << 4);
            *(uint4*)(Hb + off) = *(uint4*)hs;
            *(uint4*)(Lb + off) = *(uint4*)ls;
        }
    }
    // V^T: rows = channel c (128), cols = token m (64, zero-padded >= 49)
    for (int i = tid; i < 1024; i += THREADS) {
        int c = i & 127, mg = i >> 7;
        ushort hs[8], ls[8];
        #pragma unroll
        for (int j = 0; j < 8; ++j) {
            int m = mg * 8 + j;
            float val = (m < NTOK) ? QKV[m * QS + 256 + c] : 0.f;
            __nv_bfloat16 hb = __float2bfloat16(val);
            hs[j] = *(ushort*)&hb;
            ls[j] = bfbits(val - __bfloat162float(hb));
        }
        uint off = (uint)c * 128 + (((uint)(mg ^ (c & 7))) << 4);
        *(uint4*)(VHb + off) = *(uint4*)hs;
        *(uint4*)(VLb + off) = *(uint4*)ls;
    }
    __syncthreads();

    // ---------------- P4: logits = q^.k^ via bf16 3-split mma; + rpb + mask -> ATL f32 ----------------
    {
        const int h = wg >> 2, mt = wg & 3;
        const int arow = mt * 16 + (og & 15);
        const int ac8  = og >> 4;
        float acc[7][4];
        #pragma unroll
        for (int t = 0; t < 7; ++t)
            #pragma unroll
            for (int j = 0; j < 4; ++j) acc[t][j] = 0.f;

        #pragma unroll
        for (int ks = 0; ks < 2; ++ks) {
            uint aoff = (uint)arow * 256 + (((uint)((h * 4 + 2 * ks + ac8) ^ (arow & 7))) << 4);
            uint ah[4], al[4];
            ldsm4(ah, qhA + aoff);
            ldsm4(al, qlA + aoff);
            #pragma unroll
            for (int p = 0; p < 3; ++p) {
                int tok = p * 16 + brl2;
                uint boff = (uint)tok * 256 + (((uint)((h * 4 + 2 * ks + bc8g) ^ (tok & 7))) << 4);
                uint bh[4], bl[4];
                ldsm4(bh, khA + boff);
                ldsm4(bl, klA + boff);
                mma16816(acc[2 * p],     ah, bh[0], bh[1]);
                mma16816(acc[2 * p],     ah, bl[0], bl[1]);
                mma16816(acc[2 * p],     al, bh[0], bh[1]);
                mma16816(acc[2 * p + 1], ah, bh[2], bh[3]);
                mma16816(acc[2 * p + 1], ah, bl[2], bl[3]);
                mma16816(acc[2 * p + 1], al, bh[2], bh[3]);
            }
            {   // single tile nt=6 (tokens 48..55; rows >=49 garbage, discarded per-column)
                int tok = 48 + brl;
                uint boff = (uint)tok * 256 + (((uint)((h * 4 + 2 * ks + bc8g) ^ (tok & 7))) << 4);
                uint bh0, bh1, bl0, bl1;
                ldsm2(bh0, bh1, khA + boff);
                ldsm2(bl0, bl1, klA + boff);
                mma16816(acc[6], ah, bh0, bh1);
                mma16816(acc[6], ah, bl0, bl1);
                mma16816(acc[6], al, bh0, bh1);
            }
        }
        const int g = og >> 2, tig = og & 3;
        const int n0 = mt * 16 + g;
        const float* rpbh = g_rpb + h * 2450;
        #pragma unroll
        for (int nt = 0; nt < 7; ++nt) {
            int m0 = nt * 8 + 2 * tig;
            if (n0 < NTOK && m0 < NTOK) {
                float2 rp = *(const float2*)&rpbh[n0 * 50 + m0];
                ATL[(h * ATN + n0) * ATS + m0] = acc[nt][0] + rp.x + MASKS[n0 * NTOK + m0];
                if (m0 + 1 < NTOK)
                    ATL[(h * ATN + n0) * ATS + m0 + 1] = acc[nt][1] + rp.y + MASKS[n0 * NTOK + m0 + 1];
            }
            if (n0 + 8 < NTOK && m0 < NTOK) {
                float2 rp = *(const float2*)&rpbh[(n0 + 8) * 50 + m0];
                ATL[(h * ATN + n0 + 8) * ATS + m0] = acc[nt][2] + rp.x + MASKS[(n0 + 8) * NTOK + m0];
                if (m0 + 1 < NTOK)
                    ATL[(h * ATN + n0 + 8) * ATS + m0 + 1] = acc[nt][3] + rp.y + MASKS[(n0 + 8) * NTOK + m0 + 1];
            }
        }
    }
    __syncthreads();

    // ---------------- softmax; write P as bf16 hi/lo (cols 49..63 zero) ----------------
    {
        for (int r = wg; r < HEADS * NTOK; r += 16) {
            int h = r / NTOK, n = r % NTOK;
            float* arow = &ATL[(h * ATN + n) * ATS];
            float v0 = arow[og];
            float v1 = (og + 32 < NTOK) ? arow[og + 32] : -1e30f;
            float mx = fmaxf(v0, v1);
            #pragma unroll
            for (int o = 16; o; o >>= 1) mx = fmaxf(mx, __shfl_xor_sync(0xffffffffu, mx, o));
            float e0 = __expf(v0 - mx);
            float e1 = (og + 32 < NTOK) ? __expf(v1 - mx) : 0.f;
            float sm = e0 + e1;
            #pragma unroll
            for (int o = 16; o; o >>= 1) sm += __shfl_xor_sync(0xffffffffu, sm, o);
            float inv = 1.f / sm;
            float p0 = e0 * inv, p1 = e1 * inv;
            {
                __nv_bfloat16 hb = __float2bfloat16(p0);
                ushort hs = *(ushort*)&hb;
                ushort ls = bfbits(p0 - __bfloat162float(hb));
                uint off = (uint)h * 8192 + (uint)n * 128 + (((uint)((og >> 3) ^ (n & 7))) << 4) + ((uint)(og & 7)) * 2;
                *(ushort*)(PHb + off) = hs;
                *(ushort*)(PLb + off) = ls;
            }
            {
                int cc = og + 32;
                __nv_bfloat16 hb = __float2bfloat16(p1);
                ushort hs = *(ushort*)&hb;
                ushort ls = bfbits(p1 - __bfloat162float(hb));
                uint off = (uint)h * 8192 + (uint)n * 128 + (((uint)((cc >> 3) ^ (n & 7))) << 4) + ((uint)(cc & 7)) * 2;
                *(ushort*)(PHb + off) = hs;
                *(ushort*)(PLb + off) = ls;
            }
        }
    }
    __syncthreads();

    // ---------------- P5: O = P @ V via bf16 3-split mma; write O bf16 hi/lo ----------------
    {
        const int h = wg >> 2, mt = wg & 3;
        const int arow = mt * 16 + (og & 15);
        const int ac8  = og >> 4;
        float acc[4][4];
        #pragma unroll
        for (int t = 0; t < 4; ++t)
            #pragma unroll
            for (int j = 0; j < 4; ++j) acc[t][j] = 0.f;

        #pragma unroll
        for (int ks = 0; ks < 4; ++ks) {
            uint aoff = (uint)h * 8192 + (uint)arow * 128 + (((uint)((2 * ks + ac8) ^ (arow & 7))) << 4);
            uint ah[4], al[4];
            ldsm4(ah, phA + aoff);
            ldsm4(al, plA + aoff);
            #pragma unroll
            for (int tp = 0; tp < 2; ++tp) {
                int nr = h * 32 + tp * 16 + brl2;
                uint boff = (uint)nr * 128 + (((uint)((2 * ks + bc8g) ^ (nr & 7))) << 4);
                uint bh[4], bl[4];
                ldsm4(bh, vhA + boff);
                ldsm4(bl, vlA + boff);
                mma16816(acc[2 * tp],     ah, bh[0], bh[1]);
                mma16816(acc[2 * tp],     ah, bl[0], bl[1]);
                mma16816(acc[2 * tp],     al, bh[0], bh[1]);
                mma16816(acc[2 * tp + 1], ah, bh[2], bh[3]);
                mma16816(acc[2 * tp + 1], ah, bl[2], bl[3]);
                mma16816(acc[2 * tp + 1], al, bh[2], bh[3]);
            }
        }
        const int g = og >> 2, tig = og & 3;
        const int n0 = mt * 16 + g;
        #pragma unroll
        for (int nt = 0; nt < 4; ++nt) {
            int col = h * 32 + nt * 8 + 2 * tig;
            #pragma unroll
            for (int half = 0; half < 2; ++half) {
                int n = n0 + 8 * half;
                if (n < NTOK) {
                    float v0 = acc[nt][2 * half], v1 = acc[nt][2 * half + 1];
                    __nv_bfloat16 hb0 = __float2bfloat16(v0), hb1 = __float2bfloat16(v1);
                    ushort hs0 = *(ushort*)&hb0, hs1 = *(ushort*)&hb1;
                    ushort ls0 = bfbits(v0 - __bfloat162float(hb0));
                    ushort ls1 = bfbits(v1 - __bfloat162float(hb1));
                    uint off = (uint)n * 256 + (((uint)((col >> 3) ^ (n & 7))) << 4) + ((uint)(col & 7)) * 2;
                    *(uint*)(OHb + off) = ((uint)hs1 << 16) | hs0;
                    *(uint*)(OLb + off) = ((uint)ls1 << 16) | ls0;
                }
            }
        }
    }
    __syncthreads();

    // ---------------- P6a: stage proj W bf16 hi/lo ----------------
    for (int i = tid; i < 2048; i += THREADS) {
        int row = i >> 4, c8 = i & 15;
        uint4 hv = ((const uint4*)g_wp_hi)[i];
        uint4 lv = ((const uint4*)g_wp_lo)[i];
        uint off = (uint)row * 256 + (((uint)(c8 ^ (row & 7))) << 4);
        *(uint4*)(WHb + off) = hv;
        *(uint4*)(WLb + off) = lv;
    }
    __syncthreads();

    // ---------------- P6b: proj GEMM via bf16 3-split mma.sync ----------------
    {
        const int mw = wg & 3, nwg = wg >> 2;
        const int arow = mw * 16 + (og & 15);
        const int ac8  = og >> 4;
        float acc[4][4];
        #pragma unroll
        for (int t = 0; t < 4; ++t)
            #pragma unroll
            for (int j = 0; j < 4; ++j) acc[t][j] = 0.f;

        #pragma unroll
        for (int ks = 0; ks < 8; ++ks) {
            uint aoff = (uint)arow * 256 + (((uint)((2 * ks + ac8) ^ (arow & 7))) << 4);
            uint ah[4], al[4];
            ldsm4(ah, ohA + aoff);
            ldsm4(al, olA + aoff);
            #pragma unroll
            for (int tp = 0; tp < 2; ++tp) {
                int nr = nwg * 32 + tp * 16 + brl2;
                uint boff = (uint)nr * 256 + (((uint)((2 * ks + bc8g) ^ (nr & 7))) << 4);
                uint bh[4], bl[4];
                ldsm4(bh, whA + boff);
                ldsm4(bl, wlA + boff);
                mma16816(acc[2 * tp],     ah, bh[0], bh[1]);
                mma16816(acc[2 * tp],     ah, bl[0], bl[1]);
                mma16816(acc[2 * tp],     al, bh[0], bh[1]);
                mma16816(acc[2 * tp + 1], ah, bh[2], bh[3]);
                mma16816(acc[2 * tp + 1], ah, bl[2], bl[3]);
                mma16816(acc[2 * tp + 1], al, bh[2], bh[3]);
            }
        }
        float* og_ptr = out + (size_t)b * NTOK * CDIM;
        const int g = og >> 2, c = (og & 3) * 2;
        const int n0 = mw * 16 + g;
        #pragma unroll
        for (int t = 0; t < 4; ++t) {
            int o = nwg * 32 + t * 8 + c;
            float b0 = __ldg(&proj_b[o]), b1 = __ldg(&proj_b[o + 1]);
            if (n0 < NTOK)
                *(float2*)&og_ptr[n0 * CDIM + o] = make_float2(acc[t][0] + b0, acc[t][1] + b1);
            if (n0 + 8 < NTOK)
                *(float2*)&og_ptr[(n0 + 8) * CDIM + o] = make_float2(acc[t][2] + b0, acc[t][3] + b1);
        }
    }
}

extern "C" void kernel_launch(void* const* d_in, const int* in_sizes, int n_in,
                              void* d_out, int out_size)
{
    (void)in_sizes; (void)n_in; (void)out_size;
    const float* x          = (const float*)d_in[0];
    const float* mask       = (const float*)d_in[1];
    const float* qkv_w      = (const float*)d_in[2];
    const float* proj_w     = (const float*)d_in[3];
    const float* proj_b     = (const float*)d_in[4];
    const float* bias_table = (const float*)d_in[5];
    const float* alpha      = (const float*)d_in[6];
    const int*   rel_idx    = (const int*)d_in[7];
    float* out = (float*)d_out;

    int conv_elems = 384 * 128 + 128 * 128 + HEADS * 2401;
    conv_w_kernel<<<(conv_elems + 255) / 256, 256>>>(qkv_w, proj_w, bias_table, rel_idx);

    cudaFuncSetAttribute(lpwin_attn_kernel,
                         cudaFuncAttributeMaxDynamicSharedMemorySize, SMEM_BYTES);
    lpwin_attn_kernel<<<BWIN, THREADS, SMEM_BYTES>>>(
        x, mask, qkv_w, proj_w, proj_b, bias_table, alpha, rel_idx, out);
}

// round 11
// speedup vs baseline: 3.9816x; 1.1717x over previous
#include <cuda_runtime.h>
#include <cuda_bf16.h>
#include <math.h>

// Problem constants
#define BWIN 8192
#define NTOK 49
#define CDIM 128
#define HEADS 4
#define NWIN 4096
#define THREADS 512

// smem byte offsets
#define B_P    0         // P bf16 hi (32KB)  | W-stage hi during P2b/P6a
#define B_PLO  32768     // P bf16 lo         | W-stage lo
#define B_OB   65536     // O bf16 hi (16KB)
#define B_OBLO 81920     // O bf16 lo
#define B_QH   98304     // Q^ bf16 hi (16KB)
#define B_QL   114688    // Q^ bf16 lo
#define B_KH   131072    // K^ bf16 hi
#define B_KL   147456    // K^ bf16 lo
#define B_X    163840    // X bf16 hi (16KB) -> V^T bf16 hi
#define B_XLO  180224    // X bf16 lo -> V^T bf16 lo
#define B_MASK 196608    // mask f32 (2401 floats)
#define SMEM_BYTES 206212

typedef unsigned long long ull;
typedef unsigned int uint;
typedef unsigned short ushort;

__device__ __nv_bfloat16 g_wq_hi[384 * 128];
__device__ __nv_bfloat16 g_wq_lo[384 * 128];
__device__ __nv_bfloat16 g_wp_hi[128 * 128];
__device__ __nv_bfloat16 g_wp_lo[128 * 128];
__device__ float g_rpb[HEADS * 49 * 50];   // [h][n][m], row stride 50

__device__ __forceinline__ uint smem_u32(const void* p){
    uint a; asm("{ .reg .u64 t; cvta.to.shared.u64 t, %1; cvt.u32.u64 %0, t; }" : "=r"(a) : "l"(p));
    return a;
}
__device__ __forceinline__ void ldsm4(uint* r, uint addr){
    asm volatile("ldmatrix.sync.aligned.m8n8.x4.shared.b16 {%0,%1,%2,%3}, [%4];"
        : "=r"(r[0]), "=r"(r[1]), "=r"(r[2]), "=r"(r[3]) : "r"(addr));
}
__device__ __forceinline__ void ldsm2(uint &r0, uint &r1, uint addr){
    asm volatile("ldmatrix.sync.aligned.m8n8.x2.shared.b16 {%0,%1}, [%2];"
        : "=r"(r0), "=r"(r1) : "r"(addr));
}
__device__ __forceinline__ void mma16816(float* d, const uint* a, uint b0, uint b1){
    asm volatile("mma.sync.aligned.m16n8k16.row.col.f32.bf16.bf16.f32 "
        "{%0,%1,%2,%3}, {%4,%5,%6,%7}, {%8,%9}, {%0,%1,%2,%3};"
        : "+f"(d[0]), "+f"(d[1]), "+f"(d[2]), "+f"(d[3])
        : "r"(a[0]), "r"(a[1]), "r"(a[2]), "r"(a[3]), "r"(b0), "r"(b1));
}
__device__ __forceinline__ ushort bfhi(float v, float &rest){
    __nv_bfloat16 h = __float2bfloat16(v);
    rest = v - __bfloat162float(h);
    return *(ushort*)&h;
}
__device__ __forceinline__ ushort bfbits(float v){
    __nv_bfloat16 h = __float2bfloat16(v);
    return *(ushort*)&h;
}

extern __shared__ float smem[];

__global__ void conv_w_kernel(const float* __restrict__ qkv_w,
                              const float* __restrict__ proj_w,
                              const float* __restrict__ bias_table,
                              const int*   __restrict__ rel_idx){
    int i = blockIdx.x * blockDim.x + threadIdx.x;
    if (i < 384 * 128) {
        float v = qkv_w[i];
        __nv_bfloat16 h = __float2bfloat16(v);
        g_wq_hi[i] = h;
        g_wq_lo[i] = __float2bfloat16(v - __bfloat162float(h));
    } else if (i < 384 * 128 + 128 * 128) {
        int j = i - 384 * 128;
        float v = proj_w[j];
        __nv_bfloat16 h = __float2bfloat16(v);
        g_wp_hi[j] = h;
        g_wp_lo[j] = __float2bfloat16(v - __bfloat162float(h));
    } else if (i < 384 * 128 + 128 * 128 + HEADS * 2401) {
        int j = i - (384 * 128 + 128 * 128);
        int h = j / 2401, e = j % 2401;
        int n = e / 49, m = e % 49;
        g_rpb[h * 2450 + n * 50 + m] = bias_table[rel_idx[e] * 4 + h];
    }
}

__global__ void __launch_bounds__(THREADS, 1)
lpwin_attn_kernel(const float* __restrict__ x,
                  const float* __restrict__ mask,
                  const float* __restrict__ qkv_w,
                  const float* __restrict__ proj_w,
                  const float* __restrict__ proj_b,
                  const float* __restrict__ bias_table,
                  const float* __restrict__ alpha,
                  const int*   __restrict__ rel_idx,
                  float* __restrict__ out)
{
    char* SB = (char*)smem;
    float* MASKS = (float*)(SB + B_MASK);

    const int tid = threadIdx.x;
    const int b   = blockIdx.x;
    const int w   = b & (NWIN - 1);
    const int og  = tid & 31;
    const int wg  = tid >> 5;

    const uint base = smem_u32(smem);
    const uint whA = base + B_P,   wlA = base + B_PLO;
    const uint phA = base + B_P,   plA = base + B_PLO;
    const uint ohA = base + B_OB,  olA = base + B_OBLO;
    const uint qhA = base + B_QH,  qlA = base + B_QL;
    const uint khA = base + B_KH,  klA = base + B_KL;
    const uint xhA = base + B_X,   xlA = base + B_XLO;
    const uint vhA = base + B_X,   vlA = base + B_XLO;

    char* WHb = SB + B_P;   char* WLb = SB + B_PLO;
    char* PHb = SB + B_P;   char* PLb = SB + B_PLO;
    char* OHb = SB + B_OB;  char* OLb = SB + B_OBLO;
    char* QHb = SB + B_QH;  char* QLb = SB + B_QL;
    char* KHb = SB + B_KH;  char* KLb = SB + B_KL;
    char* XHb = SB + B_X;   char* XLb = SB + B_XLO;
    char* VHb = SB + B_X;   char* VLb = SB + B_XLO;

    // lane decomposition
    const int brl  = og & 7;
    const int bc8g = (og >> 3) & 1;
    const int brl2 = (og & 7) + ((og & 16) >> 1);
    const int g    = og >> 2, tig = og & 3;

    // ---------------- P1 + P2a: mask; x -> bf16 hi/lo swizzled; stage W rows 0..127 ----------------
    {
        const float* mg = mask + (size_t)w * NTOK * NTOK;
        for (int i = tid; i < NTOK * NTOK; i += THREADS) MASKS[i] = mg[i];

        const float4* xg4 = (const float4*)(x + (size_t)b * NTOK * CDIM);
        for (int i = tid; i < 49 * 16; i += THREADS) {
            int n = i >> 4, c8 = i & 15;
            float4 a = xg4[n * 32 + c8 * 2];
            float4 c = xg4[n * 32 + c8 * 2 + 1];
            float vs[8] = {a.x, a.y, a.z, a.w, c.x, c.y, c.z, c.w};
            ushort hs[8], ls[8];
            #pragma unroll
            for (int j = 0; j < 8; ++j) {
                float rest;
                hs[j] = bfhi(vs[j], rest);
                ls[j] = bfbits(rest);
            }
            uint off = (uint)n * 256 + (((uint)(c8 ^ (n & 7))) << 4);
            *(uint4*)(XHb + off) = *(uint4*)hs;
            *(uint4*)(XLb + off) = *(uint4*)ls;
        }
        uint4 z = make_uint4(0, 0, 0, 0);
        for (int i = tid; i < 15 * 16; i += THREADS) {
            int n = 49 + (i >> 4), c8 = i & 15;
            uint off = (uint)n * 256 + (((uint)(c8 ^ (n & 7))) << 4);
            *(uint4*)(XHb + off) = z;
            *(uint4*)(XLb + off) = z;
        }
        for (int i = tid; i < 2048; i += THREADS) {
            int row = i >> 4, c8 = i & 15;
            uint4 hv = ((const uint4*)g_wq_hi)[i];
            uint4 lv = ((const uint4*)g_wq_lo)[i];
            uint off = (uint)row * 256 + (((uint)(c8 ^ (row & 7))) << 4);
            *(uint4*)(WHb + off) = hv;
            *(uint4*)(WLb + off) = lv;
        }
    }
    __syncthreads();

    // ---------------- P2b: QKV GEMM (bf16 3-split), fused epilogues per pass ----------------
    {
        const int mw = wg & 3, nwg = wg >> 2;
        const int arow = mw * 16 + (og & 15);
        const int ac8  = og >> 4;
        const int n0 = mw * 16 + g;

        for (int pass = 0; pass < 3; ++pass) {
            float acc[4][4];
            #pragma unroll
            for (int t = 0; t < 4; ++t)
                #pragma unroll
                for (int j = 0; j < 4; ++j) acc[t][j] = 0.f;

            #pragma unroll
            for (int ks = 0; ks < 8; ++ks) {
                uint aoff = (uint)arow * 256 + (((uint)((2 * ks + ac8) ^ (arow & 7))) << 4);
                uint ah[4], al[4];
                ldsm4(ah, xhA + aoff);
                ldsm4(al, xlA + aoff);
                #pragma unroll
                for (int tp = 0; tp < 2; ++tp) {
                    int nr = nwg * 32 + tp * 16 + brl2;
                    uint boff = (uint)nr * 256 + (((uint)((2 * ks + bc8g) ^ (nr & 7))) << 4);
                    uint bh[4], bl[4];
                    ldsm4(bh, whA + boff);
                    ldsm4(bl, wlA + boff);
                    mma16816(acc[2 * tp],     ah, bh[0], bh[1]);
                    mma16816(acc[2 * tp],     ah, bl[0], bl[1]);
                    mma16816(acc[2 * tp],     al, bh[0], bh[1]);
                    mma16816(acc[2 * tp + 1], ah, bh[2], bh[3]);
                    mma16816(acc[2 * tp + 1], ah, bl[2], bl[3]);
                    mma16816(acc[2 * tp + 1], al, bh[2], bh[3]);
                }
            }
            __syncthreads();   // all warps done reading WST (and X for pass 2)

            if (pass < 2) {
                // stage next W tile into WST
                for (int i = tid; i < 2048; i += THREADS) {
                    int row = i >> 4, c8 = i & 15;
                    uint4 hv = ((const uint4*)g_wq_hi)[(pass + 1) * 2048 + i];
                    uint4 lv = ((const uint4*)g_wq_lo)[(pass + 1) * 2048 + i];
                    uint off = (uint)row * 256 + (((uint)(c8 ^ (row & 7))) << 4);
                    *(uint4*)(WHb + off) = hv;
                    *(uint4*)(WLb + off) = lv;
                }
                // fused epilogue: L2-normalize rows of this head (quad owns full head-row)
                float ss0 = 0.f, ss1 = 0.f;
                #pragma unroll
                for (int t = 0; t < 4; ++t) {
                    ss0 += acc[t][0] * acc[t][0] + acc[t][1] * acc[t][1];
                    ss1 += acc[t][2] * acc[t][2] + acc[t][3] * acc[t][3];
                }
                ss0 += __shfl_xor_sync(0xffffffffu, ss0, 1);
                ss0 += __shfl_xor_sync(0xffffffffu, ss0, 2);
                ss1 += __shfl_xor_sync(0xffffffffu, ss1, 1);
                ss1 += __shfl_xor_sync(0xffffffffu, ss1, 2);
                float sc = (pass == 0) ? __ldg(&alpha[nwg]) : 1.f;
                float inv0 = sc / (sqrtf(ss0) + 1e-6f);
                float inv1 = sc / (sqrtf(ss1) + 1e-6f);
                char* Hb = (pass == 0) ? QHb : KHb;
                char* Lb = (pass == 0) ? QLb : KLb;
                #pragma unroll
                for (int t = 0; t < 4; ++t) {
                    int col = nwg * 32 + t * 8 + 2 * tig;
                    int c8 = col >> 3;
                    float r0, r1;
                    ushort h0 = bfhi(acc[t][0] * inv0, r0);
                    ushort h1 = bfhi(acc[t][1] * inv0, r1);
                    uint off0 = (uint)n0 * 256 + (((uint)(c8 ^ (n0 & 7))) << 4) + ((uint)(col & 7)) * 2;
                    *(uint*)(Hb + off0) = ((uint)h1 << 16) | h0;
                    *(uint*)(Lb + off0) = ((uint)bfbits(r1) << 16) | bfbits(r0);
                    int n1 = n0 + 8;
                    ushort h2 = bfhi(acc[t][2] * inv1, r0);
                    ushort h3 = bfhi(acc[t][3] * inv1, r1);
                    uint off1 = (uint)n1 * 256 + (((uint)(c8 ^ (n1 & 7))) << 4) + ((uint)(col & 7)) * 2;
                    *(uint*)(Hb + off1) = ((uint)h3 << 16) | h2;
                    *(uint*)(Lb + off1) = ((uint)bfbits(r1) << 16) | bfbits(r0);
                }
            } else {
                // fused epilogue: V^T bf16 (rows = channel, cols = token; pad tokens are exact zeros)
                #pragma unroll
                for (int t = 0; t < 4; ++t) {
                    #pragma unroll
                    for (int j = 0; j < 2; ++j) {
                        int c = nwg * 32 + t * 8 + 2 * tig + j;
                        #pragma unroll
                        for (int half = 0; half < 2; ++half) {
                            int m = n0 + 8 * half;
                            float v = acc[t][2 * half + j];
                            float rest;
                            ushort hv = bfhi(v, rest);
                            uint off = (uint)c * 128 + (((uint)((m >> 3) ^ (c & 7))) << 4) + ((uint)(m & 7)) * 2;
                            *(ushort*)(VHb + off) = hv;
                            *(ushort*)(VLb + off) = bfbits(rest);
                        }
                    }
                }
            }
            __syncthreads();
        }
    }

    // ---------------- P4 + softmax (registers) -> P bf16 hi/lo ----------------
    {
        const int h = wg >> 2, mt = wg & 3;
        const int arow = mt * 16 + (og & 15);
        const int ac8  = og >> 4;
        float acc[7][4];
        #pragma unroll
        for (int t = 0; t < 7; ++t)
            #pragma unroll
            for (int j = 0; j < 4; ++j) acc[t][j] = 0.f;

        #pragma unroll
        for (int ks = 0; ks < 2; ++ks) {
            uint aoff = (uint)arow * 256 + (((uint)((h * 4 + 2 * ks + ac8) ^ (arow & 7))) << 4);
            uint ah[4], al[4];
            ldsm4(ah, qhA + aoff);
            ldsm4(al, qlA + aoff);
            #pragma unroll
            for (int p = 0; p < 3; ++p) {
                int tok = p * 16 + brl2;
                uint boff = (uint)tok * 256 + (((uint)((h * 4 + 2 * ks + bc8g) ^ (tok & 7))) << 4);
                uint bh[4], bl[4];
                ldsm4(bh, khA + boff);
                ldsm4(bl, klA + boff);
                mma16816(acc[2 * p],     ah, bh[0], bh[1]);
                mma16816(acc[2 * p],     ah, bl[0], bl[1]);
                mma16816(acc[2 * p],     al, bh[0], bh[1]);
                mma16816(acc[2 * p + 1], ah, bh[2], bh[3]);
                mma16816(acc[2 * p + 1], ah, bl[2], bl[3]);
                mma16816(acc[2 * p + 1], al, bh[2], bh[3]);
            }
            {
                int tok = 48 + brl;   // K rows 49..55 are exact zeros now
                uint boff = (uint)tok * 256 + (((uint)((h * 4 + 2 * ks + bc8g) ^ (tok & 7))) << 4);
                uint bh0, bh1, bl0, bl1;
                ldsm2(bh0, bh1, khA + boff);
                ldsm2(bl0, bl1, klA + boff);
                mma16816(acc[6], ah, bh0, bh1);
                mma16816(acc[6], ah, bl0, bl1);
                mma16816(acc[6], al, bh0, bh1);
            }
        }

        const float* rpbh = g_rpb + h * 2450;
        #pragma unroll
        for (int half = 0; half < 2; ++half) {
            int r = mt * 16 + g + 8 * half;
            int nr = (r < NTOK) ? r : 0;    // clamped for safe reads (pad rows discarded later)
            float pv[14];
            float mx = -1e30f;
            #pragma unroll
            for (int nt = 0; nt < 7; ++nt) {
                int m0 = nt * 8 + 2 * tig;
                float v0 = acc[nt][2 * half], v1 = acc[nt][2 * half + 1];
                if (m0 < NTOK) {
                    float2 rp = *(const float2*)&rpbh[nr * 50 + m0];
                    v0 += rp.x + MASKS[nr * 49 + m0];
                    v1 = (m0 + 1 < NTOK) ? (v1 + rp.y + MASKS[nr * 49 + m0 + 1]) : -1e30f;
                } else { v0 = -1e30f; v1 = -1e30f; }
                pv[2 * nt] = v0; pv[2 * nt + 1] = v1;
                mx = fmaxf(mx, fmaxf(v0, v1));
            }
            mx = fmaxf(mx, __shfl_xor_sync(0xffffffffu, mx, 1));
            mx = fmaxf(mx, __shfl_xor_sync(0xffffffffu, mx, 2));
            float sm = 0.f;
            #pragma unroll
            for (int i = 0; i < 14; ++i) { pv[i] = __expf(pv[i] - mx); sm += pv[i]; }
            sm += __shfl_xor_sync(0xffffffffu, sm, 1);
            sm += __shfl_xor_sync(0xffffffffu, sm, 2);
            float inv = 1.f / sm;
            #pragma unroll
            for (int nt = 0; nt < 7; ++nt) {
                int m0 = nt * 8 + 2 * tig;
                float p0 = pv[2 * nt] * inv, p1 = pv[2 * nt + 1] * inv;
                float r0, r1;
                ushort h0 = bfhi(p0, r0);
                ushort h1 = bfhi(p1, r1);
                int c8m = m0 >> 3;
                uint off = (uint)h * 8192 + (uint)r * 128 + (((uint)(c8m ^ (r & 7))) << 4) + ((uint)(m0 & 7)) * 2;
                *(uint*)(PHb + off) = ((uint)h1 << 16) | h0;
                *(uint*)(PLb + off) = ((uint)bfbits(r1) << 16) | bfbits(r0);
            }
            {   // zero pad cols 56..63
                int m0 = 56 + 2 * tig;
                uint off = (uint)h * 8192 + (uint)r * 128 + (((uint)(7 ^ (r & 7))) << 4) + ((uint)(m0 & 7)) * 2;
                *(uint*)(PHb + off) = 0u;
                *(uint*)(PLb + off) = 0u;
            }
        }
    }
    __syncwarp();   // P rows are warp-local; warp-level visibility suffices

    // ---------------- P5: O = P @ V (bf16 3-split) -> O bf16 hi/lo ----------------
    {
        const int h = wg >> 2, mt = wg & 3;
        const int arow = mt * 16 + (og & 15);
        const int ac8  = og >> 4;
        float acc[4][4];
        #pragma unroll
        for (int t = 0; t < 4; ++t)
            #pragma unroll
            for (int j = 0; j < 4; ++j) acc[t][j] = 0.f;

        #pragma unroll
        for (int ks = 0; ks < 4; ++ks) {
            uint aoff = (uint)h * 8192 + (uint)arow * 128 + (((uint)((2 * ks + ac8) ^ (arow & 7))) << 4);
            uint ah[4], al[4];
            ldsm4(ah, phA + aoff);
            ldsm4(al, plA + aoff);
            #pragma unroll
            for (int tp = 0; tp < 2; ++tp) {
                int nr = h * 32 + tp * 16 + brl2;
                uint boff = (uint)nr * 128 + (((uint)((2 * ks + bc8g) ^ (nr & 7))) << 4);
                uint bh[4], bl[4];
                ldsm4(bh, vhA + boff);
                ldsm4(bl, vlA + boff);
                mma16816(acc[2 * tp],     ah, bh[0], bh[1]);
                mma16816(acc[2 * tp],     ah, bl[0], bl[1]);
                mma16816(acc[2 * tp],     al, bh[0], bh[1]);
                mma16816(acc[2 * tp + 1], ah, bh[2], bh[3]);
                mma16816(acc[2 * tp + 1], ah, bl[2], bl[3]);
                mma16816(acc[2 * tp + 1], al, bh[2], bh[3]);
            }
        }
        const int n0 = mt * 16 + g;
        #pragma unroll
        for (int nt = 0; nt < 4; ++nt) {
            int col = h * 32 + nt * 8 + 2 * tig;
            #pragma unroll
            for (int half = 0; half < 2; ++half) {
                int n = n0 + 8 * half;
                if (n < NTOK) {
                    float v0 = acc[nt][2 * half], v1 = acc[nt][2 * half + 1];
                    float r0, r1;
                    ushort h0 = bfhi(v0, r0);
                    ushort h1 = bfhi(v1, r1);
                    uint off = (uint)n * 256 + (((uint)((col >> 3) ^ (n & 7))) << 4) + ((uint)(col & 7)) * 2;
                    *(uint*)(OHb + off) = ((uint)h1 << 16) | h0;
                    *(uint*)(OLb + off) = ((uint)bfbits(r1) << 16) | bfbits(r0);
                }
            }
        }
    }
    __syncthreads();

    // ---------------- P6a: stage proj W bf16 hi/lo (into WST = P region, now dead) ----------------
    for (int i = tid; i < 2048; i += THREADS) {
        int row = i >> 4, c8 = i & 15;
        uint4 hv = ((const uint4*)g_wp_hi)[i];
        uint4 lv = ((const uint4*)g_wp_lo)[i];
        uint off = (uint)row * 256 + (((uint)(c8 ^ (row & 7))) << 4);
        *(uint4*)(WHb + off) = hv;
        *(uint4*)(WLb + off) = lv;
    }
    __syncthreads();

    // ---------------- P6b: proj GEMM via bf16 3-split mma.sync ----------------
    {
        const int mw = wg & 3, nwg = wg >> 2;
        const int arow = mw * 16 + (og & 15);
        const int ac8  = og >> 4;
        float acc[4][4];
        #pragma unroll
        for (int t = 0; t < 4; ++t)
            #pragma unroll
            for (int j = 0; j < 4; ++j) acc[t][j] = 0.f;

        #pragma unroll
        for (int ks = 0; ks < 8; ++ks) {
            uint aoff = (uint)arow * 256 + (((uint)((2 * ks + ac8) ^ (arow & 7))) << 4);
            uint ah[4], al[4];
            ldsm4(ah, ohA + aoff);
            ldsm4(al, olA + aoff);
            #pragma unroll
            for (int tp = 0; tp < 2; ++tp) {
                int nr = nwg * 32 + tp * 16 + brl2;
                uint boff = (uint)nr * 256 + (((uint)((2 * ks + bc8g) ^ (nr & 7))) << 4);
                uint bh[4], bl[4];
                ldsm4(bh, whA + boff);
                ldsm4(bl, wlA + boff);
                mma16816(acc[2 * tp],     ah, bh[0], bh[1]);
                mma16816(acc[2 * tp],     ah, bl[0], bl[1]);
                mma16816(acc[2 * tp],     al, bh[0], bh[1]);
                mma16816(acc[2 * tp + 1], ah, bh[2], bh[3]);
                mma16816(acc[2 * tp + 1], ah, bl[2], bl[3]);
                mma16816(acc[2 * tp + 1], al, bh[2], bh[3]);
            }
        }
        float* og_ptr = out + (size_t)b * NTOK * CDIM;
        const int c = tig * 2;
        const int n0 = mw * 16 + g;
        #pragma unroll
        for (int t = 0; t < 4; ++t) {
            int o = nwg * 32 + t * 8 + c;
            float b0 = __ldg(&proj_b[o]), b1 = __ldg(&proj_b[o + 1]);
            if (n0 < NTOK)
                *(float2*)&og_ptr[n0 * CDIM + o] = make_float2(acc[t][0] + b0, acc[t][1] + b1);
            if (n0 + 8 < NTOK)
                *(float2*)&og_ptr[(n0 + 8) * CDIM + o] = make_float2(acc[t][2] + b0, acc[t][3] + b1);
        }
    }
}

extern "C" void kernel_launch(void* const* d_in, const int* in_sizes, int n_in,
                              void* d_out, int out_size)
{
    (void)in_sizes; (void)n_in; (void)out_size;
    const float* x          = (const float*)d_in[0];
    const float* mask       = (const float*)d_in[1];
    const float* qkv_w      = (const float*)d_in[2];
    const float* proj_w     = (const float*)d_in[3];
    const float* proj_b     = (const float*)d_in[4];
    const float* bias_table = (const float*)d_in[5];
    const float* alpha      = (const float*)d_in[6];
    const int*   rel_idx    = (const int*)d_in[7];
    float* out = (float*)d_out;

    int conv_elems = 384 * 128 + 128 * 128 + HEADS * 2401;
    conv_w_kernel<<<(conv_elems + 255) / 256, 256>>>(qkv_w, proj_w, bias_table, rel_idx);

    cudaFuncSetAttribute(lpwin_attn_kernel,
                         cudaFuncAttributeMaxDynamicSharedMemorySize, SMEM_BYTES);
    lpwin_attn_kernel<<<BWIN, THREADS, SMEM_BYTES>>>(
        x, mask, qkv_w, proj_w, proj_b, bias_table, alpha, rel_idx, out);
}

// round 12
// speedup vs baseline: 4.5082x; 1.1323x over previous
#include <cuda_runtime.h>
#include <cuda_bf16.h>
#include <math.h>

// Problem constants
#define BWIN 8192
#define NTOK 49
#define CDIM 128
#define HEADS 4
#define NWIN 4096
#define THREADS 512

// smem byte offsets
#define B_P    0         // P bf16 hi (32KB)
#define B_PLO  32768     // P bf16 lo
#define B_OB   65536     // O bf16 hi (16KB)
#define B_OBLO 81920     // O bf16 lo
#define B_QH   98304     // Q^ bf16 hi (16KB)
#define B_QL   114688    // Q^ bf16 lo
#define B_KH   131072    // K^ bf16 hi
#define B_KL   147456    // K^ bf16 lo
#define B_X    163840    // X bf16 hi (16KB) -> V^T bf16 hi
#define B_XLO  180224    // X bf16 lo -> V^T bf16 lo
#define B_MASK 196608    // mask f32 (2401 floats)
#define SMEM_BYTES 206212

#define QKV_T16  24      // n16 tiles in qkv W (384/16)
#define PROJ_T16 8       // n16 tiles in proj W
#define NFRAG_Q  (QKV_T16 * 8 * 32)    // 6144 uint4
#define NFRAG_P  (PROJ_T16 * 8 * 32)   // 2048 uint4

typedef unsigned long long ull;
typedef unsigned int uint;
typedef unsigned short ushort;

__device__ uint4 g_wqf_hi[NFRAG_Q];
__device__ uint4 g_wqf_lo[NFRAG_Q];
__device__ uint4 g_wpf_hi[NFRAG_P];
__device__ uint4 g_wpf_lo[NFRAG_P];
__device__ float g_rpb[HEADS * 49 * 50];   // [h][n][m], row stride 50

__device__ __forceinline__ uint smem_u32(const void* p){
    uint a; asm("{ .reg .u64 t; cvta.to.shared.u64 t, %1; cvt.u32.u64 %0, t; }" : "=r"(a) : "l"(p));
    return a;
}
__device__ __forceinline__ void ldsm4(uint* r, uint addr){
    asm volatile("ldmatrix.sync.aligned.m8n8.x4.shared.b16 {%0,%1,%2,%3}, [%4];"
        : "=r"(r[0]), "=r"(r[1]), "=r"(r[2]), "=r"(r[3]) : "r"(addr));
}
__device__ __forceinline__ void ldsm2(uint &r0, uint &r1, uint addr){
    asm volatile("ldmatrix.sync.aligned.m8n8.x2.shared.b16 {%0,%1}, [%2];"
        : "=r"(r0), "=r"(r1) : "r"(addr));
}
__device__ __forceinline__ void mma16816(float* d, const uint* a, uint b0, uint b1){
    asm volatile("mma.sync.aligned.m16n8k16.row.col.f32.bf16.bf16.f32 "
        "{%0,%1,%2,%3}, {%4,%5,%6,%7}, {%8,%9}, {%0,%1,%2,%3};"
        : "+f"(d[0]), "+f"(d[1]), "+f"(d[2]), "+f"(d[3])
        : "r"(a[0]), "r"(a[1]), "r"(a[2]), "r"(a[3]), "r"(b0), "r"(b1));
}
__device__ __forceinline__ ushort bfhi(float v, float &rest){
    __nv_bfloat16 h = __float2bfloat16(v);
    rest = v - __bfloat162float(h);
    return *(ushort*)&h;
}
__device__ __forceinline__ ushort bfbits(float v){
    __nv_bfloat16 h = __float2bfloat16(v);
    return *(ushort*)&h;
}
__device__ __forceinline__ uint packbf(float a, float b, uint &lo){
    float ra, rb;
    ushort ha = bfhi(a, ra), hb = bfhi(b, rb);
    lo = ((uint)bfbits(rb) << 16) | bfbits(ra);
    return ((uint)hb << 16) | ha;
}

extern __shared__ float smem[];

__global__ void conv_w_kernel(const float* __restrict__ qkv_w,
                              const float* __restrict__ proj_w,
                              const float* __restrict__ bias_table,
                              const int*   __restrict__ rel_idx){
    int i = blockIdx.x * blockDim.x + threadIdx.x;
    if (i < NFRAG_Q + NFRAG_P) {
        bool isq = (i < NFRAG_Q);
        int idx = isq ? i : i - NFRAG_Q;
        const float* W = isq ? qkv_w : proj_w;
        int tile = idx >> 8;
        int ks   = (idx >> 5) & 7;
        int lane = idx & 31;
        int r0 = tile * 16 + (lane >> 2);
        int r1 = r0 + 8;
        int c0 = ks * 16 + 2 * (lane & 3);
        uint4 hv, lv;
        hv.x = packbf(W[r0 * 128 + c0],     W[r0 * 128 + c0 + 1], lv.x);
        hv.y = packbf(W[r0 * 128 + c0 + 8], W[r0 * 128 + c0 + 9], lv.y);
        hv.z = packbf(W[r1 * 128 + c0],     W[r1 * 128 + c0 + 1], lv.z);
        hv.w = packbf(W[r1 * 128 + c0 + 8], W[r1 * 128 + c0 + 9], lv.w);
        if (isq) { g_wqf_hi[idx] = hv; g_wqf_lo[idx] = lv; }
        else     { g_wpf_hi[idx] = hv; g_wpf_lo[idx] = lv; }
    } else if (i < NFRAG_Q + NFRAG_P + HEADS * 2401) {
        int j = i - (NFRAG_Q + NFRAG_P);
        int h = j / 2401, e = j % 2401;
        int n = e / 49, m = e % 49;
        g_rpb[h * 2450 + n * 50 + m] = bias_table[rel_idx[e] * 4 + h];
    }
}

__global__ void __launch_bounds__(THREADS, 1)
lpwin_attn_kernel(const float* __restrict__ x,
                  const float* __restrict__ mask,
                  const float* __restrict__ qkv_w,
                  const float* __restrict__ proj_w,
                  const float* __restrict__ proj_b,
                  const float* __restrict__ bias_table,
                  const float* __restrict__ alpha,
                  const int*   __restrict__ rel_idx,
                  float* __restrict__ out)
{
    char* SB = (char*)smem;
    float* MASKS = (float*)(SB + B_MASK);

    const int tid = threadIdx.x;
    const int b   = blockIdx.x;
    const int w   = b & (NWIN - 1);
    const int og  = tid & 31;
    const int wg  = tid >> 5;

    const uint base = smem_u32(smem);
    const uint phA = base + B_P,   plA = base + B_PLO;
    const uint ohA = base + B_OB,  olA = base + B_OBLO;
    const uint qhA = base + B_QH,  qlA = base + B_QL;
    const uint khA = base + B_KH,  klA = base + B_KL;
    const uint xhA = base + B_X,   xlA = base + B_XLO;
    const uint vhA = base + B_X,   vlA = base + B_XLO;

    char* PHb = SB + B_P;   char* PLb = SB + B_PLO;
    char* OHb = SB + B_OB;  char* OLb = SB + B_OBLO;
    char* QHb = SB + B_QH;  char* QLb = SB + B_QL;
    char* KHb = SB + B_KH;  char* KLb = SB + B_KL;
    char* XHb = SB + B_X;   char* XLb = SB + B_XLO;
    char* VHb = SB + B_X;   char* VLb = SB + B_XLO;

    // lane decomposition
    const int brl  = og & 7;
    const int bc8g = (og >> 3) & 1;
    const int brl2 = (og & 7) + ((og & 16) >> 1);
    const int g    = og >> 2, tig = og & 3;

    // ---------------- P1 + P2a: mask; x -> bf16 hi/lo swizzled ----------------
    {
        const float* mg = mask + (size_t)w * NTOK * NTOK;
        for (int i = tid; i < NTOK * NTOK; i += THREADS) MASKS[i] = mg[i];

        const float4* xg4 = (const float4*)(x + (size_t)b * NTOK * CDIM);
        for (int i = tid; i < 49 * 16; i += THREADS) {
            int n = i >> 4, c8 = i & 15;
            float4 a = xg4[n * 32 + c8 * 2];
            float4 c = xg4[n * 32 + c8 * 2 + 1];
            float vs[8] = {a.x, a.y, a.z, a.w, c.x, c.y, c.z, c.w};
            ushort hs[8], ls[8];
            #pragma unroll
            for (int j = 0; j < 8; ++j) {
                float rest;
                hs[j] = bfhi(vs[j], rest);
                ls[j] = bfbits(rest);
            }
            uint off = (uint)n * 256 + (((uint)(c8 ^ (n & 7))) << 4);
            *(uint4*)(XHb + off) = *(uint4*)hs;
            *(uint4*)(XLb + off) = *(uint4*)ls;
        }
        uint4 z = make_uint4(0, 0, 0, 0);
        for (int i = tid; i < 15 * 16; i += THREADS) {
            int n = 49 + (i >> 4), c8 = i & 15;
            uint off = (uint)n * 256 + (((uint)(c8 ^ (n & 7))) << 4);
            *(uint4*)(XHb + off) = z;
            *(uint4*)(XLb + off) = z;
        }
    }
    __syncthreads();

    // ---------------- P2b: QKV GEMM (bf16 3-split), W fragments straight from L2 ----------------
    {
        const int mw = wg & 3, nwg = wg >> 2;
        const int arow = mw * 16 + (og & 15);
        const int ac8  = og >> 4;
        const int n0 = mw * 16 + g;
        float accV[4][4];    // pass-2 accumulators survive the barrier

        for (int pass = 0; pass < 3; ++pass) {
            float acc[4][4];
            #pragma unroll
            for (int t = 0; t < 4; ++t)
                #pragma unroll
                for (int j = 0; j < 4; ++j) acc[t][j] = 0.f;

            const uint4* fH = g_wqf_hi + ((pass * 8 + nwg * 2) * 8) * 32 + og;
            const uint4* fL = g_wqf_lo + ((pass * 8 + nwg * 2) * 8) * 32 + og;

            #pragma unroll
            for (int ks = 0; ks < 8; ++ks) {
                uint aoff = (uint)arow * 256 + (((uint)((2 * ks + ac8) ^ (arow & 7))) << 4);
                uint ah[4], al[4];
                ldsm4(ah, xhA + aoff);
                ldsm4(al, xlA + aoff);
                #pragma unroll
                for (int tp = 0; tp < 2; ++tp) {
                    uint4 bh = __ldg(fH + (tp * 8 + ks) * 32);
                    uint4 bl = __ldg(fL + (tp * 8 + ks) * 32);
                    mma16816(acc[2 * tp],     ah, bh.x, bh.y);
                    mma16816(acc[2 * tp],     ah, bl.x, bl.y);
                    mma16816(acc[2 * tp],     al, bh.x, bh.y);
                    mma16816(acc[2 * tp + 1], ah, bh.z, bh.w);
                    mma16816(acc[2 * tp + 1], ah, bl.z, bl.w);
                    mma16816(acc[2 * tp + 1], al, bh.z, bh.w);
                }
            }

            if (pass < 2) {
                // fused epilogue: L2-normalize rows of this head (quad owns full head-row)
                float ss0 = 0.f, ss1 = 0.f;
                #pragma unroll
                for (int t = 0; t < 4; ++t) {
                    ss0 += acc[t][0] * acc[t][0] + acc[t][1] * acc[t][1];
                    ss1 += acc[t][2] * acc[t][2] + acc[t][3] * acc[t][3];
                }
                ss0 += __shfl_xor_sync(0xffffffffu, ss0, 1);
                ss0 += __shfl_xor_sync(0xffffffffu, ss0, 2);
                ss1 += __shfl_xor_sync(0xffffffffu, ss1, 1);
                ss1 += __shfl_xor_sync(0xffffffffu, ss1, 2);
                float sc = (pass == 0) ? __ldg(&alpha[nwg]) : 1.f;
                float inv0 = sc / (sqrtf(ss0) + 1e-6f);
                float inv1 = sc / (sqrtf(ss1) + 1e-6f);
                char* Hb = (pass == 0) ? QHb : KHb;
                char* Lb = (pass == 0) ? QLb : KLb;
                #pragma unroll
                for (int t = 0; t < 4; ++t) {
                    int col = nwg * 32 + t * 8 + 2 * tig;
                    int c8 = col >> 3;
                    uint lo0, lo1;
                    uint h0 = packbf(acc[t][0] * inv0, acc[t][1] * inv0, lo0);
                    uint off0 = (uint)n0 * 256 + (((uint)(c8 ^ (n0 & 7))) << 4) + ((uint)(col & 7)) * 2;
                    *(uint*)(Hb + off0) = h0;
                    *(uint*)(Lb + off0) = lo0;
                    int n1 = n0 + 8;
                    uint h1 = packbf(acc[t][2] * inv1, acc[t][3] * inv1, lo1);
                    uint off1 = (uint)n1 * 256 + (((uint)(c8 ^ (n1 & 7))) << 4) + ((uint)(col & 7)) * 2;
                    *(uint*)(Hb + off1) = h1;
                    *(uint*)(Lb + off1) = lo1;
                }
            } else {
                #pragma unroll
                for (int t = 0; t < 4; ++t)
                    #pragma unroll
                    for (int j = 0; j < 4; ++j) accV[t][j] = acc[t][j];
            }
        }
        __syncthreads();   // all warps done reading X before V^T overwrite

        // fused epilogue: V^T bf16 (rows = channel, cols = token; pad tokens exact zeros)
        const int nwg2 = wg >> 2;
        #pragma unroll
        for (int t = 0; t < 4; ++t) {
            #pragma unroll
            for (int j = 0; j < 2; ++j) {
                int c = nwg2 * 32 + t * 8 + 2 * tig + j;
                #pragma unroll
                for (int half = 0; half < 2; ++half) {
                    int m = n0 + 8 * half;
                    float v = accV[t][2 * half + j];
                    float rest;
                    ushort hv = bfhi(v, rest);
                    uint off = (uint)c * 128 + (((uint)((m >> 3) ^ (c & 7))) << 4) + ((uint)(m & 7)) * 2;
                    *(ushort*)(VHb + off) = hv;
                    *(ushort*)(VLb + off) = bfbits(rest);
                }
            }
        }
    }
    __syncthreads();

    // ---------------- P4 + softmax (registers) -> P bf16 hi/lo ----------------
    {
        const int h = wg >> 2, mt = wg & 3;
        const int arow = mt * 16 + (og & 15);
        const int ac8  = og >> 4;
        float acc[7][4];
        #pragma unroll
        for (int t = 0; t < 7; ++t)
            #pragma unroll
            for (int j = 0; j < 4; ++j) acc[t][j] = 0.f;

        #pragma unroll
        for (int ks = 0; ks < 2; ++ks) {
            uint aoff = (uint)arow * 256 + (((uint)((h * 4 + 2 * ks + ac8) ^ (arow & 7))) << 4);
            uint ah[4], al[4];
            ldsm4(ah, qhA + aoff);
            ldsm4(al, qlA + aoff);
            #pragma unroll
            for (int p = 0; p < 3; ++p) {
                int tok = p * 16 + brl2;
                uint boff = (uint)tok * 256 + (((uint)((h * 4 + 2 * ks + bc8g) ^ (tok & 7))) << 4);
                uint bh[4], bl[4];
                ldsm4(bh, khA + boff);
                ldsm4(bl, klA + boff);
                mma16816(acc[2 * p],     ah, bh[0], bh[1]);
                mma16816(acc[2 * p],     ah, bl[0], bl[1]);
                mma16816(acc[2 * p],     al, bh[0], bh[1]);
                mma16816(acc[2 * p + 1], ah, bh[2], bh[3]);
                mma16816(acc[2 * p + 1], ah, bl[2], bl[3]);
                mma16816(acc[2 * p + 1], al, bh[2], bh[3]);
            }
            {
                int tok = 48 + brl;   // K rows 49..55 are exact zeros
                uint boff = (uint)tok * 256 + (((uint)((h * 4 + 2 * ks + bc8g) ^ (tok & 7))) << 4);
                uint bh0, bh1, bl0, bl1;
                ldsm2(bh0, bh1, khA + boff);
                ldsm2(bl0, bl1, klA + boff);
                mma16816(acc[6], ah, bh0, bh1);
                mma16816(acc[6], ah, bl0, bl1);
                mma16816(acc[6], al, bh0, bh1);
            }
        }

        const float* rpbh = g_rpb + h * 2450;
        #pragma unroll
        for (int half = 0; half < 2; ++half) {
            int r = mt * 16 + g + 8 * half;
            int nr = (r < NTOK) ? r : 0;
            float pv[14];
            float mx = -1e30f;
            #pragma unroll
            for (int nt = 0; nt < 7; ++nt) {
                int m0 = nt * 8 + 2 * tig;
                float v0 = acc[nt][2 * half], v1 = acc[nt][2 * half + 1];
                if (m0 < NTOK) {
                    float2 rp = *(const float2*)&rpbh[nr * 50 + m0];
                    v0 += rp.x + MASKS[nr * 49 + m0];
                    v1 = (m0 + 1 < NTOK) ? (v1 + rp.y + MASKS[nr * 49 + m0 + 1]) : -1e30f;
                } else { v0 = -1e30f; v1 = -1e30f; }
                pv[2 * nt] = v0; pv[2 * nt + 1] = v1;
                mx = fmaxf(mx, fmaxf(v0, v1));
            }
            mx = fmaxf(mx, __shfl_xor_sync(0xffffffffu, mx, 1));
            mx = fmaxf(mx, __shfl_xor_sync(0xffffffffu, mx, 2));
            float sm = 0.f;
            #pragma unroll
            for (int i = 0; i < 14; ++i) { pv[i] = __expf(pv[i] - mx); sm += pv[i]; }
            sm += __shfl_xor_sync(0xffffffffu, sm, 1);
            sm += __shfl_xor_sync(0xffffffffu, sm, 2);
            float inv = 1.f / sm;
            #pragma unroll
            for (int nt = 0; nt < 7; ++nt) {
                int m0 = nt * 8 + 2 * tig;
                uint lo;
                uint hi = packbf(pv[2 * nt] * inv, pv[2 * nt + 1] * inv, lo);
                int c8m = m0 >> 3;
                uint off = (uint)h * 8192 + (uint)r * 128 + (((uint)(c8m ^ (r & 7))) << 4) + ((uint)(m0 & 7)) * 2;
                *(uint*)(PHb + off) = hi;
                *(uint*)(PLb + off) = lo;
            }
            {   // zero pad cols 56..63
                int m0 = 56 + 2 * tig;
                uint off = (uint)h * 8192 + (uint)r * 128 + (((uint)(7 ^ (r & 7))) << 4) + ((uint)(m0 & 7)) * 2;
                *(uint*)(PHb + off) = 0u;
                *(uint*)(PLb + off) = 0u;
            }
        }
    }
    __syncwarp();   // P rows are warp-local

    // ---------------- P5: O = P @ V (bf16 3-split) -> O bf16 hi/lo ----------------
    {
        const int h = wg >> 2, mt = wg & 3;
        const int arow = mt * 16 + (og & 15);
        const int ac8  = og >> 4;
        float acc[4][4];
        #pragma unroll
        for (int t = 0; t < 4; ++t)
            #pragma unroll
            for (int j = 0; j < 4; ++j) acc[t][j] = 0.f;

        #pragma unroll
        for (int ks = 0; ks < 4; ++ks) {
            uint aoff = (uint)h * 8192 + (uint)arow * 128 + (((uint)((2 * ks + ac8) ^ (arow & 7))) << 4);
            uint ah[4], al[4];
            ldsm4(ah, phA + aoff);
            ldsm4(al, plA + aoff);
            #pragma unroll
            for (int tp = 0; tp < 2; ++tp) {
                int nr = h * 32 + tp * 16 + brl2;
                uint boff = (uint)nr * 128 + (((uint)((2 * ks + bc8g) ^ (nr & 7))) << 4);
                uint bh[4], bl[4];
                ldsm4(bh, vhA + boff);
                ldsm4(bl, vlA + boff);
                mma16816(acc[2 * tp],     ah, bh[0], bh[1]);
                mma16816(acc[2 * tp],     ah, bl[0], bl[1]);
                mma16816(acc[2 * tp],     al, bh[0], bh[1]);
                mma16816(acc[2 * tp + 1], ah, bh[2], bh[3]);
                mma16816(acc[2 * tp + 1], ah, bl[2], bl[3]);
                mma16816(acc[2 * tp + 1], al, bh[2], bh[3]);
            }
        }
        const int n0 = mt * 16 + g;
        #pragma unroll
        for (int nt = 0; nt < 4; ++nt) {
            int col = h * 32 + nt * 8 + 2 * tig;
            #pragma unroll
            for (int half = 0; half < 2; ++half) {
                int n = n0 + 8 * half;
                if (n < NTOK) {
                    uint lo;
                    uint hi = packbf(acc[nt][2 * half], acc[nt][2 * half + 1], lo);
                    uint off = (uint)n * 256 + (((uint)((col >> 3) ^ (n & 7))) << 4) + ((uint)(col & 7)) * 2;
                    *(uint*)(OHb + off) = hi;
                    *(uint*)(OLb + off) = lo;
                }
            }
        }
    }
    __syncthreads();

    // ---------------- P6: proj GEMM (bf16 3-split), W fragments from L2 ----------------
    {
        const int mw = wg & 3, nwg = wg >> 2;
        const int arow = mw * 16 + (og & 15);
        const int ac8  = og >> 4;
        float acc[4][4];
        #pragma unroll
        for (int t = 0; t < 4; ++t)
            #pragma unroll
            for (int j = 0; j < 4; ++j) acc[t][j] = 0.f;

        const uint4* fH = g_wpf_hi + ((nwg * 2) * 8) * 32 + og;
        const uint4* fL = g_wpf_lo + ((nwg * 2) * 8) * 32 + og;

        #pragma unroll
        for (int ks = 0; ks < 8; ++ks) {
            uint aoff = (uint)arow * 256 + (((uint)((2 * ks + ac8) ^ (arow & 7))) << 4);
            uint ah[4], al[4];
            ldsm4(ah, ohA + aoff);
            ldsm4(al, olA + aoff);
            #pragma unroll
            for (int tp = 0; tp < 2; ++tp) {
                uint4 bh = __ldg(fH + (tp * 8 + ks) * 32);
                uint4 bl = __ldg(fL + (tp * 8 + ks) * 32);
                mma16816(acc[2 * tp],     ah, bh.x, bh.y);
                mma16816(acc[2 * tp],     ah, bl.x, bl.y);
                mma16816(acc[2 * tp],     al, bh.x, bh.y);
                mma16816(acc[2 * tp + 1], ah, bh.z, bh.w);
                mma16816(acc[2 * tp + 1], ah, bl.z, bl.w);
                mma16816(acc[2 * tp + 1], al, bh.z, bh.w);
            }
        }
        float* og_ptr = out + (size_t)b * NTOK * CDIM;
        const int c = tig * 2;
        const int n0 = mw * 16 + g;
        #pragma unroll
        for (int t = 0; t < 4; ++t) {
            int o = nwg * 32 + t * 8 + c;
            float b0 = __ldg(&proj_b[o]), b1 = __ldg(&proj_b[o + 1]);
            if (n0 < NTOK)
                *(float2*)&og_ptr[n0 * CDIM + o] = make_float2(acc[t][0] + b0, acc[t][1] + b1);
            if (n0 + 8 < NTOK)
                *(float2*)&og_ptr[(n0 + 8) * CDIM + o] = make_float2(acc[t][2] + b0, acc[t][3] + b1);
        }
    }
}

extern "C" void kernel_launch(void* const* d_in, const int* in_sizes, int n_in,
                              void* d_out, int out_size)
{
    (void)in_sizes; (void)n_in; (void)out_size;
    const float* x          = (const float*)d_in[0];
    const float* mask       = (const float*)d_in[1];
    const float* qkv_w      = (const float*)d_in[2];
    const float* proj_w     = (const float*)d_in[3];
    const float* proj_b     = (const float*)d_in[4];
    const float* bias_table = (const float*)d_in[5];
    const float* alpha      = (const float*)d_in[6];
    const int*   rel_idx    = (const int*)d_in[7];
    float* out = (float*)d_out;

    int conv_elems = NFRAG_Q + NFRAG_P + HEADS * 2401;
    conv_w_kernel<<<(conv_elems + 255) / 256, 256>>>(qkv_w, proj_w, bias_table, rel_idx);

    cudaFuncSetAttribute(lpwin_attn_kernel,
                         cudaFuncAttributeMaxDynamicSharedMemorySize, SMEM_BYTES);
    lpwin_attn_kernel<<<BWIN, THREADS, SMEM_BYTES>>>(
        x, mask, qkv_w, proj_w, proj_b, bias_table, alpha, rel_idx, out);
}

// round 13
// speedup vs baseline: 4.6211x; 1.0250x over previous
#include <cuda_runtime.h>
#include <cuda_bf16.h>
#include <math.h>

// Problem constants
#define BWIN 8192
#define NTOK 49
#define CDIM 128
#define HEADS 4
#define NWIN 4096
#define THREADS 512

// smem byte offsets
#define B_KH   0         // K^ bf16 hi (16KB)
#define B_KL   16384     // K^ bf16 lo
#define B_QO   32768     // Q^ bf16 hi -> O bf16 hi (warp-local overlay)
#define B_QOL  49152     // Q^ bf16 lo -> O bf16 lo
#define B_X    65536     // X bf16 hi -> V^T bf16 hi
#define B_XLO  81920     // X bf16 lo -> V^T bf16 lo
#define B_MASK 98304     // mask f32 (2401 floats)
#define SMEM_BYTES 107908

#define QKV_T16  24
#define PROJ_T16 8
#define NFRAG_Q  (QKV_T16 * 8 * 32)    // 6144 uint4
#define NFRAG_P  (PROJ_T16 * 8 * 32)   // 2048 uint4

typedef unsigned long long ull;
typedef unsigned int uint;
typedef unsigned short ushort;

__device__ uint4 g_wqf_hi[NFRAG_Q];
__device__ uint4 g_wqf_lo[NFRAG_Q];
__device__ uint4 g_wpf_hi[NFRAG_P];
__device__ uint4 g_wpf_lo[NFRAG_P];
__device__ float g_rpb[HEADS * 49 * 50];   // [h][n][m], row stride 50

__device__ __forceinline__ uint smem_u32(const void* p){
    uint a; asm("{ .reg .u64 t; cvta.to.shared.u64 t, %1; cvt.u32.u64 %0, t; }" : "=r"(a) : "l"(p));
    return a;
}
__device__ __forceinline__ void ldsm4(uint* r, uint addr){
    asm volatile("ldmatrix.sync.aligned.m8n8.x4.shared.b16 {%0,%1,%2,%3}, [%4];"
        : "=r"(r[0]), "=r"(r[1]), "=r"(r[2]), "=r"(r[3]) : "r"(addr));
}
__device__ __forceinline__ void ldsm2(uint &r0, uint &r1, uint addr){
    asm volatile("ldmatrix.sync.aligned.m8n8.x2.shared.b16 {%0,%1}, [%2];"
        : "=r"(r0), "=r"(r1) : "r"(addr));
}
__device__ __forceinline__ void mma16816(float* d, const uint* a, uint b0, uint b1){
    asm volatile("mma.sync.aligned.m16n8k16.row.col.f32.bf16.bf16.f32 "
        "{%0,%1,%2,%3}, {%4,%5,%6,%7}, {%8,%9}, {%0,%1,%2,%3};"
        : "+f"(d[0]), "+f"(d[1]), "+f"(d[2]), "+f"(d[3])
        : "r"(a[0]), "r"(a[1]), "r"(a[2]), "r"(a[3]), "r"(b0), "r"(b1));
}
__device__ __forceinline__ ushort bfhi(float v, float &rest){
    __nv_bfloat16 h = __float2bfloat16(v);
    rest = v - __bfloat162float(h);
    return *(ushort*)&h;
}
__device__ __forceinline__ ushort bfbits(float v){
    __nv_bfloat16 h = __float2bfloat16(v);
    return *(ushort*)&h;
}
__device__ __forceinline__ uint packbf(float a, float b, uint &lo){
    float ra, rb;
    ushort ha = bfhi(a, ra), hb = bfhi(b, rb);
    lo = ((uint)bfbits(rb) << 16) | bfbits(ra);
    return ((uint)hb << 16) | ha;
}

extern __shared__ float smem[];

__global__ void conv_w_kernel(const float* __restrict__ qkv_w,
                              const float* __restrict__ proj_w,
                              const float* __restrict__ bias_table,
                              const int*   __restrict__ rel_idx){
    int i = blockIdx.x * blockDim.x + threadIdx.x;
    if (i < NFRAG_Q + NFRAG_P) {
        bool isq = (i < NFRAG_Q);
        int idx = isq ? i : i - NFRAG_Q;
        const float* W = isq ? qkv_w : proj_w;
        int tile = idx >> 8;
        int ks   = (idx >> 5) & 7;
        int lane = idx & 31;
        int r0 = tile * 16 + (lane >> 2);
        int r1 = r0 + 8;
        int c0 = ks * 16 + 2 * (lane & 3);
        uint4 hv, lv;
        hv.x = packbf(W[r0 * 128 + c0],     W[r0 * 128 + c0 + 1], lv.x);
        hv.y = packbf(W[r0 * 128 + c0 + 8], W[r0 * 128 + c0 + 9], lv.y);
        hv.z = packbf(W[r1 * 128 + c0],     W[r1 * 128 + c0 + 1], lv.z);
        hv.w = packbf(W[r1 * 128 + c0 + 8], W[r1 * 128 + c0 + 9], lv.w);
        if (isq) { g_wqf_hi[idx] = hv; g_wqf_lo[idx] = lv; }
        else     { g_wpf_hi[idx] = hv; g_wpf_lo[idx] = lv; }
    } else if (i < NFRAG_Q + NFRAG_P + HEADS * 2401) {
        int j = i - (NFRAG_Q + NFRAG_P);
        int h = j / 2401, e = j % 2401;
        int n = e / 49, m = e % 49;
        g_rpb[h * 2450 + n * 50 + m] = bias_table[rel_idx[e] * 4 + h];
    }
}

__global__ void __launch_bounds__(THREADS, 1)
lpwin_attn_kernel(const float* __restrict__ x,
                  const float* __restrict__ mask,
                  const float* __restrict__ qkv_w,
                  const float* __restrict__ proj_w,
                  const float* __restrict__ proj_b,
                  const float* __restrict__ bias_table,
                  const float* __restrict__ alpha,
                  const int*   __restrict__ rel_idx,
                  float* __restrict__ out)
{
    char* SB = (char*)smem;
    float* MASKS = (float*)(SB + B_MASK);

    const int tid = threadIdx.x;
    const int b   = blockIdx.x;
    const int w   = b & (NWIN - 1);
    const int og  = tid & 31;
    const int wg  = tid >> 5;

    const uint base = smem_u32(smem);
    const uint khA = base + B_KH,  klA = base + B_KL;
    const uint qoA = base + B_QO,  qolA = base + B_QOL;
    const uint xhA = base + B_X,   xlA = base + B_XLO;
    const uint vhA = base + B_X,   vlA = base + B_XLO;

    char* KHb = SB + B_KH;  char* KLb = SB + B_KL;
    char* QOb = SB + B_QO;  char* QOLb = SB + B_QOL;
    char* XHb = SB + B_X;   char* XLb = SB + B_XLO;
    char* VHb = SB + B_X;   char* VLb = SB + B_XLO;

    // lane decomposition
    const int brl  = og & 7;
    const int bc8g = (og >> 3) & 1;
    const int brl2 = (og & 7) + ((og & 16) >> 1);
    const int g    = og >> 2, tig = og & 3;

    // ---------------- P1 + P2a: mask; x -> bf16 hi/lo swizzled ----------------
    {
        const float* mg = mask + (size_t)w * NTOK * NTOK;
        for (int i = tid; i < NTOK * NTOK; i += THREADS) MASKS[i] = mg[i];

        const float4* xg4 = (const float4*)(x + (size_t)b * NTOK * CDIM);
        for (int i = tid; i < 49 * 16; i += THREADS) {
            int n = i >> 4, c8 = i & 15;
            float4 a = xg4[n * 32 + c8 * 2];
            float4 c = xg4[n * 32 + c8 * 2 + 1];
            float vs[8] = {a.x, a.y, a.z, a.w, c.x, c.y, c.z, c.w};
            ushort hs[8], ls[8];
            #pragma unroll
            for (int j = 0; j < 8; ++j) {
                float rest;
                hs[j] = bfhi(vs[j], rest);
                ls[j] = bfbits(rest);
            }
            uint off = (uint)n * 256 + (((uint)(c8 ^ (n & 7))) << 4);
            *(uint4*)(XHb + off) = *(uint4*)hs;
            *(uint4*)(XLb + off) = *(uint4*)ls;
        }
        uint4 z = make_uint4(0, 0, 0, 0);
        for (int i = tid; i < 15 * 16; i += THREADS) {
            int n = 49 + (i >> 4), c8 = i & 15;
            uint off = (uint)n * 256 + (((uint)(c8 ^ (n & 7))) << 4);
            *(uint4*)(XHb + off) = z;
            *(uint4*)(XLb + off) = z;
        }
    }
    __syncthreads();

    // ---------------- P2b: QKV GEMM (bf16 3-split), W fragments from L2, fused epilogues ----------------
    {
        const int mw = wg & 3, nwg = wg >> 2;
        const int arow = mw * 16 + (og & 15);
        const int ac8  = og >> 4;
        const int n0 = mw * 16 + g;
        float accV[4][4];

        for (int pass = 0; pass < 3; ++pass) {
            float acc[4][4];
            #pragma unroll
            for (int t = 0; t < 4; ++t)
                #pragma unroll
                for (int j = 0; j < 4; ++j) acc[t][j] = 0.f;

            const uint4* fH = g_wqf_hi + ((pass * 8 + nwg * 2) * 8) * 32 + og;
            const uint4* fL = g_wqf_lo + ((pass * 8 + nwg * 2) * 8) * 32 + og;

            #pragma unroll
            for (int ks = 0; ks < 8; ++ks) {
                uint aoff = (uint)arow * 256 + (((uint)((2 * ks + ac8) ^ (arow & 7))) << 4);
                uint ah[4], al[4];
                ldsm4(ah, xhA + aoff);
                ldsm4(al, xlA + aoff);
                #pragma unroll
                for (int tp = 0; tp < 2; ++tp) {
                    uint4 bh = __ldg(fH + (tp * 8 + ks) * 32);
                    uint4 bl = __ldg(fL + (tp * 8 + ks) * 32);
                    mma16816(acc[2 * tp],     ah, bh.x, bh.y);
                    mma16816(acc[2 * tp],     ah, bl.x, bl.y);
                    mma16816(acc[2 * tp],     al, bh.x, bh.y);
                    mma16816(acc[2 * tp + 1], ah, bh.z, bh.w);
                    mma16816(acc[2 * tp + 1], ah, bl.z, bl.w);
                    mma16816(acc[2 * tp + 1], al, bh.z, bh.w);
                }
            }

            if (pass < 2) {
                // fused epilogue: L2-normalize rows of this head (quad owns full head-row)
                float ss0 = 0.f, ss1 = 0.f;
                #pragma unroll
                for (int t = 0; t < 4; ++t) {
                    ss0 += acc[t][0] * acc[t][0] + acc[t][1] * acc[t][1];
                    ss1 += acc[t][2] * acc[t][2] + acc[t][3] * acc[t][3];
                }
                ss0 += __shfl_xor_sync(0xffffffffu, ss0, 1);
                ss0 += __shfl_xor_sync(0xffffffffu, ss0, 2);
                ss1 += __shfl_xor_sync(0xffffffffu, ss1, 1);
                ss1 += __shfl_xor_sync(0xffffffffu, ss1, 2);
                float sc = (pass == 0) ? __ldg(&alpha[nwg]) : 1.f;
                float inv0 = sc / (sqrtf(ss0) + 1e-6f);
                float inv1 = sc / (sqrtf(ss1) + 1e-6f);
                char* Hb = (pass == 0) ? QOb : KHb;
                char* Lb = (pass == 0) ? QOLb : KLb;
                #pragma unroll
                for (int t = 0; t < 4; ++t) {
                    int col = nwg * 32 + t * 8 + 2 * tig;
                    int c8 = col >> 3;
                    uint lo0, lo1;
                    uint h0 = packbf(acc[t][0] * inv0, acc[t][1] * inv0, lo0);
                    uint off0 = (uint)n0 * 256 + (((uint)(c8 ^ (n0 & 7))) << 4) + ((uint)(col & 7)) * 2;
                    *(uint*)(Hb + off0) = h0;
                    *(uint*)(Lb + off0) = lo0;
                    int n1 = n0 + 8;
                    uint h1 = packbf(acc[t][2] * inv1, acc[t][3] * inv1, lo1);
                    uint off1 = (uint)n1 * 256 + (((uint)(c8 ^ (n1 & 7))) << 4) + ((uint)(col & 7)) * 2;
                    *(uint*)(Hb + off1) = h1;
                    *(uint*)(Lb + off1) = lo1;
                }
            } else {
                #pragma unroll
                for (int t = 0; t < 4; ++t)
                    #pragma unroll
                    for (int j = 0; j < 4; ++j) accV[t][j] = acc[t][j];
            }
        }
        __syncthreads();   // all warps done reading X before V^T overwrite

        // fused epilogue: V^T bf16 (rows = channel, cols = token; pad tokens exact zeros)
        const int nwg2 = wg >> 2;
        #pragma unroll
        for (int t = 0; t < 4; ++t) {
            #pragma unroll
            for (int j = 0; j < 2; ++j) {
                int c = nwg2 * 32 + t * 8 + 2 * tig + j;
                #pragma unroll
                for (int half = 0; half < 2; ++half) {
                    int m = n0 + 8 * half;
                    float v = accV[t][2 * half + j];
                    float rest;
                    ushort hv = bfhi(v, rest);
                    uint off = (uint)c * 128 + (((uint)((m >> 3) ^ (c & 7))) << 4) + ((uint)(m & 7)) * 2;
                    *(ushort*)(VHb + off) = hv;
                    *(ushort*)(VLb + off) = bfbits(rest);
                }
            }
        }
    }
    __syncthreads();

    // ---------------- P4+P5 fused: logits -> register softmax -> P@V, all per-warp ----------------
    {
        const int h = wg >> 2, mt = wg & 3;
        const int arow = mt * 16 + (og & 15);
        const int ac8  = og >> 4;
        float acc[7][4];
        #pragma unroll
        for (int t = 0; t < 7; ++t)
            #pragma unroll
            for (int j = 0; j < 4; ++j) acc[t][j] = 0.f;

        #pragma unroll
        for (int ks = 0; ks < 2; ++ks) {
            uint aoff = (uint)arow * 256 + (((uint)((h * 4 + 2 * ks + ac8) ^ (arow & 7))) << 4);
            uint ah[4], al[4];
            ldsm4(ah, qoA + aoff);
            ldsm4(al, qolA + aoff);
            #pragma unroll
            for (int p = 0; p < 3; ++p) {
                int tok = p * 16 + brl2;
                uint boff = (uint)tok * 256 + (((uint)((h * 4 + 2 * ks + bc8g) ^ (tok & 7))) << 4);
                uint bh[4], bl[4];
                ldsm4(bh, khA + boff);
                ldsm4(bl, klA + boff);
                mma16816(acc[2 * p],     ah, bh[0], bh[1]);
                mma16816(acc[2 * p],     ah, bl[0], bl[1]);
                mma16816(acc[2 * p],     al, bh[0], bh[1]);
                mma16816(acc[2 * p + 1], ah, bh[2], bh[3]);
                mma16816(acc[2 * p + 1], ah, bl[2], bl[3]);
                mma16816(acc[2 * p + 1], al, bh[2], bh[3]);
            }
            {
                int tok = 48 + brl;   // K rows 49..55 exact zeros
                uint boff = (uint)tok * 256 + (((uint)((h * 4 + 2 * ks + bc8g) ^ (tok & 7))) << 4);
                uint bh0, bh1, bl0, bl1;
                ldsm2(bh0, bh1, khA + boff);
                ldsm2(bl0, bl1, klA + boff);
                mma16816(acc[6], ah, bh0, bh1);
                mma16816(acc[6], ah, bl0, bl1);
                mma16816(acc[6], al, bh0, bh1);
            }
        }

        // register softmax -> pv0 (rows g), pv1 (rows g+8), already scaled by 1/sum
        const float* rpbh = g_rpb + h * 2450;
        float pv0[14], pv1[14];
        #pragma unroll
        for (int half = 0; half < 2; ++half) {
            int r = mt * 16 + g + 8 * half;
            int nr = (r < NTOK) ? r : 0;
            float* pv = half ? pv1 : pv0;
            float mx = -1e30f;
            #pragma unroll
            for (int nt = 0; nt < 7; ++nt) {
                int m0 = nt * 8 + 2 * tig;
                float v0 = acc[nt][2 * half], v1 = acc[nt][2 * half + 1];
                if (m0 < NTOK) {
                    float2 rp = *(const float2*)&rpbh[nr * 50 + m0];
                    v0 += rp.x + MASKS[nr * 49 + m0];
                    v1 = (m0 + 1 < NTOK) ? (v1 + rp.y + MASKS[nr * 49 + m0 + 1]) : -1e30f;
                } else { v0 = -1e30f; v1 = -1e30f; }
                pv[2 * nt] = v0; pv[2 * nt + 1] = v1;
                mx = fmaxf(mx, fmaxf(v0, v1));
            }
            mx = fmaxf(mx, __shfl_xor_sync(0xffffffffu, mx, 1));
            mx = fmaxf(mx, __shfl_xor_sync(0xffffffffu, mx, 2));
            float sm = 0.f;
            #pragma unroll
            for (int i = 0; i < 14; ++i) { pv[i] = __expf(pv[i] - mx); sm += pv[i]; }
            sm += __shfl_xor_sync(0xffffffffu, sm, 1);
            sm += __shfl_xor_sync(0xffffffffu, sm, 2);
            float inv = 1.f / sm;
            #pragma unroll
            for (int i = 0; i < 14; ++i) pv[i] *= inv;
        }

        // P5: O = P @ V; A-fragments straight from pv registers (accumulator->A layout identity)
        float oacc[4][4];
        #pragma unroll
        for (int t = 0; t < 4; ++t)
            #pragma unroll
            for (int j = 0; j < 4; ++j) oacc[t][j] = 0.f;

        #pragma unroll
        for (int ks = 0; ks < 4; ++ks) {
            uint ah[4], al[4];
            ah[0] = packbf(pv0[4 * ks],     pv0[4 * ks + 1], al[0]);
            ah[1] = packbf(pv1[4 * ks],     pv1[4 * ks + 1], al[1]);
            if (ks < 3) {
                ah[2] = packbf(pv0[4 * ks + 2], pv0[4 * ks + 3], al[2]);
                ah[3] = packbf(pv1[4 * ks + 2], pv1[4 * ks + 3], al[3]);
            } else {
                ah[2] = 0u; ah[3] = 0u; al[2] = 0u; al[3] = 0u;   // m 56..63
            }
            #pragma unroll
            for (int tp = 0; tp < 2; ++tp) {
                int nr = h * 32 + tp * 16 + brl2;
                uint boff = (uint)nr * 128 + (((uint)((2 * ks + bc8g) ^ (nr & 7))) << 4);
                uint bh[4], bl[4];
                ldsm4(bh, vhA + boff);
                ldsm4(bl, vlA + boff);
                mma16816(oacc[2 * tp],     ah, bh[0], bh[1]);
                mma16816(oacc[2 * tp],     ah, bl[0], bl[1]);
                mma16816(oacc[2 * tp],     al, bh[0], bh[1]);
                mma16816(oacc[2 * tp + 1], ah, bh[2], bh[3]);
                mma16816(oacc[2 * tp + 1], ah, bl[2], bl[3]);
                mma16816(oacc[2 * tp + 1], al, bh[2], bh[3]);
            }
        }
        // O epilogue -> QO region (warp-local overlay of Q)
        const int n0 = mt * 16 + g;
        #pragma unroll
        for (int nt = 0; nt < 4; ++nt) {
            int col = h * 32 + nt * 8 + 2 * tig;
            #pragma unroll
            for (int half = 0; half < 2; ++half) {
                int n = n0 + 8 * half;
                if (n < NTOK) {
                    uint lo;
                    uint hi = packbf(oacc[nt][2 * half], oacc[nt][2 * half + 1], lo);
                    uint off = (uint)n * 256 + (((uint)((col >> 3) ^ (n & 7))) << 4) + ((uint)(col & 7)) * 2;
                    *(uint*)(QOb + off) = hi;
                    *(uint*)(QOLb + off) = lo;
                }
            }
        }
    }
    __syncthreads();

    // ---------------- P6: proj GEMM (bf16 3-split), W fragments from L2 ----------------
    {
        const int mw = wg & 3, nwg = wg >> 2;
        const int arow = mw * 16 + (og & 15);
        const int ac8  = og >> 4;
        float acc[4][4];
        #pragma unroll
        for (int t = 0; t < 4; ++t)
            #pragma unroll
            for (int j = 0; j < 4; ++j) acc[t][j] = 0.f;

        const uint4* fH = g_wpf_hi + ((nwg * 2) * 8) * 32 + og;
        const uint4* fL = g_wpf_lo + ((nwg * 2) * 8) * 32 + og;

        #pragma unroll
        for (int ks = 0; ks < 8; ++ks) {
            uint aoff = (uint)arow * 256 + (((uint)((2 * ks + ac8) ^ (arow & 7))) << 4);
            uint ah[4], al[4];
            ldsm4(ah, qoA + aoff);
            ldsm4(al, qolA + aoff);
            #pragma unroll
            for (int tp = 0; tp < 2; ++tp) {
                uint4 bh = __ldg(fH + (tp * 8 + ks) * 32);
                uint4 bl = __ldg(fL + (tp * 8 + ks) * 32);
                mma16816(acc[2 * tp],     ah, bh.x, bh.y);
                mma16816(acc[2 * tp],     ah, bl.x, bl.y);
                mma16816(acc[2 * tp],     al, bh.x, bh.y);
                mma16816(acc[2 * tp + 1], ah, bh.z, bh.w);
                mma16816(acc[2 * tp + 1], ah, bl.z, bl.w);
                mma16816(acc[2 * tp + 1], al, bh.z, bh.w);
            }
        }
        float* og_ptr = out + (size_t)b * NTOK * CDIM;
        const int c = tig * 2;
        const int n0 = mw * 16 + g;
        #pragma unroll
        for (int t = 0; t < 4; ++t) {
            int o = nwg * 32 + t * 8 + c;
            float b0 = __ldg(&proj_b[o]), b1 = __ldg(&proj_b[o + 1]);
            if (n0 < NTOK)
                *(float2*)&og_ptr[n0 * CDIM + o] = make_float2(acc[t][0] + b0, acc[t][1] + b1);
            if (n0 + 8 < NTOK)
                *(float2*)&og_ptr[(n0 + 8) * CDIM + o] = make_float2(acc[t][2] + b0, acc[t][3] + b1);
        }
    }
}

extern "C" void kernel_launch(void* const* d_in, const int* in_sizes, int n_in,
                              void* d_out, int out_size)
{
    (void)in_sizes; (void)n_in; (void)out_size;
    const float* x          = (const float*)d_in[0];
    const float* mask       = (const float*)d_in[1];
    const float* qkv_w      = (const float*)d_in[2];
    const float* proj_w     = (const float*)d_in[3];
    const float* proj_b     = (const float*)d_in[4];
    const float* bias_table = (const float*)d_in[5];
    const float* alpha      = (const float*)d_in[6];
    const int*   rel_idx    = (const int*)d_in[7];
    float* out = (float*)d_out;

    int conv_elems = NFRAG_Q + NFRAG_P + HEADS * 2401;
    conv_w_kernel<<<(conv_elems + 255) / 256, 256>>>(qkv_w, proj_w, bias_table, rel_idx);

    cudaFuncSetAttribute(lpwin_attn_kernel,
                         cudaFuncAttributeMaxDynamicSharedMemorySize, SMEM_BYTES);
    lpwin_attn_kernel<<<BWIN, THREADS, SMEM_BYTES>>>(
        x, mask, qkv_w, proj_w, proj_b, bias_table, alpha, rel_idx, out);
}

// round 14
// speedup vs baseline: 4.6235x; 1.0005x over previous
#include <cuda_runtime.h>
#include <cuda_bf16.h>
#include <math.h>

// Problem constants
#define BWIN 8192
#define NTOK 49
#define CDIM 128
#define HEADS 4
#define NWIN 4096
#define THREADS 512

// smem byte offsets (regions hold 128 rows x 256B = 32KB; rows = win*64 + n)
#define B_KH   0         // K^ bf16 hi
#define B_KL   32768     // K^ bf16 lo
#define B_QO   65536     // Q^ bf16 hi -> O bf16 hi (warp-local overlay)
#define B_QOL  98304     // Q^ bf16 lo -> O bf16 lo
#define B_X    131072    // X bf16 hi -> V^T bf16 hi
#define B_XLO  163840    // X bf16 lo -> V^T bf16 lo
#define B_MASK 196608    // 2 masks f32 (2*2401 floats)
#define SMEM_BYTES 215816

#define QKV_T16  24
#define PROJ_T16 8
#define NFRAG_Q  (QKV_T16 * 8 * 32)    // 6144 uint4
#define NFRAG_P  (PROJ_T16 * 8 * 32)   // 2048 uint4

typedef unsigned long long ull;
typedef unsigned int uint;
typedef unsigned short ushort;

__device__ uint4 g_wqf_hi[NFRAG_Q];
__device__ uint4 g_wqf_lo[NFRAG_Q];
__device__ uint4 g_wpf_hi[NFRAG_P];
__device__ uint4 g_wpf_lo[NFRAG_P];
__device__ float g_rpb[HEADS * 49 * 50];   // [h][n][m], row stride 50

__device__ __forceinline__ uint smem_u32(const void* p){
    uint a; asm("{ .reg .u64 t; cvta.to.shared.u64 t, %1; cvt.u32.u64 %0, t; }" : "=r"(a) : "l"(p));
    return a;
}
__device__ __forceinline__ void ldsm4(uint* r, uint addr){
    asm volatile("ldmatrix.sync.aligned.m8n8.x4.shared.b16 {%0,%1,%2,%3}, [%4];"
        : "=r"(r[0]), "=r"(r[1]), "=r"(r[2]), "=r"(r[3]) : "r"(addr));
}
__device__ __forceinline__ void ldsm2(uint &r0, uint &r1, uint addr){
    asm volatile("ldmatrix.sync.aligned.m8n8.x2.shared.b16 {%0,%1}, [%2];"
        : "=r"(r0), "=r"(r1) : "r"(addr));
}
__device__ __forceinline__ void mma16816(float* d, const uint* a, uint b0, uint b1){
    asm volatile("mma.sync.aligned.m16n8k16.row.col.f32.bf16.bf16.f32 "
        "{%0,%1,%2,%3}, {%4,%5,%6,%7}, {%8,%9}, {%0,%1,%2,%3};"
        : "+f"(d[0]), "+f"(d[1]), "+f"(d[2]), "+f"(d[3])
        : "r"(a[0]), "r"(a[1]), "r"(a[2]), "r"(a[3]), "r"(b0), "r"(b1));
}
__device__ __forceinline__ ushort bfhi(float v, float &rest){
    __nv_bfloat16 h = __float2bfloat16(v);
    rest = v - __bfloat162float(h);
    return *(ushort*)&h;
}
__device__ __forceinline__ ushort bfbits(float v){
    __nv_bfloat16 h = __float2bfloat16(v);
    return *(ushort*)&h;
}
__device__ __forceinline__ uint packbf(float a, float b, uint &lo){
    float ra, rb;
    ushort ha = bfhi(a, ra), hb = bfhi(b, rb);
    lo = ((uint)bfbits(rb) << 16) | bfbits(ra);
    return ((uint)hb << 16) | ha;
}

extern __shared__ float smem[];

__global__ void conv_w_kernel(const float* __restrict__ qkv_w,
                              const float* __restrict__ proj_w,
                              const float* __restrict__ bias_table,
                              const int*   __restrict__ rel_idx){
    int i = blockIdx.x * blockDim.x + threadIdx.x;
    if (i < NFRAG_Q + NFRAG_P) {
        bool isq = (i < NFRAG_Q);
        int idx = isq ? i : i - NFRAG_Q;
        const float* W = isq ? qkv_w : proj_w;
        int tile = idx >> 8;
        int ks   = (idx >> 5) & 7;
        int lane = idx & 31;
        int r0 = tile * 16 + (lane >> 2);
        int r1 = r0 + 8;
        int c0 = ks * 16 + 2 * (lane & 3);
        uint4 hv, lv;
        hv.x = packbf(W[r0 * 128 + c0],     W[r0 * 128 + c0 + 1], lv.x);
        hv.y = packbf(W[r0 * 128 + c0 + 8], W[r0 * 128 + c0 + 9], lv.y);
        hv.z = packbf(W[r1 * 128 + c0],     W[r1 * 128 + c0 + 1], lv.z);
        hv.w = packbf(W[r1 * 128 + c0 + 8], W[r1 * 128 + c0 + 9], lv.w);
        if (isq) { g_wqf_hi[idx] = hv; g_wqf_lo[idx] = lv; }
        else     { g_wpf_hi[idx] = hv; g_wpf_lo[idx] = lv; }
    } else if (i < NFRAG_Q + NFRAG_P + HEADS * 2401) {
        int j = i - (NFRAG_Q + NFRAG_P);
        int h = j / 2401, e = j % 2401;
        int n = e / 49, m = e % 49;
        g_rpb[h * 2450 + n * 50 + m] = bias_table[rel_idx[e] * 4 + h];
    }
}

__global__ void __launch_bounds__(THREADS, 1)
lpwin_attn_kernel(const float* __restrict__ x,
                  const float* __restrict__ mask,
                  const float* __restrict__ qkv_w,
                  const float* __restrict__ proj_w,
                  const float* __restrict__ proj_b,
                  const float* __restrict__ bias_table,
                  const float* __restrict__ alpha,
                  const int*   __restrict__ rel_idx,
                  float* __restrict__ out)
{
    char* SB = (char*)smem;

    const int tid = threadIdx.x;
    const int blk = blockIdx.x;             // window pair: windows 2*blk, 2*blk+1
    const int bw0 = (2 * blk) & (NWIN - 1); // mask indices bw0, bw0+1
    const int og  = tid & 31;
    const int wg  = tid >> 5;

    const uint base = smem_u32(smem);
    const uint khA = base + B_KH,  klA = base + B_KL;
    const uint qoA = base + B_QO,  qolA = base + B_QOL;
    const uint xhA = base + B_X,   xlA = base + B_XLO;
    const uint vhA = base + B_X,   vlA = base + B_XLO;

    char* KHb = SB + B_KH;  char* KLb = SB + B_KL;
    char* QOb = SB + B_QO;  char* QOLb = SB + B_QOL;
    char* XHb = SB + B_X;   char* XLb = SB + B_XLO;
    char* VHb = SB + B_X;   char* VLb = SB + B_XLO;
    float* MASK0 = (float*)(SB + B_MASK);
    float* MASK1 = MASK0 + 2401;

    // lane decomposition
    const int brl  = og & 7;
    const int bc8g = (og >> 3) & 1;
    const int brl2 = (og & 7) + ((og & 16) >> 1);
    const int g    = og >> 2, tig = og & 3;

    // ---------------- P1 + P2a: masks; x (2 windows) -> bf16 hi/lo swizzled ----------------
    {
        for (int i = tid; i < 2401; i += THREADS) MASK0[i] = mask[(size_t)bw0 * 2401 + i];
        for (int i = tid; i < 2401; i += THREADS) MASK1[i] = mask[(size_t)(bw0 + 1) * 2401 + i];

        #pragma unroll
        for (int win = 0; win < 2; ++win) {
            const float4* xg4 = (const float4*)(x + (size_t)(2 * blk + win) * NTOK * CDIM);
            for (int i = tid; i < 49 * 16; i += THREADS) {
                int n = i >> 4, c8 = i & 15;
                int row = win * 64 + n;
                float4 a = xg4[n * 32 + c8 * 2];
                float4 c = xg4[n * 32 + c8 * 2 + 1];
                float vs[8] = {a.x, a.y, a.z, a.w, c.x, c.y, c.z, c.w};
                ushort hs[8], ls[8];
                #pragma unroll
                for (int j = 0; j < 8; ++j) {
                    float rest;
                    hs[j] = bfhi(vs[j], rest);
                    ls[j] = bfbits(rest);
                }
                uint off = (uint)row * 256 + (((uint)(c8 ^ (row & 7))) << 4);
                *(uint4*)(XHb + off) = *(uint4*)hs;
                *(uint4*)(XLb + off) = *(uint4*)ls;
            }
        }
        uint4 z = make_uint4(0, 0, 0, 0);
        for (int i = tid; i < 2 * 15 * 16; i += THREADS) {
            int ni = i >> 4, c8 = i & 15;
            int win = ni / 15, n = 49 + ni % 15;
            int row = win * 64 + n;
            uint off = (uint)row * 256 + (((uint)(c8 ^ (row & 7))) << 4);
            *(uint4*)(XHb + off) = z;
            *(uint4*)(XLb + off) = z;
        }
    }
    __syncthreads();

    // ---------------- P2b: QKV GEMM (bf16 3-split), M=128, W fragments from L2 ----------------
    {
        const int mw = wg >> 1, nwg = wg & 1;          // 8 m-tiles x 2 n-halves
        const int arow = mw * 16 + (og & 15);
        const int ac8  = og >> 4;
        const int n0 = mw * 16 + g;
        float accV[8][4];

        for (int pass = 0; pass < 3; ++pass) {
            float acc[8][4];
            #pragma unroll
            for (int t = 0; t < 8; ++t)
                #pragma unroll
                for (int j = 0; j < 4; ++j) acc[t][j] = 0.f;

            const uint4* fH = g_wqf_hi + (pass * 8 + nwg * 4) * 256 + og;
            const uint4* fL = g_wqf_lo + (pass * 8 + nwg * 4) * 256 + og;

            #pragma unroll
            for (int ks = 0; ks < 8; ++ks) {
                uint aoff = (uint)arow * 256 + (((uint)((2 * ks + ac8) ^ (arow & 7))) << 4);
                uint ah[4], al[4];
                ldsm4(ah, xhA + aoff);
                ldsm4(al, xlA + aoff);
                #pragma unroll
                for (int tp = 0; tp < 4; ++tp) {
                    uint4 bh = __ldg(fH + tp * 256 + ks * 32);
                    uint4 bl = __ldg(fL + tp * 256 + ks * 32);
                    mma16816(acc[2 * tp],     ah, bh.x, bh.y);
                    mma16816(acc[2 * tp],     ah, bl.x, bl.y);
                    mma16816(acc[2 * tp],     al, bh.x, bh.y);
                    mma16816(acc[2 * tp + 1], ah, bh.z, bh.w);
                    mma16816(acc[2 * tp + 1], ah, bl.z, bl.w);
                    mma16816(acc[2 * tp + 1], al, bh.z, bh.w);
                }
            }

            if (pass < 2) {
                // fused epilogue: L2-normalize; warp covers 2 heads (nwg*2+hh)
                char* Hb = (pass == 0) ? QOb : KHb;
                char* Lb = (pass == 0) ? QOLb : KLb;
                #pragma unroll
                for (int hh = 0; hh < 2; ++hh) {
                    float ss0 = 0.f, ss1 = 0.f;
                    #pragma unroll
                    for (int tt = 0; tt < 4; ++tt) {
                        int t = hh * 4 + tt;
                        ss0 += acc[t][0] * acc[t][0] + acc[t][1] * acc[t][1];
                        ss1 += acc[t][2] * acc[t][2] + acc[t][3] * acc[t][3];
                    }
                    ss0 += __shfl_xor_sync(0xffffffffu, ss0, 1);
                    ss0 += __shfl_xor_sync(0xffffffffu, ss0, 2);
                    ss1 += __shfl_xor_sync(0xffffffffu, ss1, 1);
                    ss1 += __shfl_xor_sync(0xffffffffu, ss1, 2);
                    float sc = (pass == 0) ? __ldg(&alpha[nwg * 2 + hh]) : 1.f;
                    float inv0 = sc / (sqrtf(ss0) + 1e-6f);
                    float inv1 = sc / (sqrtf(ss1) + 1e-6f);
                    #pragma unroll
                    for (int tt = 0; tt < 4; ++tt) {
                        int t = hh * 4 + tt;
                        int col = nwg * 64 + t * 8 + 2 * tig;
                        int c8 = col >> 3;
                        uint lo0, lo1;
                        uint h0 = packbf(acc[t][0] * inv0, acc[t][1] * inv0, lo0);
                        uint off0 = (uint)n0 * 256 + (((uint)(c8 ^ (n0 & 7))) << 4) + ((uint)(col & 7)) * 2;
                        *(uint*)(Hb + off0) = h0;
                        *(uint*)(Lb + off0) = lo0;
                        int n1 = n0 + 8;
                        uint h1 = packbf(acc[t][2] * inv1, acc[t][3] * inv1, lo1);
                        uint off1 = (uint)n1 * 256 + (((uint)(c8 ^ (n1 & 7))) << 4) + ((uint)(col & 7)) * 2;
                        *(uint*)(Hb + off1) = h1;
                        *(uint*)(Lb + off1) = lo1;
                    }
                }
            } else {
                #pragma unroll
                for (int t = 0; t < 8; ++t)
                    #pragma unroll
                    for (int j = 0; j < 4; ++j) accV[t][j] = acc[t][j];
            }
        }
        __syncthreads();   // all warps done reading X before V^T overwrite

        // fused epilogue: V^T bf16 (rows = channel 0..127, cols = global row 0..127)
        #pragma unroll
        for (int t = 0; t < 8; ++t) {
            #pragma unroll
            for (int j = 0; j < 2; ++j) {
                int c = nwg * 64 + t * 8 + 2 * tig + j;
                #pragma unroll
                for (int half = 0; half < 2; ++half) {
                    int row = n0 + 8 * half;    // global row = win*64 + token (pads exact zero)
                    float v = accV[t][2 * half + j];
                    float rest;
                    ushort hv = bfhi(v, rest);
                    uint off = (uint)c * 256 + (((uint)((row >> 3) ^ (c & 7))) << 4) + ((uint)(row & 7)) * 2;
                    *(ushort*)(VHb + off) = hv;
                    *(ushort*)(VLb + off) = bfbits(rest);
                }
            }
        }
    }
    __syncthreads();

    // ---------------- P4+P5 fused, per warp: (win, head, mt-pair), 2 sequential units ----------------
    {
        const int win = wg >> 3, h = (wg >> 1) & 3, mtp = wg & 1;
        const float* rpbh = g_rpb + h * 2450;
        const float* MW = win ? MASK1 : MASK0;
        const int ac8 = og >> 4;

        #pragma unroll 1
        for (int uu = 0; uu < 2; ++uu) {
            const int mt = mtp + 2 * uu;
            const int arow = win * 64 + mt * 16 + (og & 15);
            float acc[7][4];
            #pragma unroll
            for (int t = 0; t < 7; ++t)
                #pragma unroll
                for (int j = 0; j < 4; ++j) acc[t][j] = 0.f;

            #pragma unroll
            for (int ks = 0; ks < 2; ++ks) {
                uint aoff = (uint)arow * 256 + (((uint)((h * 4 + 2 * ks + ac8) ^ (arow & 7))) << 4);
                uint ah[4], al[4];
                ldsm4(ah, qoA + aoff);
                ldsm4(al, qolA + aoff);
                #pragma unroll
                for (int p = 0; p < 3; ++p) {
                    int krow = win * 64 + p * 16 + brl2;
                    uint boff = (uint)krow * 256 + (((uint)((h * 4 + 2 * ks + bc8g) ^ (krow & 7))) << 4);
                    uint bh[4], bl[4];
                    ldsm4(bh, khA + boff);
                    ldsm4(bl, klA + boff);
                    mma16816(acc[2 * p],     ah, bh[0], bh[1]);
                    mma16816(acc[2 * p],     ah, bl[0], bl[1]);
                    mma16816(acc[2 * p],     al, bh[0], bh[1]);
                    mma16816(acc[2 * p + 1], ah, bh[2], bh[3]);
                    mma16816(acc[2 * p + 1], ah, bl[2], bl[3]);
                    mma16816(acc[2 * p + 1], al, bh[2], bh[3]);
                }
                {
                    int krow = win * 64 + 48 + brl;   // K rows 49..55 exact zeros
                    uint boff = (uint)krow * 256 + (((uint)((h * 4 + 2 * ks + bc8g) ^ (krow & 7))) << 4);
                    uint bh0, bh1, bl0, bl1;
                    ldsm2(bh0, bh1, khA + boff);
                    ldsm2(bl0, bl1, klA + boff);
                    mma16816(acc[6], ah, bh0, bh1);
                    mma16816(acc[6], ah, bl0, bl1);
                    mma16816(acc[6], al, bh0, bh1);
                }
            }

            // register softmax
            float pv0[14], pv1[14];
            #pragma unroll
            for (int half = 0; half < 2; ++half) {
                int r = mt * 16 + g + 8 * half;      // token index
                int nr = (r < NTOK) ? r : 0;
                float* pv = half ? pv1 : pv0;
                float mx = -1e30f;
                #pragma unroll
                for (int nt = 0; nt < 7; ++nt) {
                    int m0 = nt * 8 + 2 * tig;
                    float v0 = acc[nt][2 * half], v1 = acc[nt][2 * half + 1];
                    if (m0 < NTOK) {
                        float2 rp = *(const float2*)&rpbh[nr * 50 + m0];
                        v0 += rp.x + MW[nr * 49 + m0];
                        v1 = (m0 + 1 < NTOK) ? (v1 + rp.y + MW[nr * 49 + m0 + 1]) : -1e30f;
                    } else { v0 = -1e30f; v1 = -1e30f; }
                    pv[2 * nt] = v0; pv[2 * nt + 1] = v1;
                    mx = fmaxf(mx, fmaxf(v0, v1));
                }
                mx = fmaxf(mx, __shfl_xor_sync(0xffffffffu, mx, 1));
                mx = fmaxf(mx, __shfl_xor_sync(0xffffffffu, mx, 2));
                float sm = 0.f;
                #pragma unroll
                for (int i = 0; i < 14; ++i) { pv[i] = __expf(pv[i] - mx); sm += pv[i]; }
                sm += __shfl_xor_sync(0xffffffffu, sm, 1);
                sm += __shfl_xor_sync(0xffffffffu, sm, 2);
                float inv = 1.f / sm;
                #pragma unroll
                for (int i = 0; i < 14; ++i) pv[i] *= inv;
            }

            // P5: O = P @ V; A-fragments from pv registers
            float oacc[4][4];
            #pragma unroll
            for (int t = 0; t < 4; ++t)
                #pragma unroll
                for (int j = 0; j < 4; ++j) oacc[t][j] = 0.f;

            #pragma unroll
            for (int ks = 0; ks < 4; ++ks) {
                uint ah[4], al[4];
                ah[0] = packbf(pv0[4 * ks],     pv0[4 * ks + 1], al[0]);
                ah[1] = packbf(pv1[4 * ks],     pv1[4 * ks + 1], al[1]);
                if (ks < 3) {
                    ah[2] = packbf(pv0[4 * ks + 2], pv0[4 * ks + 3], al[2]);
                    ah[3] = packbf(pv1[4 * ks + 2], pv1[4 * ks + 3], al[3]);
                } else {
                    ah[2] = 0u; ah[3] = 0u; al[2] = 0u; al[3] = 0u;
                }
                #pragma unroll
                for (int tp = 0; tp < 2; ++tp) {
                    int c = h * 32 + tp * 16 + brl2;     // V^T row = channel
                    uint boff = (uint)c * 256 + (((uint)((win * 8 + 2 * ks + bc8g) ^ (c & 7))) << 4);
                    uint bh[4], bl[4];
                    ldsm4(bh, vhA + boff);
                    ldsm4(bl, vlA + boff);
                    mma16816(oacc[2 * tp],     ah, bh[0], bh[1]);
                    mma16816(oacc[2 * tp],     ah, bl[0], bl[1]);
                    mma16816(oacc[2 * tp],     al, bh[0], bh[1]);
                    mma16816(oacc[2 * tp + 1], ah, bh[2], bh[3]);
                    mma16816(oacc[2 * tp + 1], ah, bl[2], bl[3]);
                    mma16816(oacc[2 * tp + 1], al, bh[2], bh[3]);
                }
            }
            // O epilogue -> QO region rows win*64 + n (warp-local overlay of Q)
            const int n0 = mt * 16 + g;
            #pragma unroll
            for (int nt = 0; nt < 4; ++nt) {
                int col = h * 32 + nt * 8 + 2 * tig;
                #pragma unroll
                for (int half = 0; half < 2; ++half) {
                    int n = n0 + 8 * half;
                    if (n < NTOK) {
                        int row = win * 64 + n;
                        uint lo;
                        uint hi = packbf(oacc[nt][2 * half], oacc[nt][2 * half + 1], lo);
                        uint off = (uint)row * 256 + (((uint)((col >> 3) ^ (row & 7))) << 4) + ((uint)(col & 7)) * 2;
                        *(uint*)(QOb + off) = hi;
                        *(uint*)(QOLb + off) = lo;
                    }
                }
            }
        }
    }
    __syncthreads();

    // ---------------- P6: proj GEMM (bf16 3-split), M=128, W fragments from L2 ----------------
    {
        const int mw = wg >> 1, nwg = wg & 1;
        const int arow = mw * 16 + (og & 15);
        const int ac8  = og >> 4;
        float acc[8][4];
        #pragma unroll
        for (int t = 0; t < 8; ++t)
            #pragma unroll
            for (int j = 0; j < 4; ++j) acc[t][j] = 0.f;

        const uint4* fH = g_wpf_hi + (nwg * 4) * 256 + og;
        const uint4* fL = g_wpf_lo + (nwg * 4) * 256 + og;

        #pragma unroll
        for (int ks = 0; ks < 8; ++ks) {
            uint aoff = (uint)arow * 256 + (((uint)((2 * ks + ac8) ^ (arow & 7))) << 4);
            uint ah[4], al[4];
            ldsm4(ah, qoA + aoff);
            ldsm4(al, qolA + aoff);
            #pragma unroll
            for (int tp = 0; tp < 4; ++tp) {
                uint4 bh = __ldg(fH + tp * 256 + ks * 32);
                uint4 bl = __ldg(fL + tp * 256 + ks * 32);
                mma16816(acc[2 * tp],     ah, bh.x, bh.y);
                mma16816(acc[2 * tp],     ah, bl.x, bl.y);
                mma16816(acc[2 * tp],     al, bh.x, bh.y);
                mma16816(acc[2 * tp + 1], ah, bh.z, bh.w);
                mma16816(acc[2 * tp + 1], ah, bl.z, bl.w);
                mma16816(acc[2 * tp + 1], al, bh.z, bh.w);
            }
        }
        const int n0 = mw * 16 + g;
        const int win = n0 >> 6;
        const int tok0 = n0 & 63;
        float* og_ptr = out + (size_t)(2 * blk + win) * NTOK * CDIM;
        #pragma unroll
        for (int t = 0; t < 8; ++t) {
            int o = nwg * 64 + t * 8 + tig * 2;
            float b0 = __ldg(&proj_b[o]), b1 = __ldg(&proj_b[o + 1]);
            if (tok0 < NTOK)
                *(float2*)&og_ptr[tok0 * CDIM + o] = make_float2(acc[t][0] + b0, acc[t][1] + b1);
            if (tok0 + 8 < NTOK)
                *(float2*)&og_ptr[(tok0 + 8) * CDIM + o] = make_float2(acc[t][2] + b0, acc[t][3] + b1);
        }
    }
}

extern "C" void kernel_launch(void* const* d_in, const int* in_sizes, int n_in,
                              void* d_out, int out_size)
{
    (void)in_sizes; (void)n_in; (void)out_size;
    const float* x          = (const float*)d_in[0];
    const float* mask       = (const float*)d_in[1];
    const float* qkv_w      = (const float*)d_in[2];
    const float* proj_w     = (const float*)d_in[3];
    const float* proj_b     = (const float*)d_in[4];
    const float* bias_table = (const float*)d_in[5];
    const float* alpha      = (const float*)d_in[6];
    const int*   rel_idx    = (const int*)d_in[7];
    float* out = (float*)d_out;

    int conv_elems = NFRAG_Q + NFRAG_P + HEADS * 2401;
    conv_w_kernel<<<(conv_elems + 255) / 256, 256>>>(qkv_w, proj_w, bias_table, rel_idx);

    cudaFuncSetAttribute(lpwin_attn_kernel,
                         cudaFuncAttributeMaxDynamicSharedMemorySize, SMEM_BYTES);
    lpwin_attn_kernel<<<BWIN / 2, THREADS, SMEM_BYTES>>>(
        x, mask, qkv_w, proj_w, proj_b, bias_table, alpha, rel_idx, out);
}

// round 15
// speedup vs baseline: 5.0183x; 1.0854x over previous
#include <cuda_runtime.h>
#include <cuda_bf16.h>
#include <math.h>

// Problem constants
#define BWIN 8192
#define NTOK 49
#define CDIM 128
#define HEADS 4
#define NWIN 4096
#define THREADS 512

// smem byte offsets (regions hold 128 rows x 256B = 32KB; rows = win*64 + n)
#define B_KH   0         // K^ bf16 hi
#define B_KL   32768     // K^ bf16 lo
#define B_QO   65536     // Q^ bf16 hi -> O bf16 hi (warp-local overlay)
#define B_QOL  98304     // Q^ bf16 lo -> O bf16 lo
#define B_X    131072    // X bf16 hi -> V^T bf16 hi
#define B_XLO  163840    // X bf16 lo -> V^T bf16 lo
#define B_MASK 196608    // 2 masks f32 (2*2401 floats)
#define SMEM_BYTES 215816

#define QKV_T16  24
#define PROJ_T16 8
#define NFRAG_Q  (QKV_T16 * 8 * 32)    // 6144 uint4
#define NFRAG_P  (PROJ_T16 * 8 * 32)   // 2048 uint4

typedef unsigned long long ull;
typedef unsigned int uint;
typedef unsigned short ushort;

__device__ uint4 g_wqf_hi[NFRAG_Q];
__device__ uint4 g_wqf_lo[NFRAG_Q];
__device__ uint4 g_wpf_hi[NFRAG_P];
__device__ uint4 g_wpf_lo[NFRAG_P];
__device__ float g_rpb[HEADS * 49 * 50];   // [h][n][m], row stride 50

__device__ __forceinline__ uint smem_u32(const void* p){
    uint a; asm("{ .reg .u64 t; cvta.to.shared.u64 t, %1; cvt.u32.u64 %0, t; }" : "=r"(a) : "l"(p));
    return a;
}
__device__ __forceinline__ void ldsm4(uint* r, uint addr){
    asm volatile("ldmatrix.sync.aligned.m8n8.x4.shared.b16 {%0,%1,%2,%3}, [%4];"
        : "=r"(r[0]), "=r"(r[1]), "=r"(r[2]), "=r"(r[3]) : "r"(addr));
}
__device__ __forceinline__ void ldsm2(uint &r0, uint &r1, uint addr){
    asm volatile("ldmatrix.sync.aligned.m8n8.x2.shared.b16 {%0,%1}, [%2];"
        : "=r"(r0), "=r"(r1) : "r"(addr));
}
__device__ __forceinline__ void mma16816(float* d, const uint* a, uint b0, uint b1){
    asm volatile("mma.sync.aligned.m16n8k16.row.col.f32.bf16.bf16.f32 "
        "{%0,%1,%2,%3}, {%4,%5,%6,%7}, {%8,%9}, {%0,%1,%2,%3};"
        : "+f"(d[0]), "+f"(d[1]), "+f"(d[2]), "+f"(d[3])
        : "r"(a[0]), "r"(a[1]), "r"(a[2]), "r"(a[3]), "r"(b0), "r"(b1));
}
__device__ __forceinline__ ushort bfhi(float v, float &rest){
    __nv_bfloat16 h = __float2bfloat16(v);
    rest = v - __bfloat162float(h);
    return *(ushort*)&h;
}
__device__ __forceinline__ ushort bfbits(float v){
    __nv_bfloat16 h = __float2bfloat16(v);
    return *(ushort*)&h;
}
__device__ __forceinline__ uint packbf(float a, float b, uint &lo){
    float ra, rb;
    ushort ha = bfhi(a, ra), hb = bfhi(b, rb);
    lo = ((uint)bfbits(rb) << 16) | bfbits(ra);
    return ((uint)hb << 16) | ha;
}

extern __shared__ float smem[];

__global__ void conv_w_kernel(const float* __restrict__ qkv_w,
                              const float* __restrict__ proj_w,
                              const float* __restrict__ bias_table,
                              const int*   __restrict__ rel_idx){
    int i = blockIdx.x * blockDim.x + threadIdx.x;
    if (i < NFRAG_Q + NFRAG_P) {
        bool isq = (i < NFRAG_Q);
        int idx = isq ? i : i - NFRAG_Q;
        const float* W = isq ? qkv_w : proj_w;
        int tile = idx >> 8;
        int ks   = (idx >> 5) & 7;
        int lane = idx & 31;
        int r0 = tile * 16 + (lane >> 2);
        int r1 = r0 + 8;
        int c0 = ks * 16 + 2 * (lane & 3);
        uint4 hv, lv;
        hv.x = packbf(W[r0 * 128 + c0],     W[r0 * 128 + c0 + 1], lv.x);
        hv.y = packbf(W[r0 * 128 + c0 + 8], W[r0 * 128 + c0 + 9], lv.y);
        hv.z = packbf(W[r1 * 128 + c0],     W[r1 * 128 + c0 + 1], lv.z);
        hv.w = packbf(W[r1 * 128 + c0 + 8], W[r1 * 128 + c0 + 9], lv.w);
        if (isq) { g_wqf_hi[idx] = hv; g_wqf_lo[idx] = lv; }
        else     { g_wpf_hi[idx] = hv; g_wpf_lo[idx] = lv; }
    } else if (i < NFRAG_Q + NFRAG_P + HEADS * 2401) {
        int j = i - (NFRAG_Q + NFRAG_P);
        int h = j / 2401, e = j % 2401;
        int n = e / 49, m = e % 49;
        g_rpb[h * 2450 + n * 50 + m] = bias_table[rel_idx[e] * 4 + h];
    }
}

__global__ void __launch_bounds__(THREADS, 1)
lpwin_attn_kernel(const float* __restrict__ x,
                  const float* __restrict__ mask,
                  const float* __restrict__ qkv_w,
                  const float* __restrict__ proj_w,
                  const float* __restrict__ proj_b,
                  const float* __restrict__ bias_table,
                  const float* __restrict__ alpha,
                  const int*   __restrict__ rel_idx,
                  float* __restrict__ out)
{
    char* SB = (char*)smem;

    const int tid = threadIdx.x;
    const int blk = blockIdx.x;             // window pair: windows 2*blk, 2*blk+1
    const int bw0 = (2 * blk) & (NWIN - 1);
    const int og  = tid & 31;
    const int wg  = tid >> 5;

    const uint base = smem_u32(smem);
    const uint khA = base + B_KH,  klA = base + B_KL;
    const uint qoA = base + B_QO,  qolA = base + B_QOL;
    const uint xhA = base + B_X,   xlA = base + B_XLO;
    const uint vhA = base + B_X,   vlA = base + B_XLO;

    char* KHb = SB + B_KH;  char* KLb = SB + B_KL;
    char* QOb = SB + B_QO;  char* QOLb = SB + B_QOL;
    char* XHb = SB + B_X;   char* XLb = SB + B_XLO;
    char* VHb = SB + B_X;   char* VLb = SB + B_XLO;
    float* MASK0 = (float*)(SB + B_MASK);
    float* MASK1 = MASK0 + 2401;

    // lane decomposition
    const int brl  = og & 7;
    const int bc8g = (og >> 3) & 1;
    const int brl2 = (og & 7) + ((og & 16) >> 1);
    const int g    = og >> 2, tig = og & 3;

    // ---------------- P1 + P2a: masks; x (2 windows) -> bf16 hi/lo swizzled ----------------
    {
        for (int i = tid; i < 2401; i += THREADS) MASK0[i] = mask[(size_t)bw0 * 2401 + i];
        for (int i = tid; i < 2401; i += THREADS) MASK1[i] = mask[(size_t)(bw0 + 1) * 2401 + i];

        #pragma unroll
        for (int win = 0; win < 2; ++win) {
            const float4* xg4 = (const float4*)(x + (size_t)(2 * blk + win) * NTOK * CDIM);
            for (int i = tid; i < 49 * 16; i += THREADS) {
                int n = i >> 4, c8 = i & 15;
                int row = win * 64 + n;
                float4 a = xg4[n * 32 + c8 * 2];
                float4 c = xg4[n * 32 + c8 * 2 + 1];
                float vs[8] = {a.x, a.y, a.z, a.w, c.x, c.y, c.z, c.w};
                ushort hs[8], ls[8];
                #pragma unroll
                for (int j = 0; j < 8; ++j) {
                    float rest;
                    hs[j] = bfhi(vs[j], rest);
                    ls[j] = bfbits(rest);
                }
                uint off = (uint)row * 256 + (((uint)(c8 ^ (row & 7))) << 4);
                *(uint4*)(XHb + off) = *(uint4*)hs;
                *(uint4*)(XLb + off) = *(uint4*)ls;
            }
        }
        uint4 z = make_uint4(0, 0, 0, 0);
        for (int i = tid; i < 2 * 15 * 16; i += THREADS) {
            int ni = i >> 4, c8 = i & 15;
            int win = ni / 15, n = 49 + ni % 15;
            int row = win * 64 + n;
            uint off = (uint)row * 256 + (((uint)(c8 ^ (row & 7))) << 4);
            *(uint4*)(XHb + off) = z;
            *(uint4*)(XLb + off) = z;
        }
    }
    __syncthreads();

    // ---------------- P2b: QKV GEMM (bf16 3-split), split-major mma order ----------------
    {
        const int mw = wg >> 1, nwg = wg & 1;
        const int arow = mw * 16 + (og & 15);
        const int ac8  = og >> 4;
        const int n0 = mw * 16 + g;
        float accV[8][4];

        for (int pass = 0; pass < 3; ++pass) {
            float acc[8][4];
            #pragma unroll
            for (int t = 0; t < 8; ++t)
                #pragma unroll
                for (int j = 0; j < 4; ++j) acc[t][j] = 0.f;

            const uint4* fH = g_wqf_hi + (pass * 8 + nwg * 4) * 256 + og;
            const uint4* fL = g_wqf_lo + (pass * 8 + nwg * 4) * 256 + og;

            #pragma unroll
            for (int ks = 0; ks < 8; ++ks) {
                uint aoff = (uint)arow * 256 + (((uint)((2 * ks + ac8) ^ (arow & 7))) << 4);
                uint ah[4], al[4];
                ldsm4(ah, xhA + aoff);
                ldsm4(al, xlA + aoff);
                uint4 bh[4], bl[4];
                #pragma unroll
                for (int tp = 0; tp < 4; ++tp) {
                    bh[tp] = __ldg(fH + tp * 256 + ks * 32);
                    bl[tp] = __ldg(fL + tp * 256 + ks * 32);
                }
                // split-major: all hi*hi, then hi*lo, then lo*hi (RAW distance 8)
                #pragma unroll
                for (int tp = 0; tp < 4; ++tp) {
                    mma16816(acc[2 * tp],     ah, bh[tp].x, bh[tp].y);
                    mma16816(acc[2 * tp + 1], ah, bh[tp].z, bh[tp].w);
                }
                #pragma unroll
                for (int tp = 0; tp < 4; ++tp) {
                    mma16816(acc[2 * tp],     ah, bl[tp].x, bl[tp].y);
                    mma16816(acc[2 * tp + 1], ah, bl[tp].z, bl[tp].w);
                }
                #pragma unroll
                for (int tp = 0; tp < 4; ++tp) {
                    mma16816(acc[2 * tp],     al, bh[tp].x, bh[tp].y);
                    mma16816(acc[2 * tp + 1], al, bh[tp].z, bh[tp].w);
                }
            }

            if (pass < 2) {
                // fused epilogue: L2-normalize; warp covers 2 heads (nwg*2+hh)
                char* Hb = (pass == 0) ? QOb : KHb;
                char* Lb = (pass == 0) ? QOLb : KLb;
                #pragma unroll
                for (int hh = 0; hh < 2; ++hh) {
                    float ss0 = 0.f, ss1 = 0.f;
                    #pragma unroll
                    for (int tt = 0; tt < 4; ++tt) {
                        int t = hh * 4 + tt;
                        ss0 += acc[t][0] * acc[t][0] + acc[t][1] * acc[t][1];
                        ss1 += acc[t][2] * acc[t][2] + acc[t][3] * acc[t][3];
                    }
                    ss0 += __shfl_xor_sync(0xffffffffu, ss0, 1);
                    ss0 += __shfl_xor_sync(0xffffffffu, ss0, 2);
                    ss1 += __shfl_xor_sync(0xffffffffu, ss1, 1);
                    ss1 += __shfl_xor_sync(0xffffffffu, ss1, 2);
                    float sc = (pass == 0) ? __ldg(&alpha[nwg * 2 + hh]) : 1.f;
                    float inv0 = sc / (sqrtf(ss0) + 1e-6f);
                    float inv1 = sc / (sqrtf(ss1) + 1e-6f);
                    #pragma unroll
                    for (int tt = 0; tt < 4; ++tt) {
                        int t = hh * 4 + tt;
                        int col = nwg * 64 + t * 8 + 2 * tig;
                        int c8 = col >> 3;
                        uint lo0, lo1;
                        uint h0 = packbf(acc[t][0] * inv0, acc[t][1] * inv0, lo0);
                        uint off0 = (uint)n0 * 256 + (((uint)(c8 ^ (n0 & 7))) << 4) + ((uint)(col & 7)) * 2;
                        *(uint*)(Hb + off0) = h0;
                        *(uint*)(Lb + off0) = lo0;
                        int n1 = n0 + 8;
                        uint h1 = packbf(acc[t][2] * inv1, acc[t][3] * inv1, lo1);
                        uint off1 = (uint)n1 * 256 + (((uint)(c8 ^ (n1 & 7))) << 4) + ((uint)(col & 7)) * 2;
                        *(uint*)(Hb + off1) = h1;
                        *(uint*)(Lb + off1) = lo1;
                    }
                }
            } else {
                #pragma unroll
                for (int t = 0; t < 8; ++t)
                    #pragma unroll
                    for (int j = 0; j < 4; ++j) accV[t][j] = acc[t][j];
            }
        }
        __syncthreads();   // all warps done reading X before V^T overwrite

        // fused epilogue: V^T bf16 (rows = channel 0..127, cols = global row 0..127)
        #pragma unroll
        for (int t = 0; t < 8; ++t) {
            #pragma unroll
            for (int j = 0; j < 2; ++j) {
                int c = nwg * 64 + t * 8 + 2 * tig + j;
                #pragma unroll
                for (int half = 0; half < 2; ++half) {
                    int row = n0 + 8 * half;
                    float v = accV[t][2 * half + j];
                    float rest;
                    ushort hv = bfhi(v, rest);
                    uint off = (uint)c * 256 + (((uint)((row >> 3) ^ (c & 7))) << 4) + ((uint)(row & 7)) * 2;
                    *(ushort*)(VHb + off) = hv;
                    *(ushort*)(VLb + off) = bfbits(rest);
                }
            }
        }
    }
    __syncthreads();

    // ---------------- P4+P5 fused, per warp: (win, head, mt-pair), split-major mma ----------------
    {
        const int win = wg >> 3, h = (wg >> 1) & 3, mtp = wg & 1;
        const float* rpbh = g_rpb + h * 2450;
        const float* MW = win ? MASK1 : MASK0;
        const int ac8 = og >> 4;

        #pragma unroll 1
        for (int uu = 0; uu < 2; ++uu) {
            const int mt = mtp + 2 * uu;
            const int arow = win * 64 + mt * 16 + (og & 15);
            float acc[7][4];
            #pragma unroll
            for (int t = 0; t < 7; ++t)
                #pragma unroll
                for (int j = 0; j < 4; ++j) acc[t][j] = 0.f;

            #pragma unroll
            for (int ks = 0; ks < 2; ++ks) {
                uint aoff = (uint)arow * 256 + (((uint)((h * 4 + 2 * ks + ac8) ^ (arow & 7))) << 4);
                uint ah[4], al[4];
                ldsm4(ah, qoA + aoff);
                ldsm4(al, qolA + aoff);
                uint bh[3][4], bl[3][4];
                uint bh6a, bh6b, bl6a, bl6b;
                #pragma unroll
                for (int p = 0; p < 3; ++p) {
                    int krow = win * 64 + p * 16 + brl2;
                    uint boff = (uint)krow * 256 + (((uint)((h * 4 + 2 * ks + bc8g) ^ (krow & 7))) << 4);
                    ldsm4(bh[p], khA + boff);
                    ldsm4(bl[p], klA + boff);
                }
                {
                    int krow = win * 64 + 48 + brl;   // K rows 49..55 exact zeros
                    uint boff = (uint)krow * 256 + (((uint)((h * 4 + 2 * ks + bc8g) ^ (krow & 7))) << 4);
                    ldsm2(bh6a, bh6b, khA + boff);
                    ldsm2(bl6a, bl6b, klA + boff);
                }
                // split-major across 7 accumulators
                #pragma unroll
                for (int p = 0; p < 3; ++p) {
                    mma16816(acc[2 * p],     ah, bh[p][0], bh[p][1]);
                    mma16816(acc[2 * p + 1], ah, bh[p][2], bh[p][3]);
                }
                mma16816(acc[6], ah, bh6a, bh6b);
                #pragma unroll
                for (int p = 0; p < 3; ++p) {
                    mma16816(acc[2 * p],     ah, bl[p][0], bl[p][1]);
                    mma16816(acc[2 * p + 1], ah, bl[p][2], bl[p][3]);
                }
                mma16816(acc[6], ah, bl6a, bl6b);
                #pragma unroll
                for (int p = 0; p < 3; ++p) {
                    mma16816(acc[2 * p],     al, bh[p][0], bh[p][1]);
                    mma16816(acc[2 * p + 1], al, bh[p][2], bh[p][3]);
                }
                mma16816(acc[6], al, bh6a, bh6b);
            }

            // register softmax
            float pv0[14], pv1[14];
            #pragma unroll
            for (int half = 0; half < 2; ++half) {
                int r = mt * 16 + g + 8 * half;
                int nr = (r < NTOK) ? r : 0;
                float* pv = half ? pv1 : pv0;
                float mx = -1e30f;
                #pragma unroll
                for (int nt = 0; nt < 7; ++nt) {
                    int m0 = nt * 8 + 2 * tig;
                    float v0 = acc[nt][2 * half], v1 = acc[nt][2 * half + 1];
                    if (m0 < NTOK) {
                        float2 rp = *(const float2*)&rpbh[nr * 50 + m0];
                        v0 += rp.x + MW[nr * 49 + m0];
                        v1 = (m0 + 1 < NTOK) ? (v1 + rp.y + MW[nr * 49 + m0 + 1]) : -1e30f;
                    } else { v0 = -1e30f; v1 = -1e30f; }
                    pv[2 * nt] = v0; pv[2 * nt + 1] = v1;
                    mx = fmaxf(mx, fmaxf(v0, v1));
                }
                mx = fmaxf(mx, __shfl_xor_sync(0xffffffffu, mx, 1));
                mx = fmaxf(mx, __shfl_xor_sync(0xffffffffu, mx, 2));
                float sm = 0.f;
                #pragma unroll
                for (int i = 0; i < 14; ++i) { pv[i] = __expf(pv[i] - mx); sm += pv[i]; }
                sm += __shfl_xor_sync(0xffffffffu, sm, 1);
                sm += __shfl_xor_sync(0xffffffffu, sm, 2);
                float inv = 1.f / sm;
                #pragma unroll
                for (int i = 0; i < 14; ++i) pv[i] *= inv;
            }

            // P5: O = P @ V; A-fragments from pv registers; split-major
            float oacc[4][4];
            #pragma unroll
            for (int t = 0; t < 4; ++t)
                #pragma unroll
                for (int j = 0; j < 4; ++j) oacc[t][j] = 0.f;

            #pragma unroll
            for (int ks = 0; ks < 4; ++ks) {
                uint ah[4], al[4];
                ah[0] = packbf(pv0[4 * ks],     pv0[4 * ks + 1], al[0]);
                ah[1] = packbf(pv1[4 * ks],     pv1[4 * ks + 1], al[1]);
                if (ks < 3) {
                    ah[2] = packbf(pv0[4 * ks + 2], pv0[4 * ks + 3], al[2]);
                    ah[3] = packbf(pv1[4 * ks + 2], pv1[4 * ks + 3], al[3]);
                } else {
                    ah[2] = 0u; ah[3] = 0u; al[2] = 0u; al[3] = 0u;
                }
                uint bh[2][4], bl[2][4];
                #pragma unroll
                for (int tp = 0; tp < 2; ++tp) {
                    int c = h * 32 + tp * 16 + brl2;
                    uint boff = (uint)c * 256 + (((uint)((win * 8 + 2 * ks + bc8g) ^ (c & 7))) << 4);
                    ldsm4(bh[tp], vhA + boff);
                    ldsm4(bl[tp], vlA + boff);
                }
                #pragma unroll
                for (int tp = 0; tp < 2; ++tp) {
                    mma16816(oacc[2 * tp],     ah, bh[tp][0], bh[tp][1]);
                    mma16816(oacc[2 * tp + 1], ah, bh[tp][2], bh[tp][3]);
                }
                #pragma unroll
                for (int tp = 0; tp < 2; ++tp) {
                    mma16816(oacc[2 * tp],     ah, bl[tp][0], bl[tp][1]);
                    mma16816(oacc[2 * tp + 1], ah, bl[tp][2], bl[tp][3]);
                }
                #pragma unroll
                for (int tp = 0; tp < 2; ++tp) {
                    mma16816(oacc[2 * tp],     al, bh[tp][0], bh[tp][1]);
                    mma16816(oacc[2 * tp + 1], al, bh[tp][2], bh[tp][3]);
                }
            }
            // O epilogue -> QO region rows win*64 + n (warp-local overlay of Q)
            const int n0 = mt * 16 + g;
            #pragma unroll
            for (int nt = 0; nt < 4; ++nt) {
                int col = h * 32 + nt * 8 + 2 * tig;
                #pragma unroll
                for (int half = 0; half < 2; ++half) {
                    int n = n0 + 8 * half;
                    if (n < NTOK) {
                        int row = win * 64 + n;
                        uint lo;
                        uint hi = packbf(oacc[nt][2 * half], oacc[nt][2 * half + 1], lo);
                        uint off = (uint)row * 256 + (((uint)((col >> 3) ^ (row & 7))) << 4) + ((uint)(col & 7)) * 2;
                        *(uint*)(QOb + off) = hi;
                        *(uint*)(QOLb + off) = lo;
                    }
                }
            }
        }
    }
    __syncthreads();

    // ---------------- P6: proj GEMM (bf16 3-split), split-major mma order ----------------
    {
        const int mw = wg >> 1, nwg = wg & 1;
        const int arow = mw * 16 + (og & 15);
        const int ac8  = og >> 4;
        float acc[8][4];
        #pragma unroll
        for (int t = 0; t < 8; ++t)
            #pragma unroll
            for (int j = 0; j < 4; ++j) acc[t][j] = 0.f;

        const uint4* fH = g_wpf_hi + (nwg * 4) * 256 + og;
        const uint4* fL = g_wpf_lo + (nwg * 4) * 256 + og;

        #pragma unroll
        for (int ks = 0; ks < 8; ++ks) {
            uint aoff = (uint)arow * 256 + (((uint)((2 * ks + ac8) ^ (arow & 7))) << 4);
            uint ah[4], al[4];
            ldsm4(ah, qoA + aoff);
            ldsm4(al, qolA + aoff);
            uint4 bh[4], bl[4];
            #pragma unroll
            for (int tp = 0; tp < 4; ++tp) {
                bh[tp] = __ldg(fH + tp * 256 + ks * 32);
                bl[tp] = __ldg(fL + tp * 256 + ks * 32);
            }
            #pragma unroll
            for (int tp = 0; tp < 4; ++tp) {
                mma16816(acc[2 * tp],     ah, bh[tp].x, bh[tp].y);
                mma16816(acc[2 * tp + 1], ah, bh[tp].z, bh[tp].w);
            }
            #pragma unroll
            for (int tp = 0; tp < 4; ++tp) {
                mma16816(acc[2 * tp],     ah, bl[tp].x, bl[tp].y);
                mma16816(acc[2 * tp + 1], ah, bl[tp].z, bl[tp].w);
            }
            #pragma unroll
            for (int tp = 0; tp < 4; ++tp) {
                mma16816(acc[2 * tp],     al, bh[tp].x, bh[tp].y);
                mma16816(acc[2 * tp + 1], al, bh[tp].z, bh[tp].w);
            }
        }
        const int n0 = mw * 16 + g;
        const int win = n0 >> 6;
        const int tok0 = n0 & 63;
        float* og_ptr = out + (size_t)(2 * blk + win) * NTOK * CDIM;
        #pragma unroll
        for (int t = 0; t < 8; ++t) {
            int o = nwg * 64 + t * 8 + tig * 2;
            float b0 = __ldg(&proj_b[o]), b1 = __ldg(&proj_b[o + 1]);
            if (tok0 < NTOK)
                *(float2*)&og_ptr[tok0 * CDIM + o] = make_float2(acc[t][0] + b0, acc[t][1] + b1);
            if (tok0 + 8 < NTOK)
                *(float2*)&og_ptr[(tok0 + 8) * CDIM + o] = make_float2(acc[t][2] + b0, acc[t][3] + b1);
        }
    }
}

extern "C" void kernel_launch(void* const* d_in, const int* in_sizes, int n_in,
                              void* d_out, int out_size)
{
    (void)in_sizes; (void)n_in; (void)out_size;
    const float* x          = (const float*)d_in[0];
    const float* mask       = (const float*)d_in[1];
    const float* qkv_w      = (const float*)d_in[2];
    const float* proj_w     = (const float*)d_in[3];
    const float* proj_b     = (const float*)d_in[4];
    const float* bias_table = (const float*)d_in[5];
    const float* alpha      = (const float*)d_in[6];
    const int*   rel_idx    = (const int*)d_in[7];
    float* out = (float*)d_out;

    int conv_elems = NFRAG_Q + NFRAG_P + HEADS * 2401;
    conv_w_kernel<<<(conv_elems + 255) / 256, 256>>>(qkv_w, proj_w, bias_table, rel_idx);

    cudaFuncSetAttribute(lpwin_attn_kernel,
                         cudaFuncAttributeMaxDynamicSharedMemorySize, SMEM_BYTES);
    lpwin_attn_kernel<<<BWIN / 2, THREADS, SMEM_BYTES>>>(
        x, mask, qkv_w, proj_w, proj_b, bias_table, alpha, rel_idx, out);
}

// round 16
// speedup vs baseline: 5.8071x; 1.1572x over previous
#include <cuda_runtime.h>
#include <cuda_bf16.h>
#include <math.h>

// Problem constants
#define BWIN 8192
#define NTOK 49
#define CDIM 128
#define HEADS 4
#define NWIN 4096
#define THREADS 256

// smem byte offsets (regions: 64 rows x 256B = 16KB)
#define B_KH   0         // K^ bf16 hi
#define B_KL   16384     // K^ bf16 lo
#define B_QO   32768     // Q^ bf16 hi -> O bf16 hi (warp-local overlay)
#define B_QOL  49152     // Q^ bf16 lo -> O bf16 lo
#define B_X    65536     // X bf16 hi -> V^T bf16 hi
#define B_XLO  81920     // X bf16 lo -> V^T bf16 lo
#define B_MASK 98304     // mask f32 (2401 floats)
#define SMEM_BYTES 107908

#define QKV_T16  24
#define PROJ_T16 8
#define NFRAG_Q  (QKV_T16 * 8 * 32)    // 6144 uint4
#define NFRAG_P  (PROJ_T16 * 8 * 32)   // 2048 uint4

typedef unsigned long long ull;
typedef unsigned int uint;
typedef unsigned short ushort;

__device__ uint4 g_wqf_hi[NFRAG_Q];
__device__ uint4 g_wqf_lo[NFRAG_Q];
__device__ uint4 g_wpf_hi[NFRAG_P];
__device__ uint4 g_wpf_lo[NFRAG_P];
__device__ float g_rpb[HEADS * 49 * 50];   // [h][n][m], row stride 50

__device__ __forceinline__ uint smem_u32(const void* p){
    uint a; asm("{ .reg .u64 t; cvta.to.shared.u64 t, %1; cvt.u32.u64 %0, t; }" : "=r"(a) : "l"(p));
    return a;
}
__device__ __forceinline__ void ldsm4(uint* r, uint addr){
    asm volatile("ldmatrix.sync.aligned.m8n8.x4.shared.b16 {%0,%1,%2,%3}, [%4];"
        : "=r"(r[0]), "=r"(r[1]), "=r"(r[2]), "=r"(r[3]) : "r"(addr));
}
__device__ __forceinline__ void ldsm2(uint &r0, uint &r1, uint addr){
    asm volatile("ldmatrix.sync.aligned.m8n8.x2.shared.b16 {%0,%1}, [%2];"
        : "=r"(r0), "=r"(r1) : "r"(addr));
}
__device__ __forceinline__ void mma16816(float* d, const uint* a, uint b0, uint b1){
    asm volatile("mma.sync.aligned.m16n8k16.row.col.f32.bf16.bf16.f32 "
        "{%0,%1,%2,%3}, {%4,%5,%6,%7}, {%8,%9}, {%0,%1,%2,%3};"
        : "+f"(d[0]), "+f"(d[1]), "+f"(d[2]), "+f"(d[3])
        : "r"(a[0]), "r"(a[1]), "r"(a[2]), "r"(a[3]), "r"(b0), "r"(b1));
}
__device__ __forceinline__ ushort bfhi(float v, float &rest){
    __nv_bfloat16 h = __float2bfloat16(v);
    rest = v - __bfloat162float(h);
    return *(ushort*)&h;
}
__device__ __forceinline__ ushort bfbits(float v){
    __nv_bfloat16 h = __float2bfloat16(v);
    return *(ushort*)&h;
}
__device__ __forceinline__ uint packbf(float a, float b, uint &lo){
    float ra, rb;
    ushort ha = bfhi(a, ra), hb = bfhi(b, rb);
    lo = ((uint)bfbits(rb) << 16) | bfbits(ra);
    return ((uint)hb << 16) | ha;
}

extern __shared__ float smem[];

__global__ void conv_w_kernel(const float* __restrict__ qkv_w,
                              const float* __restrict__ proj_w,
                              const float* __restrict__ bias_table,
                              const int*   __restrict__ rel_idx){
    int i = blockIdx.x * blockDim.x + threadIdx.x;
    if (i < NFRAG_Q + NFRAG_P) {
        bool isq = (i < NFRAG_Q);
        int idx = isq ? i : i - NFRAG_Q;
        const float* W = isq ? qkv_w : proj_w;
        int tile = idx >> 8;
        int ks   = (idx >> 5) & 7;
        int lane = idx & 31;
        int r0 = tile * 16 + (lane >> 2);
        int r1 = r0 + 8;
        int c0 = ks * 16 + 2 * (lane & 3);
        uint4 hv, lv;
        hv.x = packbf(W[r0 * 128 + c0],     W[r0 * 128 + c0 + 1], lv.x);
        hv.y = packbf(W[r0 * 128 + c0 + 8], W[r0 * 128 + c0 + 9], lv.y);
        hv.z = packbf(W[r1 * 128 + c0],     W[r1 * 128 + c0 + 1], lv.z);
        hv.w = packbf(W[r1 * 128 + c0 + 8], W[r1 * 128 + c0 + 9], lv.w);
        if (isq) { g_wqf_hi[idx] = hv; g_wqf_lo[idx] = lv; }
        else     { g_wpf_hi[idx] = hv; g_wpf_lo[idx] = lv; }
    } else if (i < NFRAG_Q + NFRAG_P + HEADS * 2401) {
        int j = i - (NFRAG_Q + NFRAG_P);
        int h = j / 2401, e = j % 2401;
        int n = e / 49, m = e % 49;
        g_rpb[h * 2450 + n * 50 + m] = bias_table[rel_idx[e] * 4 + h];
    }
}

__global__ void __launch_bounds__(THREADS, 2)
lpwin_attn_kernel(const float* __restrict__ x,
                  const float* __restrict__ mask,
                  const float* __restrict__ qkv_w,
                  const float* __restrict__ proj_w,
                  const float* __restrict__ proj_b,
                  const float* __restrict__ bias_table,
                  const float* __restrict__ alpha,
                  const int*   __restrict__ rel_idx,
                  float* __restrict__ out)
{
    char* SB = (char*)smem;
    float* MASKS = (float*)(SB + B_MASK);

    const int tid = threadIdx.x;
    const int b   = blockIdx.x;
    const int w   = b & (NWIN - 1);
    const int og  = tid & 31;
    const int wg  = tid >> 5;          // 0..7

    const uint base = smem_u32(smem);
    const uint khA = base + B_KH,  klA = base + B_KL;
    const uint qoA = base + B_QO,  qolA = base + B_QOL;
    const uint xhA = base + B_X,   xlA = base + B_XLO;
    const uint vhA = base + B_X,   vlA = base + B_XLO;

    char* KHb = SB + B_KH;  char* KLb = SB + B_KL;
    char* QOb = SB + B_QO;  char* QOLb = SB + B_QOL;
    char* XHb = SB + B_X;   char* XLb = SB + B_XLO;
    char* VHb = SB + B_X;   char* VLb = SB + B_XLO;

    // lane decomposition
    const int brl  = og & 7;
    const int bc8g = (og >> 3) & 1;
    const int brl2 = (og & 7) + ((og & 16) >> 1);
    const int g    = og >> 2, tig = og & 3;

    // ---------------- P1 + P2a: mask; x -> bf16 hi/lo swizzled ----------------
    {
        const float* mg = mask + (size_t)w * 2401;
        for (int i = tid; i < 2401; i += THREADS) MASKS[i] = mg[i];

        const float4* xg4 = (const float4*)(x + (size_t)b * NTOK * CDIM);
        for (int i = tid; i < 49 * 16; i += THREADS) {
            int n = i >> 4, c8 = i & 15;
            float4 a = xg4[n * 32 + c8 * 2];
            float4 c = xg4[n * 32 + c8 * 2 + 1];
            float vs[8] = {a.x, a.y, a.z, a.w, c.x, c.y, c.z, c.w};
            ushort hs[8], ls[8];
            #pragma unroll
            for (int j = 0; j < 8; ++j) {
                float rest;
                hs[j] = bfhi(vs[j], rest);
                ls[j] = bfbits(rest);
            }
            uint off = (uint)n * 256 + (((uint)(c8 ^ (n & 7))) << 4);
            *(uint4*)(XHb + off) = *(uint4*)hs;
            *(uint4*)(XLb + off) = *(uint4*)ls;
        }
        uint4 z = make_uint4(0, 0, 0, 0);
        for (int i = tid; i < 15 * 16; i += THREADS) {
            int n = 49 + (i >> 4), c8 = i & 15;
            uint off = (uint)n * 256 + (((uint)(c8 ^ (n & 7))) << 4);
            *(uint4*)(XHb + off) = z;
            *(uint4*)(XLb + off) = z;
        }
    }
    __syncthreads();

    // ---------------- P2b: QKV GEMM (bf16 3-split), split-major, W fragments from L2 ----------------
    {
        const int mw = wg >> 1, nwg = wg & 1;    // 4 m-tiles x 2 n-halves (192 each... cols nwg*64 per pass half)
        const int arow = mw * 16 + (og & 15);
        const int ac8  = og >> 4;
        const int n0 = mw * 16 + g;
        float accV[8][4];

        for (int pass = 0; pass < 3; ++pass) {
            float acc[8][4];
            #pragma unroll
            for (int t = 0; t < 8; ++t)
                #pragma unroll
                for (int j = 0; j < 4; ++j) acc[t][j] = 0.f;

            const uint4* fH = g_wqf_hi + (pass * 8 + nwg * 4) * 256 + og;
            const uint4* fL = g_wqf_lo + (pass * 8 + nwg * 4) * 256 + og;

            #pragma unroll
            for (int ks = 0; ks < 8; ++ks) {
                uint aoff = (uint)arow * 256 + (((uint)((2 * ks + ac8) ^ (arow & 7))) << 4);
                uint ah[4], al[4];
                ldsm4(ah, xhA + aoff);
                ldsm4(al, xlA + aoff);
                uint4 bh[4], bl[4];
                #pragma unroll
                for (int tp = 0; tp < 4; ++tp) {
                    bh[tp] = __ldg(fH + tp * 256 + ks * 32);
                    bl[tp] = __ldg(fL + tp * 256 + ks * 32);
                }
                #pragma unroll
                for (int tp = 0; tp < 4; ++tp) {
                    mma16816(acc[2 * tp],     ah, bh[tp].x, bh[tp].y);
                    mma16816(acc[2 * tp + 1], ah, bh[tp].z, bh[tp].w);
                }
                #pragma unroll
                for (int tp = 0; tp < 4; ++tp) {
                    mma16816(acc[2 * tp],     ah, bl[tp].x, bl[tp].y);
                    mma16816(acc[2 * tp + 1], ah, bl[tp].z, bl[tp].w);
                }
                #pragma unroll
                for (int tp = 0; tp < 4; ++tp) {
                    mma16816(acc[2 * tp],     al, bh[tp].x, bh[tp].y);
                    mma16816(acc[2 * tp + 1], al, bh[tp].z, bh[tp].w);
                }
            }

            if (pass < 2) {
                // fused epilogue: L2-normalize; warp covers 2 heads (nwg*2+hh)
                char* Hb = (pass == 0) ? QOb : KHb;
                char* Lb = (pass == 0) ? QOLb : KLb;
                #pragma unroll
                for (int hh = 0; hh < 2; ++hh) {
                    float ss0 = 0.f, ss1 = 0.f;
                    #pragma unroll
                    for (int tt = 0; tt < 4; ++tt) {
                        int t = hh * 4 + tt;
                        ss0 += acc[t][0] * acc[t][0] + acc[t][1] * acc[t][1];
                        ss1 += acc[t][2] * acc[t][2] + acc[t][3] * acc[t][3];
                    }
                    ss0 += __shfl_xor_sync(0xffffffffu, ss0, 1);
                    ss0 += __shfl_xor_sync(0xffffffffu, ss0, 2);
                    ss1 += __shfl_xor_sync(0xffffffffu, ss1, 1);
                    ss1 += __shfl_xor_sync(0xffffffffu, ss1, 2);
                    float sc = (pass == 0) ? __ldg(&alpha[nwg * 2 + hh]) : 1.f;
                    float inv0 = sc / (sqrtf(ss0) + 1e-6f);
                    float inv1 = sc / (sqrtf(ss1) + 1e-6f);
                    #pragma unroll
                    for (int tt = 0; tt < 4; ++tt) {
                        int t = hh * 4 + tt;
                        int col = nwg * 64 + t * 8 + 2 * tig;
                        int c8 = col >> 3;
                        uint lo0, lo1;
                        uint h0 = packbf(acc[t][0] * inv0, acc[t][1] * inv0, lo0);
                        uint off0 = (uint)n0 * 256 + (((uint)(c8 ^ (n0 & 7))) << 4) + ((uint)(col & 7)) * 2;
                        *(uint*)(Hb + off0) = h0;
                        *(uint*)(Lb + off0) = lo0;
                        int n1 = n0 + 8;
                        uint h1 = packbf(acc[t][2] * inv1, acc[t][3] * inv1, lo1);
                        uint off1 = (uint)n1 * 256 + (((uint)(c8 ^ (n1 & 7))) << 4) + ((uint)(col & 7)) * 2;
                        *(uint*)(Hb + off1) = h1;
                        *(uint*)(Lb + off1) = lo1;
                    }
                }
            } else {
                #pragma unroll
                for (int t = 0; t < 8; ++t)
                    #pragma unroll
                    for (int j = 0; j < 4; ++j) accV[t][j] = acc[t][j];
            }
        }
        __syncthreads();   // all warps done reading X before V^T overwrite

        // fused epilogue: V^T bf16 (rows = channel 0..127 x 128B, cols = token)
        #pragma unroll
        for (int t = 0; t < 8; ++t) {
            #pragma unroll
            for (int j = 0; j < 2; ++j) {
                int c = nwg * 64 + t * 8 + 2 * tig + j;
                #pragma unroll
                for (int half = 0; half < 2; ++half) {
                    int m = n0 + 8 * half;    // token (pads exact zero)
                    float v = accV[t][2 * half + j];
                    float rest;
                    ushort hv = bfhi(v, rest);
                    uint off = (uint)c * 128 + (((uint)((m >> 3) ^ (c & 7))) << 4) + ((uint)(m & 7)) * 2;
                    *(ushort*)(VHb + off) = hv;
                    *(ushort*)(VLb + off) = bfbits(rest);
                }
            }
        }
    }
    __syncthreads();

    // ---------------- P4+P5 fused, per warp: (head, mt-pair), 2 sequential units ----------------
    {
        const int h = wg >> 1, mtp = wg & 1;
        const float* rpbh = g_rpb + h * 2450;
        const int ac8 = og >> 4;

        #pragma unroll 1
        for (int uu = 0; uu < 2; ++uu) {
            const int mt = mtp + 2 * uu;
            const int arow = mt * 16 + (og & 15);
            float acc[7][4];
            #pragma unroll
            for (int t = 0; t < 7; ++t)
                #pragma unroll
                for (int j = 0; j < 4; ++j) acc[t][j] = 0.f;

            #pragma unroll
            for (int ks = 0; ks < 2; ++ks) {
                uint aoff = (uint)arow * 256 + (((uint)((h * 4 + 2 * ks + ac8) ^ (arow & 7))) << 4);
                uint ah[4], al[4];
                ldsm4(ah, qoA + aoff);
                ldsm4(al, qolA + aoff);
                uint bh[3][4], bl[3][4];
                uint bh6a, bh6b, bl6a, bl6b;
                #pragma unroll
                for (int p = 0; p < 3; ++p) {
                    int krow = p * 16 + brl2;
                    uint boff = (uint)krow * 256 + (((uint)((h * 4 + 2 * ks + bc8g) ^ (krow & 7))) << 4);
                    ldsm4(bh[p], khA + boff);
                    ldsm4(bl[p], klA + boff);
                }
                {
                    int krow = 48 + brl;   // K rows 49..55 exact zeros
                    uint boff = (uint)krow * 256 + (((uint)((h * 4 + 2 * ks + bc8g) ^ (krow & 7))) << 4);
                    ldsm2(bh6a, bh6b, khA + boff);
                    ldsm2(bl6a, bl6b, klA + boff);
                }
                #pragma unroll
                for (int p = 0; p < 3; ++p) {
                    mma16816(acc[2 * p],     ah, bh[p][0], bh[p][1]);
                    mma16816(acc[2 * p + 1], ah, bh[p][2], bh[p][3]);
                }
                mma16816(acc[6], ah, bh6a, bh6b);
                #pragma unroll
                for (int p = 0; p < 3; ++p) {
                    mma16816(acc[2 * p],     ah, bl[p][0], bl[p][1]);
                    mma16816(acc[2 * p + 1], ah, bl[p][2], bl[p][3]);
                }
                mma16816(acc[6], ah, bl6a, bl6b);
                #pragma unroll
                for (int p = 0; p < 3; ++p) {
                    mma16816(acc[2 * p],     al, bh[p][0], bh[p][1]);
                    mma16816(acc[2 * p + 1], al, bh[p][2], bh[p][3]);
                }
                mma16816(acc[6], al, bh6a, bh6b);
            }

            // register softmax
            float pv0[14], pv1[14];
            #pragma unroll
            for (int half = 0; half < 2; ++half) {
                int r = mt * 16 + g + 8 * half;
                int nr = (r < NTOK) ? r : 0;
                float* pv = half ? pv1 : pv0;
                float mx = -1e30f;
                #pragma unroll
                for (int nt = 0; nt < 7; ++nt) {
                    int m0 = nt * 8 + 2 * tig;
                    float v0 = acc[nt][2 * half], v1 = acc[nt][2 * half + 1];
                    if (m0 < NTOK) {
                        float2 rp = *(const float2*)&rpbh[nr * 50 + m0];
                        v0 += rp.x + MASKS[nr * 49 + m0];
                        v1 = (m0 + 1 < NTOK) ? (v1 + rp.y + MASKS[nr * 49 + m0 + 1]) : -1e30f;
                    } else { v0 = -1e30f; v1 = -1e30f; }
                    pv[2 * nt] = v0; pv[2 * nt + 1] = v1;
                    mx = fmaxf(mx, fmaxf(v0, v1));
                }
                mx = fmaxf(mx, __shfl_xor_sync(0xffffffffu, mx, 1));
                mx = fmaxf(mx, __shfl_xor_sync(0xffffffffu, mx, 2));
                float sm = 0.f;
                #pragma unroll
                for (int i = 0; i < 14; ++i) { pv[i] = __expf(pv[i] - mx); sm += pv[i]; }
                sm += __shfl_xor_sync(0xffffffffu, sm, 1);
                sm += __shfl_xor_sync(0xffffffffu, sm, 2);
                float inv = 1.f / sm;
                #pragma unroll
                for (int i = 0; i < 14; ++i) pv[i] *= inv;
            }

            // P5: O = P @ V; A-fragments from pv registers; split-major
            float oacc[4][4];
            #pragma unroll
            for (int t = 0; t < 4; ++t)
                #pragma unroll
                for (int j = 0; j < 4; ++j) oacc[t][j] = 0.f;

            #pragma unroll
            for (int ks = 0; ks < 4; ++ks) {
                uint ah[4], al[4];
                ah[0] = packbf(pv0[4 * ks],     pv0[4 * ks + 1], al[0]);
                ah[1] = packbf(pv1[4 * ks],     pv1[4 * ks + 1], al[1]);
                if (ks < 3) {
                    ah[2] = packbf(pv0[4 * ks + 2], pv0[4 * ks + 3], al[2]);
                    ah[3] = packbf(pv1[4 * ks + 2], pv1[4 * ks + 3], al[3]);
                } else {
                    ah[2] = 0u; ah[3] = 0u; al[2] = 0u; al[3] = 0u;
                }
                uint bh[2][4], bl[2][4];
                #pragma unroll
                for (int tp = 0; tp < 2; ++tp) {
                    int c = h * 32 + tp * 16 + brl2;
                    uint boff = (uint)c * 128 + (((uint)((2 * ks + bc8g) ^ (c & 7))) << 4);
                    ldsm4(bh[tp], vhA + boff);
                    ldsm4(bl[tp], vlA + boff);
                }
                #pragma unroll
                for (int tp = 0; tp < 2; ++tp) {
                    mma16816(oacc[2 * tp],     ah, bh[tp][0], bh[tp][1]);
                    mma16816(oacc[2 * tp + 1], ah, bh[tp][2], bh[tp][3]);
                }
                #pragma unroll
                for (int tp = 0; tp < 2; ++tp) {
                    mma16816(oacc[2 * tp],     ah, bl[tp][0], bl[tp][1]);
                    mma16816(oacc[2 * tp + 1], ah, bl[tp][2], bl[tp][3]);
                }
                #pragma unroll
                for (int tp = 0; tp < 2; ++tp) {
                    mma16816(oacc[2 * tp],     al, bh[tp][0], bh[tp][1]);
                    mma16816(oacc[2 * tp + 1], al, bh[tp][2], bh[tp][3]);
                }
            }
            // O epilogue -> QO region (warp-local overlay of Q)
            const int n0 = mt * 16 + g;
            #pragma unroll
            for (int nt = 0; nt < 4; ++nt) {
                int col = h * 32 + nt * 8 + 2 * tig;
                #pragma unroll
                for (int half = 0; half < 2; ++half) {
                    int n = n0 + 8 * half;
                    if (n < NTOK) {
                        uint lo;
                        uint hi = packbf(oacc[nt][2 * half], oacc[nt][2 * half + 1], lo);
                        uint off = (uint)n * 256 + (((uint)((col >> 3) ^ (n & 7))) << 4) + ((uint)(col & 7)) * 2;
                        *(uint*)(QOb + off) = hi;
                        *(uint*)(QOLb + off) = lo;
                    }
                }
            }
        }
    }
    __syncthreads();

    // ---------------- P6: proj GEMM (bf16 3-split), split-major, W fragments from L2 ----------------
    {
        const int mw = wg >> 1, nwg = wg & 1;
        const int arow = mw * 16 + (og & 15);
        const int ac8  = og >> 4;
        float acc[8][4];
        #pragma unroll
        for (int t = 0; t < 8; ++t)
            #pragma unroll
            for (int j = 0; j < 4; ++j) acc[t][j] = 0.f;

        const uint4* fH = g_wpf_hi + (nwg * 4) * 256 + og;
        const uint4* fL = g_wpf_lo + (nwg * 4) * 256 + og;

        #pragma unroll
        for (int ks = 0; ks < 8; ++ks) {
            uint aoff = (uint)arow * 256 + (((uint)((2 * ks + ac8) ^ (arow & 7))) << 4);
            uint ah[4], al[4];
            ldsm4(ah, qoA + aoff);
            ldsm4(al, qolA + aoff);
            uint4 bh[4], bl[4];
            #pragma unroll
            for (int tp = 0; tp < 4; ++tp) {
                bh[tp] = __ldg(fH + tp * 256 + ks * 32);
                bl[tp] = __ldg(fL + tp * 256 + ks * 32);
            }
            #pragma unroll
            for (int tp = 0; tp < 4; ++tp) {
                mma16816(acc[2 * tp],     ah, bh[tp].x, bh[tp].y);
                mma16816(acc[2 * tp + 1], ah, bh[tp].z, bh[tp].w);
            }
            #pragma unroll
            for (int tp = 0; tp < 4; ++tp) {
                mma16816(acc[2 * tp],     ah, bl[tp].x, bl[tp].y);
                mma16816(acc[2 * tp + 1], ah, bl[tp].z, bl[tp].w);
            }
            #pragma unroll
            for (int tp = 0; tp < 4; ++tp) {
                mma16816(acc[2 * tp],     al, bh[tp].x, bh[tp].y);
                mma16816(acc[2 * tp + 1], al, bh[tp].z, bh[tp].w);
            }
        }
        const int n0 = mw * 16 + g;
        float* og_ptr = out + (size_t)b * NTOK * CDIM;
        #pragma unroll
        for (int t = 0; t < 8; ++t) {
            int o = nwg * 64 + t * 8 + tig * 2;
            float b0 = __ldg(&proj_b[o]), b1 = __ldg(&proj_b[o + 1]);
            if (n0 < NTOK)
                *(float2*)&og_ptr[n0 * CDIM + o] = make_float2(acc[t][0] + b0, acc[t][1] + b1);
            if (n0 + 8 < NTOK)
                *(float2*)&og_ptr[(n0 + 8) * CDIM + o] = make_float2(acc[t][2] + b0, acc[t][3] + b1);
        }
    }
}

extern "C" void kernel_launch(void* const* d_in, const int* in_sizes, int n_in,
                              void* d_out, int out_size)
{
    (void)in_sizes; (void)n_in; (void)out_size;
    const float* x          = (const float*)d_in[0];
    const float* mask       = (const float*)d_in[1];
    const float* qkv_w      = (const float*)d_in[2];
    const float* proj_w     = (const float*)d_in[3];
    const float* proj_b     = (const float*)d_in[4];
    const float* bias_table = (const float*)d_in[5];
    const float* alpha      = (const float*)d_in[6];
    const int*   rel_idx    = (const int*)d_in[7];
    float* out = (float*)d_out;

    int conv_elems = NFRAG_Q + NFRAG_P + HEADS * 2401;
    conv_w_kernel<<<(conv_elems + 255) / 256, 256>>>(qkv_w, proj_w, bias_table, rel_idx);

    cudaFuncSetAttribute(lpwin_attn_kernel,
                         cudaFuncAttributeMaxDynamicSharedMemorySize, SMEM_BYTES);
    lpwin_attn_kernel<<<BWIN, THREADS, SMEM_BYTES>>>(
        x, mask, qkv_w, proj_w, proj_b, bias_table, alpha, rel_idx, out);
}

// round 17
// speedup vs baseline: 5.8541x; 1.0081x over previous
#include <cuda_runtime.h>
#include <cuda_bf16.h>
#include <math.h>

// Problem constants
#define BWIN 8192
#define NTOK 49
#define CDIM 128
#define HEADS 4
#define NWIN 4096
#define THREADS 256

// smem byte offsets (regions: 64 rows x 256B = 16KB)
#define B_KH   0         // K^ bf16 hi
#define B_KL   16384     // K^ bf16 lo
#define B_QO   32768     // Q^ bf16 hi -> O bf16 hi (warp-local overlay)
#define B_QOL  49152     // Q^ bf16 lo -> O bf16 lo
#define B_X    65536     // X bf16 hi -> V^T bf16 hi
#define B_XLO  81920     // X bf16 lo -> V^T bf16 lo
#define B_MASK 98304     // mask f32 (2401 floats)
#define SMEM_BYTES 107908

#define QKV_T16  24
#define PROJ_T16 8
#define NFRAG_Q  (QKV_T16 * 8 * 32)    // 6144 uint4
#define NFRAG_P  (PROJ_T16 * 8 * 32)   // 2048 uint4

typedef unsigned long long ull;
typedef unsigned int uint;
typedef unsigned short ushort;

__device__ uint4 g_wqf_hi[NFRAG_Q];
__device__ uint4 g_wqf_lo[NFRAG_Q];
__device__ uint4 g_wpf_hi[NFRAG_P];
__device__ uint4 g_wpf_lo[NFRAG_P];
__device__ float g_rpb[HEADS * 49 * 50];   // [h][n][m], row stride 50

__device__ __forceinline__ uint smem_u32(const void* p){
    uint a; asm("{ .reg .u64 t; cvta.to.shared.u64 t, %1; cvt.u32.u64 %0, t; }" : "=r"(a) : "l"(p));
    return a;
}
__device__ __forceinline__ void ldsm4(uint* r, uint addr){
    asm volatile("ldmatrix.sync.aligned.m8n8.x4.shared.b16 {%0,%1,%2,%3}, [%4];"
        : "=r"(r[0]), "=r"(r[1]), "=r"(r[2]), "=r"(r[3]) : "r"(addr));
}
__device__ __forceinline__ void ldsm2(uint &r0, uint &r1, uint addr){
    asm volatile("ldmatrix.sync.aligned.m8n8.x2.shared.b16 {%0,%1}, [%2];"
        : "=r"(r0), "=r"(r1) : "r"(addr));
}
__device__ __forceinline__ void mma16816(float* d, const uint* a, uint b0, uint b1){
    asm volatile("mma.sync.aligned.m16n8k16.row.col.f32.bf16.bf16.f32 "
        "{%0,%1,%2,%3}, {%4,%5,%6,%7}, {%8,%9}, {%0,%1,%2,%3};"
        : "+f"(d[0]), "+f"(d[1]), "+f"(d[2]), "+f"(d[3])
        : "r"(a[0]), "r"(a[1]), "r"(a[2]), "r"(a[3]), "r"(b0), "r"(b1));
}
__device__ __forceinline__ ushort bfhi(float v, float &rest){
    __nv_bfloat16 h = __float2bfloat16(v);
    rest = v - __bfloat162float(h);
    return *(ushort*)&h;
}
__device__ __forceinline__ ushort bfbits(float v){
    __nv_bfloat16 h = __float2bfloat16(v);
    return *(ushort*)&h;
}
__device__ __forceinline__ uint packbf(float a, float b, uint &lo){
    float ra, rb;
    ushort ha = bfhi(a, ra), hb = bfhi(b, rb);
    lo = ((uint)bfbits(rb) << 16) | bfbits(ra);
    return ((uint)hb << 16) | ha;
}

extern __shared__ float smem[];

__global__ void conv_w_kernel(const float* __restrict__ qkv_w,
                              const float* __restrict__ proj_w,
                              const float* __restrict__ bias_table,
                              const int*   __restrict__ rel_idx){
    int i = blockIdx.x * blockDim.x + threadIdx.x;
    if (i < NFRAG_Q + NFRAG_P) {
        bool isq = (i < NFRAG_Q);
        int idx = isq ? i : i - NFRAG_Q;
        const float* W = isq ? qkv_w : proj_w;
        int tile = idx >> 8;
        int ks   = (idx >> 5) & 7;
        int lane = idx & 31;
        int r0 = tile * 16 + (lane >> 2);
        int r1 = r0 + 8;
        int c0 = ks * 16 + 2 * (lane & 3);
        uint4 hv, lv;
        hv.x = packbf(W[r0 * 128 + c0],     W[r0 * 128 + c0 + 1], lv.x);
        hv.y = packbf(W[r0 * 128 + c0 + 8], W[r0 * 128 + c0 + 9], lv.y);
        hv.z = packbf(W[r1 * 128 + c0],     W[r1 * 128 + c0 + 1], lv.z);
        hv.w = packbf(W[r1 * 128 + c0 + 8], W[r1 * 128 + c0 + 9], lv.w);
        if (isq) { g_wqf_hi[idx] = hv; g_wqf_lo[idx] = lv; }
        else     { g_wpf_hi[idx] = hv; g_wpf_lo[idx] = lv; }
    } else if (i < NFRAG_Q + NFRAG_P + HEADS * 2401) {
        int j = i - (NFRAG_Q + NFRAG_P);
        int h = j / 2401, e = j % 2401;
        int n = e / 49, m = e % 49;
        g_rpb[h * 2450 + n * 50 + m] = bias_table[rel_idx[e] * 4 + h];
    }
}

__global__ void __launch_bounds__(THREADS, 2)
lpwin_attn_kernel(const float* __restrict__ x,
                  const float* __restrict__ mask,
                  const float* __restrict__ qkv_w,
                  const float* __restrict__ proj_w,
                  const float* __restrict__ proj_b,
                  const float* __restrict__ bias_table,
                  const float* __restrict__ alpha,
                  const int*   __restrict__ rel_idx,
                  float* __restrict__ out)
{
    char* SB = (char*)smem;
    float* MASKS = (float*)(SB + B_MASK);

    const int tid = threadIdx.x;
    const int b   = blockIdx.x;
    const int w   = b & (NWIN - 1);
    const int og  = tid & 31;
    const int wg  = tid >> 5;          // 0..7

    const uint base = smem_u32(smem);
    const uint khA = base + B_KH,  klA = base + B_KL;
    const uint qoA = base + B_QO,  qolA = base + B_QOL;
    const uint xhA = base + B_X,   xlA = base + B_XLO;
    const uint vhA = base + B_X,   vlA = base + B_XLO;

    char* KHb = SB + B_KH;  char* KLb = SB + B_KL;
    char* QOb = SB + B_QO;  char* QOLb = SB + B_QOL;
    char* XHb = SB + B_X;   char* XLb = SB + B_XLO;
    char* VHb = SB + B_X;   char* VLb = SB + B_XLO;

    // lane decomposition
    const int brl  = og & 7;
    const int bc8g = (og >> 3) & 1;
    const int brl2 = (og & 7) + ((og & 16) >> 1);
    const int g    = og >> 2, tig = og & 3;

    // ---------------- P1 + P2a: mask; x -> bf16 hi/lo swizzled ----------------
    {
        const float* mg = mask + (size_t)w * 2401;
        for (int i = tid; i < 2401; i += THREADS) MASKS[i] = mg[i];

        const float4* xg4 = (const float4*)(x + (size_t)b * NTOK * CDIM);
        for (int i = tid; i < 49 * 16; i += THREADS) {
            int n = i >> 4, c8 = i & 15;
            float4 a = xg4[n * 32 + c8 * 2];
            float4 c = xg4[n * 32 + c8 * 2 + 1];
            float vs[8] = {a.x, a.y, a.z, a.w, c.x, c.y, c.z, c.w};
            ushort hs[8], ls[8];
            #pragma unroll
            for (int j = 0; j < 8; ++j) {
                float rest;
                hs[j] = bfhi(vs[j], rest);
                ls[j] = bfbits(rest);
            }
            uint off = (uint)n * 256 + (((uint)(c8 ^ (n & 7))) << 4);
            *(uint4*)(XHb + off) = *(uint4*)hs;
            *(uint4*)(XLb + off) = *(uint4*)ls;
        }
        uint4 z = make_uint4(0, 0, 0, 0);
        for (int i = tid; i < 15 * 16; i += THREADS) {
            int n = 49 + (i >> 4), c8 = i & 15;
            uint off = (uint)n * 256 + (((uint)(c8 ^ (n & 7))) << 4);
            *(uint4*)(XHb + off) = z;
            *(uint4*)(XLb + off) = z;
        }
    }
    __syncthreads();

    // ---------------- P2b: QKV GEMM (bf16 3-split), balanced 2m x 2n16 warp tile ----------------
    {
        const int mw2 = wg >> 2, ns = wg & 3;   // 2 m-groups x 4 n-slices (32 cols each)
        const int ac8 = og >> 4;
        float accV[2][4][4];

        for (int pass = 0; pass < 3; ++pass) {
            float acc[2][4][4];   // [mt][n8][frag]
            #pragma unroll
            for (int m2 = 0; m2 < 2; ++m2)
                #pragma unroll
                for (int t = 0; t < 4; ++t)
                    #pragma unroll
                    for (int j = 0; j < 4; ++j) acc[m2][t][j] = 0.f;

            const uint4* fH = g_wqf_hi + (pass * 8 + ns * 2) * 256 + og;
            const uint4* fL = g_wqf_lo + (pass * 8 + ns * 2) * 256 + og;

            #pragma unroll
            for (int ks = 0; ks < 8; ++ks) {
                uint ah[2][4], al[2][4];
                #pragma unroll
                for (int m2 = 0; m2 < 2; ++m2) {
                    int arow = (2 * mw2 + m2) * 16 + (og & 15);
                    uint aoff = (uint)arow * 256 + (((uint)((2 * ks + ac8) ^ (arow & 7))) << 4);
                    ldsm4(ah[m2], xhA + aoff);
                    ldsm4(al[m2], xlA + aoff);
                }
                uint4 bh[2], bl[2];
                #pragma unroll
                for (int nt = 0; nt < 2; ++nt) {
                    bh[nt] = __ldg(fH + nt * 256 + ks * 32);
                    bl[nt] = __ldg(fL + nt * 256 + ks * 32);
                }
                // split-major over 8 accumulators
                #pragma unroll
                for (int m2 = 0; m2 < 2; ++m2)
                    #pragma unroll
                    for (int nt = 0; nt < 2; ++nt) {
                        mma16816(acc[m2][2 * nt],     ah[m2], bh[nt].x, bh[nt].y);
                        mma16816(acc[m2][2 * nt + 1], ah[m2], bh[nt].z, bh[nt].w);
                    }
                #pragma unroll
                for (int m2 = 0; m2 < 2; ++m2)
                    #pragma unroll
                    for (int nt = 0; nt < 2; ++nt) {
                        mma16816(acc[m2][2 * nt],     ah[m2], bl[nt].x, bl[nt].y);
                        mma16816(acc[m2][2 * nt + 1], ah[m2], bl[nt].z, bl[nt].w);
                    }
                #pragma unroll
                for (int m2 = 0; m2 < 2; ++m2)
                    #pragma unroll
                    for (int nt = 0; nt < 2; ++nt) {
                        mma16816(acc[m2][2 * nt],     al[m2], bh[nt].x, bh[nt].y);
                        mma16816(acc[m2][2 * nt + 1], al[m2], bh[nt].z, bh[nt].w);
                    }
            }

            if (pass < 2) {
                // fused epilogue: L2-normalize; warp's 32 cols = exactly head ns
                char* Hb = (pass == 0) ? QOb : KHb;
                char* Lb = (pass == 0) ? QOLb : KLb;
                float sc = (pass == 0) ? __ldg(&alpha[ns]) : 1.f;
                #pragma unroll
                for (int m2 = 0; m2 < 2; ++m2) {
                    int n0 = (2 * mw2 + m2) * 16 + g;
                    float ss0 = 0.f, ss1 = 0.f;
                    #pragma unroll
                    for (int t = 0; t < 4; ++t) {
                        ss0 += acc[m2][t][0] * acc[m2][t][0] + acc[m2][t][1] * acc[m2][t][1];
                        ss1 += acc[m2][t][2] * acc[m2][t][2] + acc[m2][t][3] * acc[m2][t][3];
                    }
                    ss0 += __shfl_xor_sync(0xffffffffu, ss0, 1);
                    ss0 += __shfl_xor_sync(0xffffffffu, ss0, 2);
                    ss1 += __shfl_xor_sync(0xffffffffu, ss1, 1);
                    ss1 += __shfl_xor_sync(0xffffffffu, ss1, 2);
                    float inv0 = sc / (sqrtf(ss0) + 1e-6f);
                    float inv1 = sc / (sqrtf(ss1) + 1e-6f);
                    #pragma unroll
                    for (int t = 0; t < 4; ++t) {
                        int col = ns * 32 + t * 8 + 2 * tig;
                        int c8 = col >> 3;
                        uint lo0, lo1;
                        uint h0 = packbf(acc[m2][t][0] * inv0, acc[m2][t][1] * inv0, lo0);
                        uint off0 = (uint)n0 * 256 + (((uint)(c8 ^ (n0 & 7))) << 4) + ((uint)(col & 7)) * 2;
                        *(uint*)(Hb + off0) = h0;
                        *(uint*)(Lb + off0) = lo0;
                        int n1 = n0 + 8;
                        uint h1 = packbf(acc[m2][t][2] * inv1, acc[m2][t][3] * inv1, lo1);
                        uint off1 = (uint)n1 * 256 + (((uint)(c8 ^ (n1 & 7))) << 4) + ((uint)(col & 7)) * 2;
                        *(uint*)(Hb + off1) = h1;
                        *(uint*)(Lb + off1) = lo1;
                    }
                }
            } else {
                #pragma unroll
                for (int m2 = 0; m2 < 2; ++m2)
                    #pragma unroll
                    for (int t = 0; t < 4; ++t)
                        #pragma unroll
                        for (int j = 0; j < 4; ++j) accV[m2][t][j] = acc[m2][t][j];
            }
        }
        __syncthreads();   // all warps done reading X before V^T overwrite

        // fused epilogue: V^T bf16 (rows = channel, cols = token; pads exact zero)
        #pragma unroll
        for (int m2 = 0; m2 < 2; ++m2) {
            int n0 = (2 * mw2 + m2) * 16 + g;
            #pragma unroll
            for (int t = 0; t < 4; ++t) {
                #pragma unroll
                for (int j = 0; j < 2; ++j) {
                    int c = ns * 32 + t * 8 + 2 * tig + j;
                    #pragma unroll
                    for (int half = 0; half < 2; ++half) {
                        int m = n0 + 8 * half;
                        float v = accV[m2][t][2 * half + j];
                        float rest;
                        ushort hv = bfhi(v, rest);
                        uint off = (uint)c * 128 + (((uint)((m >> 3) ^ (c & 7))) << 4) + ((uint)(m & 7)) * 2;
                        *(ushort*)(VHb + off) = hv;
                        *(ushort*)(VLb + off) = bfbits(rest);
                    }
                }
            }
        }
    }
    __syncthreads();

    // ---------------- P4+P5 fused: both mt tiles in one ks loop (B loaded once) ----------------
    {
        const int h = wg >> 1, mtp = wg & 1;
        const float* rpbh = g_rpb + h * 2450;
        const int ac8 = og >> 4;

        float acc[2][7][4];
        #pragma unroll
        for (int m2 = 0; m2 < 2; ++m2)
            #pragma unroll
            for (int t = 0; t < 7; ++t)
                #pragma unroll
                for (int j = 0; j < 4; ++j) acc[m2][t][j] = 0.f;

        #pragma unroll
        for (int ks = 0; ks < 2; ++ks) {
            uint bh[3][4], bl[3][4];
            uint bh6a, bh6b, bl6a, bl6b;
            #pragma unroll
            for (int p = 0; p < 3; ++p) {
                int krow = p * 16 + brl2;
                uint boff = (uint)krow * 256 + (((uint)((h * 4 + 2 * ks + bc8g) ^ (krow & 7))) << 4);
                ldsm4(bh[p], khA + boff);
                ldsm4(bl[p], klA + boff);
            }
            {
                int krow = 48 + brl;   // K rows 49..55 exact zeros
                uint boff = (uint)krow * 256 + (((uint)((h * 4 + 2 * ks + bc8g) ^ (krow & 7))) << 4);
                ldsm2(bh6a, bh6b, khA + boff);
                ldsm2(bl6a, bl6b, klA + boff);
            }
            #pragma unroll
            for (int m2 = 0; m2 < 2; ++m2) {
                int mt = mtp + 2 * m2;
                int arow = mt * 16 + (og & 15);
                uint aoff = (uint)arow * 256 + (((uint)((h * 4 + 2 * ks + ac8) ^ (arow & 7))) << 4);
                uint ah[4], al[4];
                ldsm4(ah, qoA + aoff);
                ldsm4(al, qolA + aoff);
                #pragma unroll
                for (int p = 0; p < 3; ++p) {
                    mma16816(acc[m2][2 * p],     ah, bh[p][0], bh[p][1]);
                    mma16816(acc[m2][2 * p + 1], ah, bh[p][2], bh[p][3]);
                }
                mma16816(acc[m2][6], ah, bh6a, bh6b);
                #pragma unroll
                for (int p = 0; p < 3; ++p) {
                    mma16816(acc[m2][2 * p],     ah, bl[p][0], bl[p][1]);
                    mma16816(acc[m2][2 * p + 1], ah, bl[p][2], bl[p][3]);
                }
                mma16816(acc[m2][6], ah, bl6a, bl6b);
                #pragma unroll
                for (int p = 0; p < 3; ++p) {
                    mma16816(acc[m2][2 * p],     al, bh[p][0], bh[p][1]);
                    mma16816(acc[m2][2 * p + 1], al, bh[p][2], bh[p][3]);
                }
                mma16816(acc[m2][6], al, bh6a, bh6b);
            }
        }

        #pragma unroll 1
        for (int m2 = 0; m2 < 2; ++m2) {
            const int mt = mtp + 2 * m2;
            // register softmax
            float pv0[14], pv1[14];
            #pragma unroll
            for (int half = 0; half < 2; ++half) {
                int r = mt * 16 + g + 8 * half;
                int nr = (r < NTOK) ? r : 0;
                float* pv = half ? pv1 : pv0;
                float mx = -1e30f;
                #pragma unroll
                for (int nt = 0; nt < 7; ++nt) {
                    int m0 = nt * 8 + 2 * tig;
                    float v0 = acc[m2][nt][2 * half], v1 = acc[m2][nt][2 * half + 1];
                    if (m0 < NTOK) {
                        float2 rp = *(const float2*)&rpbh[nr * 50 + m0];
                        v0 += rp.x + MASKS[nr * 49 + m0];
                        v1 = (m0 + 1 < NTOK) ? (v1 + rp.y + MASKS[nr * 49 + m0 + 1]) : -1e30f;
                    } else { v0 = -1e30f; v1 = -1e30f; }
                    pv[2 * nt] = v0; pv[2 * nt + 1] = v1;
                    mx = fmaxf(mx, fmaxf(v0, v1));
                }
                mx = fmaxf(mx, __shfl_xor_sync(0xffffffffu, mx, 1));
                mx = fmaxf(mx, __shfl_xor_sync(0xffffffffu, mx, 2));
                float sm = 0.f;
                #pragma unroll
                for (int i = 0; i < 14; ++i) { pv[i] = __expf(pv[i] - mx); sm += pv[i]; }
                sm += __shfl_xor_sync(0xffffffffu, sm, 1);
                sm += __shfl_xor_sync(0xffffffffu, sm, 2);
                float inv = 1.f / sm;
                #pragma unroll
                for (int i = 0; i < 14; ++i) pv[i] *= inv;
            }

            // P5: O = P @ V; A-fragments from pv registers; split-major
            float oacc[4][4];
            #pragma unroll
            for (int t = 0; t < 4; ++t)
                #pragma unroll
                for (int j = 0; j < 4; ++j) oacc[t][j] = 0.f;

            #pragma unroll
            for (int ks = 0; ks < 4; ++ks) {
                uint ah[4], al[4];
                ah[0] = packbf(pv0[4 * ks],     pv0[4 * ks + 1], al[0]);
                ah[1] = packbf(pv1[4 * ks],     pv1[4 * ks + 1], al[1]);
                if (ks < 3) {
                    ah[2] = packbf(pv0[4 * ks + 2], pv0[4 * ks + 3], al[2]);
                    ah[3] = packbf(pv1[4 * ks + 2], pv1[4 * ks + 3], al[3]);
                } else {
                    ah[2] = 0u; ah[3] = 0u; al[2] = 0u; al[3] = 0u;
                }
                uint bh[2][4], bl[2][4];
                #pragma unroll
                for (int tp = 0; tp < 2; ++tp) {
                    int c = h * 32 + tp * 16 + brl2;
                    uint boff = (uint)c * 128 + (((uint)((2 * ks + bc8g) ^ (c & 7))) << 4);
                    ldsm4(bh[tp], vhA + boff);
                    ldsm4(bl[tp], vlA + boff);
                }
                #pragma unroll
                for (int tp = 0; tp < 2; ++tp) {
                    mma16816(oacc[2 * tp],     ah, bh[tp][0], bh[tp][1]);
                    mma16816(oacc[2 * tp + 1], ah, bh[tp][2], bh[tp][3]);
                }
                #pragma unroll
                for (int tp = 0; tp < 2; ++tp) {
                    mma16816(oacc[2 * tp],     ah, bl[tp][0], bl[tp][1]);
                    mma16816(oacc[2 * tp + 1], ah, bl[tp][2], bl[tp][3]);
                }
                #pragma unroll
                for (int tp = 0; tp < 2; ++tp) {
                    mma16816(oacc[2 * tp],     al, bh[tp][0], bh[tp][1]);
                    mma16816(oacc[2 * tp + 1], al, bh[tp][2], bh[tp][3]);
                }
            }
            // O epilogue -> QO region (warp-local overlay of Q)
            const int n0 = mt * 16 + g;
            #pragma unroll
            for (int nt = 0; nt < 4; ++nt) {
                int col = h * 32 + nt * 8 + 2 * tig;
                #pragma unroll
                for (int half = 0; half < 2; ++half) {
                    int n = n0 + 8 * half;
                    if (n < NTOK) {
                        uint lo;
                        uint hi = packbf(oacc[nt][2 * half], oacc[nt][2 * half + 1], lo);
                        uint off = (uint)n * 256 + (((uint)((col >> 3) ^ (n & 7))) << 4) + ((uint)(col & 7)) * 2;
                        *(uint*)(QOb + off) = hi;
                        *(uint*)(QOLb + off) = lo;
                    }
                }
            }
        }
    }
    __syncthreads();

    // ---------------- P6: proj GEMM (bf16 3-split), balanced 2m x 2n16 warp tile ----------------
    {
        const int mw2 = wg >> 2, ns = wg & 3;
        const int ac8 = og >> 4;
        float acc[2][4][4];
        #pragma unroll
        for (int m2 = 0; m2 < 2; ++m2)
            #pragma unroll
            for (int t = 0; t < 4; ++t)
                #pragma unroll
                for (int j = 0; j < 4; ++j) acc[m2][t][j] = 0.f;

        const uint4* fH = g_wpf_hi + (ns * 2) * 256 + og;
        const uint4* fL = g_wpf_lo + (ns * 2) * 256 + og;

        #pragma unroll
        for (int ks = 0; ks < 8; ++ks) {
            uint ah[2][4], al[2][4];
            #pragma unroll
            for (int m2 = 0; m2 < 2; ++m2) {
                int arow = (2 * mw2 + m2) * 16 + (og & 15);
                uint aoff = (uint)arow * 256 + (((uint)((2 * ks + ac8) ^ (arow & 7))) << 4);
                ldsm4(ah[m2], qoA + aoff);
                ldsm4(al[m2], qolA + aoff);
            }
            uint4 bh[2], bl[2];
            #pragma unroll
            for (int nt = 0; nt < 2; ++nt) {
                bh[nt] = __ldg(fH + nt * 256 + ks * 32);
                bl[nt] = __ldg(fL + nt * 256 + ks * 32);
            }
            #pragma unroll
            for (int m2 = 0; m2 < 2; ++m2)
                #pragma unroll
                for (int nt = 0; nt < 2; ++nt) {
                    mma16816(acc[m2][2 * nt],     ah[m2], bh[nt].x, bh[nt].y);
                    mma16816(acc[m2][2 * nt + 1], ah[m2], bh[nt].z, bh[nt].w);
                }
            #pragma unroll
            for (int m2 = 0; m2 < 2; ++m2)
                #pragma unroll
                for (int nt = 0; nt < 2; ++nt) {
                    mma16816(acc[m2][2 * nt],     ah[m2], bl[nt].x, bl[nt].y);
                    mma16816(acc[m2][2 * nt + 1], ah[m2], bl[nt].z, bl[nt].w);
                }
            #pragma unroll
            for (int m2 = 0; m2 < 2; ++m2)
                #pragma unroll
                for (int nt = 0; nt < 2; ++nt) {
                    mma16816(acc[m2][2 * nt],     al[m2], bh[nt].x, bh[nt].y);
                    mma16816(acc[m2][2 * nt + 1], al[m2], bh[nt].z, bh[nt].w);
                }
        }
        float* og_ptr = out + (size_t)b * NTOK * CDIM;
        #pragma unroll
        for (int m2 = 0; m2 < 2; ++m2) {
            int n0 = (2 * mw2 + m2) * 16 + g;
            #pragma unroll
            for (int t = 0; t < 4; ++t) {
                int o = ns * 32 + t * 8 + tig * 2;
                float b0 = __ldg(&proj_b[o]), b1 = __ldg(&proj_b[o + 1]);
                if (n0 < NTOK)
                    *(float2*)&og_ptr[n0 * CDIM + o] = make_float2(acc[m2][t][0] + b0, acc[m2][t][1] + b1);
                if (n0 + 8 < NTOK)
                    *(float2*)&og_ptr[(n0 + 8) * CDIM + o] = make_float2(acc[m2][t][2] + b0, acc[m2][t][3] + b1);
            }
        }
    }
}

extern "C" void kernel_launch(void* const* d_in, const int* in_sizes, int n_in,
                              void* d_out, int out_size)
{
    (void)in_sizes; (void)n_in; (void)out_size;
    const float* x          = (const float*)d_in[0];
    const float* mask       = (const float*)d_in[1];
    const float* qkv_w      = (const float*)d_in[2];
    const float* proj_w     = (const float*)d_in[3];
    const float* proj_b     = (const float*)d_in[4];
    const float* bias_table = (const float*)d_in[5];
    const float* alpha      = (const float*)d_in[6];
    const int*   rel_idx    = (const int*)d_in[7];
    float* out = (float*)d_out;

    int conv_elems = NFRAG_Q + NFRAG_P + HEADS * 2401;
    conv_w_kernel<<<(conv_elems + 255) / 256, 256>>>(qkv_w, proj_w, bias_table, rel_idx);

    cudaFuncSetAttribute(lpwin_attn_kernel,
                         cudaFuncAttributeMaxDynamicSharedMemorySize, SMEM_BYTES);
    lpwin_attn_kernel<<<BWIN, THREADS, SMEM_BYTES>>>(
        x, mask, qkv_w, proj_w, proj_b, bias_table, alpha, rel_idx, out);
}